// round 5
// baseline (speedup 1.0000x reference)
#include <cuda_runtime.h>
#include <cuda_bf16.h>
#include <math.h>
#include <stdint.h>

// ---------------- Problem constants ----------------
#define T_SEQ   2048
#define HID     5120
#define NH      16
#define D_NOPE  128
#define D_ROPE  64
#define D_V     128
#define Q_LORA  1536
#define KV_LORA 512
#define QK_HD   (D_NOPE + D_ROPE)   // 192
#define KVA_N   (KV_LORA + D_ROPE)  // 576
#define KVA_NP  640                  // padded to 128 multiple
#define QB_N    (NH * QK_HD)        // 3072
#define KVB_N   (NH * (D_NOPE + D_V)) // 4096
#define O_K     (NH * D_V)          // 2048

static const float SCALE = 0.07216878364870322f; // 192^-0.5
#define EPS_RMS 1e-6f

typedef __nv_bfloat16 bf16;

// ---------------- Scratch ----------------
// fp32 intermediates
__device__ float g_qa   [T_SEQ * Q_LORA];
__device__ float g_q    [T_SEQ * QB_N];
__device__ float g_kv   [T_SEQ * KVA_N];
__device__ float g_kvup [T_SEQ * KVB_N];
__device__ float g_scores[(long)NH * T_SEQ * T_SEQ]; // 268MB
// bf16 hi/lo operand planes
__device__ bf16 g_hs_h [T_SEQ * HID],      g_hs_l [T_SEQ * HID];
__device__ bf16 g_wqa_h[HID * Q_LORA],     g_wqa_l[HID * Q_LORA];
__device__ bf16 g_wqb_h[Q_LORA * QB_N],    g_wqb_l[Q_LORA * QB_N];
__device__ bf16 g_wkva_h[HID * KVA_NP],    g_wkva_l[HID * KVA_NP];
__device__ bf16 g_wkvb_h[KV_LORA * KVB_N], g_wkvb_l[KV_LORA * KVB_N];
__device__ bf16 g_wo_h [O_K * HID],        g_wo_l [O_K * HID];
__device__ bf16 g_qc_h [T_SEQ * Q_LORA],   g_qc_l [T_SEQ * Q_LORA];
__device__ bf16 g_kvc_h[T_SEQ * KV_LORA],  g_kvc_l[T_SEQ * KV_LORA];
__device__ bf16 g_qf_h [(long)NH*T_SEQ*QK_HD], g_qf_l[(long)NH*T_SEQ*QK_HD];
__device__ bf16 g_kf_h [(long)NH*T_SEQ*QK_HD], g_kf_l[(long)NH*T_SEQ*QK_HD];
__device__ bf16 g_v_h  [(long)NH*T_SEQ*D_V],   g_v_l [(long)NH*T_SEQ*D_V];
__device__ bf16 g_P_h  [(long)NH*T_SEQ*T_SEQ], g_P_l [(long)NH*T_SEQ*T_SEQ];
__device__ bf16 g_at_h [T_SEQ * O_K],      g_at_l [T_SEQ * O_K];

// ---------------- helpers ----------------
__device__ __forceinline__ uint32_t smem_u32(const void* p) {
    return (uint32_t)__cvta_generic_to_shared(p);
}
__device__ __forceinline__ void cp16(void* dst, const void* src) {
    asm volatile("cp.async.cg.shared.global [%0], [%1], 16;\n"
                 :: "r"(smem_u32(dst)), "l"(src));
}
__device__ __forceinline__ void cp_commit() {
    asm volatile("cp.async.commit_group;\n");
}
template<int NMAX>
__device__ __forceinline__ void cp_wait() {
    asm volatile("cp.async.wait_group %0;\n" :: "n"(NMAX));
}
__device__ __forceinline__ void ldsm_x4(uint32_t addr, uint32_t r[4]) {
    asm volatile("ldmatrix.sync.aligned.m8n8.x4.shared.b16 {%0,%1,%2,%3}, [%4];"
                 : "=r"(r[0]), "=r"(r[1]), "=r"(r[2]), "=r"(r[3]) : "r"(addr));
}
__device__ __forceinline__ void ldsm_x4_t(uint32_t addr, uint32_t r[4]) {
    asm volatile("ldmatrix.sync.aligned.m8n8.x4.trans.shared.b16 {%0,%1,%2,%3}, [%4];"
                 : "=r"(r[0]), "=r"(r[1]), "=r"(r[2]), "=r"(r[3]) : "r"(addr));
}
__device__ __forceinline__ void mma_bf16(float c[4], const uint32_t a[4],
                                         uint32_t b0, uint32_t b1) {
    asm volatile(
        "mma.sync.aligned.m16n8k16.row.col.f32.bf16.bf16.f32 "
        "{%0,%1,%2,%3}, {%4,%5,%6,%7}, {%8,%9}, {%0,%1,%2,%3};"
        : "+f"(c[0]), "+f"(c[1]), "+f"(c[2]), "+f"(c[3])
        : "r"(a[0]), "r"(a[1]), "r"(a[2]), "r"(a[3]), "r"(b0), "r"(b1));
}
__device__ __forceinline__ uint32_t pack2(bf16 a, bf16 b) {
    __nv_bfloat162 t = __halves2bfloat162(a, b);
    return *reinterpret_cast<uint32_t*>(&t);
}
__device__ __forceinline__ void split1(float f, bf16& h, bf16& l) {
    h = __float2bfloat16(f);
    l = __float2bfloat16(f - __bfloat162float(h));
}

// ---------------- Pure-bf16 tensor GEMM with cp.async ----------------
// C = alpha * A @ B (or B^T). A,B given as hi/lo bf16 planes.
// Assumes: M%128==0, K%16==0; NN path: ldb%128? no — loader covers 128 cols
// per tile and all B buffers are padded so col0+128 <= buffer width.
// EMIT==1: also write hi/lo bf16 planes Ch/Cl instead of fp32 C.
#define BM 128
#define BN 128
#define BK 16

template<int TRANSB, int CAUSAL, int CAUSAL_K, int EMIT>
__global__ __launch_bounds__(256)
void tgemm2(const bf16* __restrict__ Ah, const bf16* __restrict__ Al,
            const bf16* __restrict__ Bh, const bf16* __restrict__ Bl,
            float* __restrict__ C, bf16* __restrict__ Ch, bf16* __restrict__ Cl,
            int M, int N, int K, int lda, int ldb, int ldc,
            long sA, long sB, long sC, float alpha)
{
    constexpr int AST   = BK + 8;                  // 24
    constexpr int BROWS = TRANSB ? BN : BK;
    constexpr int BST   = TRANSB ? (BK + 8) : (BN + 8);

    __shared__ bf16 sAh[2][BM][AST];
    __shared__ bf16 sAl[2][BM][AST];
    __shared__ bf16 sBh[2][BROWS][BST];
    __shared__ bf16 sBl[2][BROWS][BST];

    int row0 = blockIdx.y * BM;
    int col0 = blockIdx.x * BN;
    if (CAUSAL && col0 > row0 + (BM - 1)) return;

    long zA = (long)blockIdx.z * sA;
    long zB = (long)blockIdx.z * sB;
    long zC = (long)blockIdx.z * sC;
    Ah += zA; Al += zA; Bh += zB; Bl += zB;

    int tid  = threadIdx.x;
    int lane = tid & 31;
    int warp = tid >> 5;
    int wm   = warp >> 1;
    int wn   = warp & 1;

    int aRow = tid >> 1;          // 0..127
    int aKc  = (tid & 1) * 8;     // 0 or 8
    int bKr  = tid >> 4;          // 0..15
    int bNc  = (tid & 15) * 8;    // 0..120

    auto issue = [&](int k0, int b) {
        cp16(&sAh[b][aRow][aKc], &Ah[(long)(row0 + aRow) * lda + k0 + aKc]);
        cp16(&sAl[b][aRow][aKc], &Al[(long)(row0 + aRow) * lda + k0 + aKc]);
        if (TRANSB) {
            cp16(&sBh[b][aRow][aKc], &Bh[(long)(col0 + aRow) * ldb + k0 + aKc]);
            cp16(&sBl[b][aRow][aKc], &Bl[(long)(col0 + aRow) * ldb + k0 + aKc]);
        } else {
            cp16(&sBh[b][bKr][bNc], &Bh[(long)(k0 + bKr) * ldb + col0 + bNc]);
            cp16(&sBl[b][bKr][bNc], &Bl[(long)(k0 + bKr) * ldb + col0 + bNc]);
        }
    };

    float acc[2][8][4];
#pragma unroll
    for (int i = 0; i < 2; i++)
#pragma unroll
        for (int j = 0; j < 8; j++)
#pragma unroll
            for (int q = 0; q < 4; q++) acc[i][j][q] = 0.f;

    auto compute = [&](int b) {
        uint32_t a_h[2][4], a_l[2][4];
#pragma unroll
        for (int mt = 0; mt < 2; mt++) {
            int r = wm * 32 + mt * 16 + (lane & 15);
            int c = (lane >> 4) * 8;
            ldsm_x4(smem_u32(&sAh[b][r][c]), a_h[mt]);
            ldsm_x4(smem_u32(&sAl[b][r][c]), a_l[mt]);
        }
#pragma unroll
        for (int p = 0; p < 4; p++) {
            uint32_t bh[4], bl[4];
            if (TRANSB) {
                int g  = lane >> 3;
                int rr = lane & 7;
                int n  = wn * 64 + p * 16 + ((g >> 1) << 3) + rr;
                int c  = (g & 1) * 8;
                ldsm_x4(smem_u32(&sBh[b][n][c]), bh);
                ldsm_x4(smem_u32(&sBl[b][n][c]), bl);
            } else {
                int r    = lane & 15;
                int half = lane >> 4;
                int c    = wn * 64 + p * 16 + half * 8;
                ldsm_x4_t(smem_u32(&sBh[b][r][c]), bh);
                ldsm_x4_t(smem_u32(&sBl[b][r][c]), bl);
            }
#pragma unroll
            for (int mt = 0; mt < 2; mt++)
#pragma unroll
                for (int j = 0; j < 2; j++) {
                    float* c4 = acc[mt][2 * p + j];
                    mma_bf16(c4, a_h[mt], bh[2 * j], bh[2 * j + 1]);
                    mma_bf16(c4, a_h[mt], bl[2 * j], bl[2 * j + 1]);
                    mma_bf16(c4, a_l[mt], bh[2 * j], bh[2 * j + 1]);
                }
        }
    };

    int kEnd = K;
    if (CAUSAL_K) { int lim = row0 + BM; kEnd = lim < K ? lim : K; }
    int ntiles = kEnd / BK;

    issue(0, 0);
    cp_commit();

    for (int i = 0; i < ntiles; i++) {
        if (i + 1 < ntiles) {
            issue((i + 1) * BK, (i + 1) & 1);
            cp_commit();
            cp_wait<1>();
        } else {
            cp_wait<0>();
        }
        __syncthreads();
        compute(i & 1);
        __syncthreads();
    }

    // Epilogue
    int gid = lane >> 2, tig = lane & 3;
#pragma unroll
    for (int mt = 0; mt < 2; mt++) {
        int r = row0 + wm * 32 + mt * 16 + gid;
#pragma unroll
        for (int nt = 0; nt < 8; nt++) {
            int c = col0 + wn * 64 + nt * 8 + tig * 2;
            if (c < N) {
                float v00 = alpha * acc[mt][nt][0], v01 = alpha * acc[mt][nt][1];
                float v10 = alpha * acc[mt][nt][2], v11 = alpha * acc[mt][nt][3];
                if (EMIT) {
                    bf16 h0, l0, h1, l1;
                    split1(v00, h0, l0); split1(v01, h1, l1);
                    *reinterpret_cast<uint32_t*>(&Ch[zC + (long)r * ldc + c]) = pack2(h0, h1);
                    *reinterpret_cast<uint32_t*>(&Cl[zC + (long)r * ldc + c]) = pack2(l0, l1);
                    split1(v10, h0, l0); split1(v11, h1, l1);
                    *reinterpret_cast<uint32_t*>(&Ch[zC + (long)(r + 8) * ldc + c]) = pack2(h0, h1);
                    *reinterpret_cast<uint32_t*>(&Cl[zC + (long)(r + 8) * ldc + c]) = pack2(l0, l1);
                } else {
                    *reinterpret_cast<float2*>(&C[zC + (long)r * ldc + c])       = make_float2(v00, v01);
                    *reinterpret_cast<float2*>(&C[zC + (long)(r + 8) * ldc + c]) = make_float2(v10, v11);
                }
            }
        }
    }
}

// ---------------- fp32 -> bf16 hi/lo converters ----------------
__global__ void cvt_flat_kernel(const float* __restrict__ src,
                                bf16* __restrict__ h, bf16* __restrict__ l, long n)
{
    long i = ((long)blockIdx.x * blockDim.x + threadIdx.x) * 4;
    if (i >= n) return;
    float4 v = *reinterpret_cast<const float4*>(&src[i]);
    bf16 hh[4], ll[4];
    split1(v.x, hh[0], ll[0]); split1(v.y, hh[1], ll[1]);
    split1(v.z, hh[2], ll[2]); split1(v.w, hh[3], ll[3]);
    *reinterpret_cast<uint2*>(&h[i]) = make_uint2(pack2(hh[0], hh[1]), pack2(hh[2], hh[3]));
    *reinterpret_cast<uint2*>(&l[i]) = make_uint2(pack2(ll[0], ll[1]), pack2(ll[2], ll[3]));
}

// padded-column convert (w_kva: 576 -> 640)
__global__ void cvt_pad_kernel(const float* __restrict__ src,
                               bf16* __restrict__ h, bf16* __restrict__ l,
                               int rows, int srcN, int dstN)
{
    long i = (long)blockIdx.x * blockDim.x + threadIdx.x;
    long total = (long)rows * dstN;
    if (i >= total) return;
    int r = (int)(i / dstN), c = (int)(i % dstN);
    float v = (c < srcN) ? src[(long)r * srcN + c] : 0.f;
    bf16 hh, ll; split1(v, hh, ll);
    h[i] = hh; l[i] = ll;
}

// ---------------- RMSNorm (emits hi/lo bf16) ----------------
__global__ void rmsnorm_hl_kernel(const float* __restrict__ in,
                                  const float* __restrict__ w,
                                  bf16* __restrict__ outh, bf16* __restrict__ outl,
                                  int L, int inStride, int outStride)
{
    int t = blockIdx.x;
    const float* x = in + (long)t * inStride;

    float ss = 0.f;
    for (int i = threadIdx.x; i < L; i += blockDim.x) {
        float v = x[i]; ss += v * v;
    }
    __shared__ float sh[33];
#pragma unroll
    for (int o = 16; o; o >>= 1) ss += __shfl_xor_sync(~0u, ss, o);
    int lane = threadIdx.x & 31, wrp = threadIdx.x >> 5;
    if (lane == 0) sh[wrp] = ss;
    __syncthreads();
    if (wrp == 0) {
        float v = (lane < (blockDim.x >> 5)) ? sh[lane] : 0.f;
#pragma unroll
        for (int o = 16; o; o >>= 1) v += __shfl_xor_sync(~0u, v, o);
        if (lane == 0) sh[32] = v;
    }
    __syncthreads();
    float r = rsqrtf(sh[32] / (float)L + EPS_RMS);
    for (int i = threadIdx.x; i < L; i += blockDim.x) {
        float v = x[i] * r * w[i];
        bf16 hh, ll; split1(v, hh, ll);
        outh[(long)t * outStride + i] = hh;
        outl[(long)t * outStride + i] = ll;
    }
}

// ---------------- RoPE + repack (emits hi/lo bf16) ----------------
__global__ void pack_rope_kernel(const int* __restrict__ positions,
                                 const float* __restrict__ q,
                                 const float* __restrict__ kvbuf,
                                 const float* __restrict__ kvup,
                                 bf16* __restrict__ qfh, bf16* __restrict__ qfl,
                                 bf16* __restrict__ kfh, bf16* __restrict__ kfl,
                                 bf16* __restrict__ vh,  bf16* __restrict__ vl)
{
    int t   = blockIdx.x;
    int tid = threadIdx.x;
    float pos = (float)positions[t];

    __shared__ float kp[D_ROPE];
    if (tid < 32) {
        int i = tid;
        float inv = expf(-logf(10000.0f) * (2.0f * i) / (float)D_ROPE);
        float ang = pos * inv;
        float c = cosf(ang), s = sinf(ang);
        float x1 = kvbuf[(long)t * KVA_N + KV_LORA + 2 * i];
        float x2 = kvbuf[(long)t * KVA_N + KV_LORA + 2 * i + 1];
        kp[2 * i]     = x1 * c - x2 * s;
        kp[2 * i + 1] = x2 * c + x1 * s;
    }
    __syncthreads();

    for (int idx = tid; idx < NH * QK_HD; idx += blockDim.x) {
        int h = idx / QK_HD, d = idx % QK_HD;
        long dst = ((long)h * T_SEQ + t) * QK_HD + d;
        bf16 hh, ll;
        if (d < D_NOPE) {
            split1(q[(long)t * QB_N + h * QK_HD + d], hh, ll);
            qfh[dst] = hh; qfl[dst] = ll;
            split1(kvup[(long)t * KVB_N + h * (D_NOPE + D_V) + d], hh, ll);
            kfh[dst] = hh; kfl[dst] = ll;
        } else {
            split1(kp[d - D_NOPE], hh, ll);
            kfh[dst] = hh; kfl[dst] = ll;
        }
    }
    for (int idx = tid; idx < NH * (D_ROPE / 2); idx += blockDim.x) {
        int h = idx / (D_ROPE / 2), i = idx % (D_ROPE / 2);
        float inv = expf(-logf(10000.0f) * (2.0f * i) / (float)D_ROPE);
        float ang = pos * inv;
        float c = cosf(ang), s = sinf(ang);
        long src = (long)t * QB_N + h * QK_HD + D_NOPE;
        float x1 = q[src + 2 * i];
        float x2 = q[src + 2 * i + 1];
        long dst = ((long)h * T_SEQ + t) * QK_HD + D_NOPE;
        bf16 hh, ll;
        split1(x1 * c - x2 * s, hh, ll);
        qfh[dst + 2 * i] = hh;     qfl[dst + 2 * i] = ll;
        split1(x2 * c + x1 * s, hh, ll);
        qfh[dst + 2 * i + 1] = hh; qfl[dst + 2 * i + 1] = ll;
    }
    for (int idx = tid; idx < NH * D_V; idx += blockDim.x) {
        int h = idx / D_V, d = idx % D_V;
        bf16 hh, ll;
        split1(kvup[(long)t * KVB_N + h * (D_NOPE + D_V) + D_NOPE + d], hh, ll);
        vh[((long)h * T_SEQ + t) * D_V + d] = hh;
        vl[((long)h * T_SEQ + t) * D_V + d] = ll;
    }
}

// ---------------- Causal softmax: fp32 scores -> hi/lo bf16 P ----------------
__global__ void softmax_causal_kernel(const float* __restrict__ scores,
                                      bf16* __restrict__ Ph, bf16* __restrict__ Pl)
{
    int t = blockIdx.x, h = blockIdx.y;
    const float* row = scores + ((long)h * T_SEQ + t) * T_SEQ;
    long po = ((long)h * T_SEQ + t) * T_SEQ;
    int n = t + 1;
    int blockEnd = ((t >> 7) + 1) << 7;  // zero out to 128-block boundary

    __shared__ float sh[33];
    int lane = threadIdx.x & 31, wrp = threadIdx.x >> 5;

    float m = -INFINITY;
    for (int i = threadIdx.x; i < n; i += blockDim.x) m = fmaxf(m, row[i]);
#pragma unroll
    for (int o = 16; o; o >>= 1) m = fmaxf(m, __shfl_xor_sync(~0u, m, o));
    if (lane == 0) sh[wrp] = m;
    __syncthreads();
    if (wrp == 0) {
        float v = (lane < (blockDim.x >> 5)) ? sh[lane] : -INFINITY;
#pragma unroll
        for (int o = 16; o; o >>= 1) v = fmaxf(v, __shfl_xor_sync(~0u, v, o));
        if (lane == 0) sh[32] = v;
    }
    __syncthreads();
    m = sh[32];
    __syncthreads();

    float s = 0.f;
    for (int i = threadIdx.x; i < n; i += blockDim.x) s += expf(row[i] - m);
#pragma unroll
    for (int o = 16; o; o >>= 1) s += __shfl_xor_sync(~0u, s, o);
    if (lane == 0) sh[wrp] = s;
    __syncthreads();
    if (wrp == 0) {
        float v = (lane < (blockDim.x >> 5)) ? sh[lane] : 0.f;
#pragma unroll
        for (int o = 16; o; o >>= 1) v += __shfl_xor_sync(~0u, v, o);
        if (lane == 0) sh[32] = v;
    }
    __syncthreads();
    float inv = 1.0f / sh[32];

    for (int i = threadIdx.x; i < n; i += blockDim.x) {
        float p = expf(row[i] - m) * inv;
        bf16 hh, ll; split1(p, hh, ll);
        Ph[po + i] = hh; Pl[po + i] = ll;
    }
    for (int i = n + threadIdx.x; i < blockEnd; i += blockDim.x) {
        Ph[po + i] = __float2bfloat16(0.f);
        Pl[po + i] = __float2bfloat16(0.f);
    }
}

// ---------------- Launch ----------------
extern "C" void kernel_launch(void* const* d_in, const int* in_sizes, int n_in,
                              void* d_out, int out_size)
{
    const int*   positions = (const int*)  d_in[0];
    const float* hs        = (const float*)d_in[1];
    const float* w_qa      = (const float*)d_in[2];
    const float* qa_ln_w   = (const float*)d_in[3];
    const float* w_qb      = (const float*)d_in[4];
    const float* w_kva     = (const float*)d_in[5];
    const float* kva_ln_w  = (const float*)d_in[6];
    const float* w_kvb     = (const float*)d_in[7];
    const float* w_o       = (const float*)d_in[8];
    float* out = (float*)d_out;

    float *p_qa, *p_q, *p_kv, *p_kvup, *p_sc;
    bf16 *hs_h, *hs_l, *wqa_h, *wqa_l, *wqb_h, *wqb_l, *wkva_h, *wkva_l;
    bf16 *wkvb_h, *wkvb_l, *wo_h, *wo_l, *qc_h, *qc_l, *kvc_h, *kvc_l;
    bf16 *qf_h, *qf_l, *kf_h, *kf_l, *v_h, *v_l, *P_h, *P_l, *at_h, *at_l;

    cudaGetSymbolAddress((void**)&p_qa,   g_qa);
    cudaGetSymbolAddress((void**)&p_q,    g_q);
    cudaGetSymbolAddress((void**)&p_kv,   g_kv);
    cudaGetSymbolAddress((void**)&p_kvup, g_kvup);
    cudaGetSymbolAddress((void**)&p_sc,   g_scores);
    cudaGetSymbolAddress((void**)&hs_h,   g_hs_h);   cudaGetSymbolAddress((void**)&hs_l,   g_hs_l);
    cudaGetSymbolAddress((void**)&wqa_h,  g_wqa_h);  cudaGetSymbolAddress((void**)&wqa_l,  g_wqa_l);
    cudaGetSymbolAddress((void**)&wqb_h,  g_wqb_h);  cudaGetSymbolAddress((void**)&wqb_l,  g_wqb_l);
    cudaGetSymbolAddress((void**)&wkva_h, g_wkva_h); cudaGetSymbolAddress((void**)&wkva_l, g_wkva_l);
    cudaGetSymbolAddress((void**)&wkvb_h, g_wkvb_h); cudaGetSymbolAddress((void**)&wkvb_l, g_wkvb_l);
    cudaGetSymbolAddress((void**)&wo_h,   g_wo_h);   cudaGetSymbolAddress((void**)&wo_l,   g_wo_l);
    cudaGetSymbolAddress((void**)&qc_h,   g_qc_h);   cudaGetSymbolAddress((void**)&qc_l,   g_qc_l);
    cudaGetSymbolAddress((void**)&kvc_h,  g_kvc_h);  cudaGetSymbolAddress((void**)&kvc_l,  g_kvc_l);
    cudaGetSymbolAddress((void**)&qf_h,   g_qf_h);   cudaGetSymbolAddress((void**)&qf_l,   g_qf_l);
    cudaGetSymbolAddress((void**)&kf_h,   g_kf_h);   cudaGetSymbolAddress((void**)&kf_l,   g_kf_l);
    cudaGetSymbolAddress((void**)&v_h,    g_v_h);    cudaGetSymbolAddress((void**)&v_l,    g_v_l);
    cudaGetSymbolAddress((void**)&P_h,    g_P_h);    cudaGetSymbolAddress((void**)&P_l,    g_P_l);
    cudaGetSymbolAddress((void**)&at_h,   g_at_h);   cudaGetSymbolAddress((void**)&at_l,   g_at_l);

    dim3 blk(256);
    auto cdiv = [](long a, long b) { return (int)((a + b - 1) / b); };

    // -------- converters --------
    auto cvt = [&](const float* s, bf16* h, bf16* l, long n) {
        cvt_flat_kernel<<<cdiv(n / 4, 256), 256>>>(s, h, l, n);
    };
    cvt(hs,    hs_h,   hs_l,   (long)T_SEQ * HID);
    cvt(w_qa,  wqa_h,  wqa_l,  (long)HID * Q_LORA);
    cvt(w_qb,  wqb_h,  wqb_l,  (long)Q_LORA * QB_N);
    cvt(w_kvb, wkvb_h, wkvb_l, (long)KV_LORA * KVB_N);
    cvt(w_o,   wo_h,   wo_l,   (long)O_K * HID);
    cvt_pad_kernel<<<cdiv((long)HID * KVA_NP, 256), 256>>>(w_kva, wkva_h, wkva_l, HID, KVA_N, KVA_NP);

    // -------- G1: qa = hs @ w_qa (2048x1536, K=5120) --------
    tgemm2<0,0,0,0><<<dim3(Q_LORA/BN, T_SEQ/BM, 1), blk>>>(
        hs_h, hs_l, wqa_h, wqa_l, p_qa, nullptr, nullptr,
        T_SEQ, Q_LORA, HID, HID, Q_LORA, Q_LORA, 0, 0, 0, 1.f);

    // -------- G2: kv = hs @ w_kva (2048x576 padded 640, K=5120) --------
    tgemm2<0,0,0,0><<<dim3(KVA_NP/BN, T_SEQ/BM, 1), blk>>>(
        hs_h, hs_l, wkva_h, wkva_l, p_kv, nullptr, nullptr,
        T_SEQ, KVA_N, HID, HID, KVA_NP, KVA_N, 0, 0, 0, 1.f);

    rmsnorm_hl_kernel<<<T_SEQ, 256>>>(p_qa, qa_ln_w, qc_h, qc_l, Q_LORA, Q_LORA, Q_LORA);
    rmsnorm_hl_kernel<<<T_SEQ, 256>>>(p_kv, kva_ln_w, kvc_h, kvc_l, KV_LORA, KVA_N, KV_LORA);

    // -------- G3: q = qc @ w_qb (2048x3072, K=1536) --------
    tgemm2<0,0,0,0><<<dim3(QB_N/BN, T_SEQ/BM, 1), blk>>>(
        qc_h, qc_l, wqb_h, wqb_l, p_q, nullptr, nullptr,
        T_SEQ, QB_N, Q_LORA, Q_LORA, QB_N, QB_N, 0, 0, 0, 1.f);

    // -------- G4: kvup = kvc @ w_kvb (2048x4096, K=512) --------
    tgemm2<0,0,0,0><<<dim3(KVB_N/BN, T_SEQ/BM, 1), blk>>>(
        kvc_h, kvc_l, wkvb_h, wkvb_l, p_kvup, nullptr, nullptr,
        T_SEQ, KVB_N, KV_LORA, KV_LORA, KVB_N, KVB_N, 0, 0, 0, 1.f);

    pack_rope_kernel<<<T_SEQ, 256>>>(positions, p_q, p_kv, p_kvup,
                                     qf_h, qf_l, kf_h, kf_l, v_h, v_l);

    // -------- G5: scores = SCALE * qfull @ kfull^T (causal, batched) --------
    tgemm2<1,1,0,0><<<dim3(T_SEQ/BN, T_SEQ/BM, NH), blk>>>(
        qf_h, qf_l, kf_h, kf_l, p_sc, nullptr, nullptr,
        T_SEQ, T_SEQ, QK_HD, QK_HD, QK_HD, T_SEQ,
        (long)T_SEQ * QK_HD, (long)T_SEQ * QK_HD, (long)T_SEQ * T_SEQ, SCALE);

    softmax_causal_kernel<<<dim3(T_SEQ, NH), 256>>>(p_sc, P_h, P_l);

    // -------- G6: attn = P @ V (batched, K truncated, emit bf16 hi/lo) --------
    tgemm2<0,0,1,1><<<dim3(D_V/BN, T_SEQ/BM, NH), blk>>>(
        P_h, P_l, v_h, v_l, nullptr, at_h, at_l,
        T_SEQ, D_V, T_SEQ, T_SEQ, D_V, O_K,
        (long)T_SEQ * T_SEQ, (long)T_SEQ * D_V, (long)D_V, 1.f);

    // -------- G7: out = attn @ w_o (2048x5120, K=2048) --------
    tgemm2<0,0,0,0><<<dim3(HID/BN, T_SEQ/BM, 1), blk>>>(
        at_h, at_l, wo_h, wo_l, out, nullptr, nullptr,
        T_SEQ, HID, O_K, O_K, HID, HID, 0, 0, 0, 1.f);
}

// round 7
// speedup vs baseline: 1.0132x; 1.0132x over previous
#include <cuda_runtime.h>
#include <cuda_bf16.h>
#include <math.h>
#include <stdint.h>

// ---------------- Problem constants ----------------
#define T_SEQ   2048
#define HID     5120
#define NH      16
#define D_NOPE  128
#define D_ROPE  64
#define D_V     128
#define Q_LORA  1536
#define KV_LORA 512
#define QK_HD   (D_NOPE + D_ROPE)   // 192
#define KVA_N   (KV_LORA + D_ROPE)  // 576
#define KVA_NP  640
#define QB_N    (NH * QK_HD)        // 3072
#define KVB_N   (NH * (D_NOPE + D_V)) // 4096
#define O_K     (NH * D_V)          // 2048

static const float SCALE = 0.07216878364870322f; // 192^-0.5
#define EPS_RMS 1e-6f

typedef __nv_bfloat16 bf16;

// ---------------- Scratch ----------------
__device__ float g_qa   [T_SEQ * Q_LORA];
__device__ float g_q    [T_SEQ * QB_N];
__device__ float g_kv   [T_SEQ * KVA_N];
__device__ float g_kvup [T_SEQ * KVB_N];

__device__ bf16 g_hs_h [T_SEQ * HID],      g_hs_l [T_SEQ * HID];
__device__ bf16 g_wqa_h[HID * Q_LORA],     g_wqa_l[HID * Q_LORA];
__device__ bf16 g_wqb_h[Q_LORA * QB_N],    g_wqb_l[Q_LORA * QB_N];
__device__ bf16 g_wkva_h[HID * KVA_NP],    g_wkva_l[HID * KVA_NP];
__device__ bf16 g_wkvb_h[KV_LORA * KVB_N], g_wkvb_l[KV_LORA * KVB_N];
__device__ bf16 g_wo_h [O_K * HID],        g_wo_l [O_K * HID];
__device__ bf16 g_qc_h [T_SEQ * Q_LORA],   g_qc_l [T_SEQ * Q_LORA];
__device__ bf16 g_kvc_h[T_SEQ * KV_LORA],  g_kvc_l[T_SEQ * KV_LORA];
__device__ bf16 g_qf_h [(long)NH*T_SEQ*QK_HD], g_qf_l[(long)NH*T_SEQ*QK_HD]; // pre-scaled by SCALE
__device__ bf16 g_kf_h [(long)NH*T_SEQ*QK_HD], g_kf_l[(long)NH*T_SEQ*QK_HD];
__device__ bf16 g_v_h  [(long)NH*T_SEQ*D_V],   g_v_l [(long)NH*T_SEQ*D_V];  // [h][t][dv]
__device__ bf16 g_at_h [T_SEQ * O_K],      g_at_l [T_SEQ * O_K];

// ---------------- helpers ----------------
__device__ __forceinline__ uint32_t smem_u32(const void* p) {
    return (uint32_t)__cvta_generic_to_shared(p);
}
__device__ __forceinline__ void cp16(uint32_t dst, const void* src) {
    asm volatile("cp.async.cg.shared.global [%0], [%1], 16;\n" :: "r"(dst), "l"(src));
}
__device__ __forceinline__ void cp_commit() {
    asm volatile("cp.async.commit_group;\n");
}
template<int NMAX>
__device__ __forceinline__ void cp_wait() {
    asm volatile("cp.async.wait_group %0;\n" :: "n"(NMAX));
}
__device__ __forceinline__ void ldsm_x4(uint32_t addr, uint32_t r[4]) {
    asm volatile("ldmatrix.sync.aligned.m8n8.x4.shared.b16 {%0,%1,%2,%3}, [%4];"
                 : "=r"(r[0]), "=r"(r[1]), "=r"(r[2]), "=r"(r[3]) : "r"(addr));
}
__device__ __forceinline__ void ldsm_x4_t(uint32_t addr, uint32_t r[4]) {
    asm volatile("ldmatrix.sync.aligned.m8n8.x4.trans.shared.b16 {%0,%1,%2,%3}, [%4];"
                 : "=r"(r[0]), "=r"(r[1]), "=r"(r[2]), "=r"(r[3]) : "r"(addr));
}
__device__ __forceinline__ void mma_bf16(float c[4], const uint32_t a[4],
                                         uint32_t b0, uint32_t b1) {
    asm volatile(
        "mma.sync.aligned.m16n8k16.row.col.f32.bf16.bf16.f32 "
        "{%0,%1,%2,%3}, {%4,%5,%6,%7}, {%8,%9}, {%0,%1,%2,%3};"
        : "+f"(c[0]), "+f"(c[1]), "+f"(c[2]), "+f"(c[3])
        : "r"(a[0]), "r"(a[1]), "r"(a[2]), "r"(a[3]), "r"(b0), "r"(b1));
}
__device__ __forceinline__ uint32_t pack2(bf16 a, bf16 b) {
    __nv_bfloat162 t = __halves2bfloat162(a, b);
    return *reinterpret_cast<uint32_t*>(&t);
}
__device__ __forceinline__ void split1(float f, bf16& h, bf16& l) {
    h = __float2bfloat16(f);
    l = __float2bfloat16(f - __bfloat162float(h));
}

// ---------------- NN tensor GEMM: C = A @ B (fp32 out) ----------------
// A hi/lo [M][K], B hi/lo [K][N]. 4-stage cp.async ring, 1 sync/tile.
// M%128==0, K%16==0, B buffer width >= col0+128 (pad w_kva).
#define BM 128
#define BN 128
#define BK 16
// stage layout (bytes): Ah 6144 | Al 6144 | Bh 4352 | Bl 4352
#define G_STG   20992
#define G_SMEM  (4 * G_STG)

__global__ __launch_bounds__(256)
void tgemm_nn(const bf16* __restrict__ Ah, const bf16* __restrict__ Al,
              const bf16* __restrict__ Bh, const bf16* __restrict__ Bl,
              float* __restrict__ C,
              int N, int K, int lda, int ldb, int ldc, float alpha)
{
    extern __shared__ char smem[];
    int row0 = blockIdx.y * BM;
    int col0 = blockIdx.x * BN;

    int tid  = threadIdx.x;
    int lane = tid & 31;
    int warp = tid >> 5;
    int wm   = warp >> 1;
    int wn   = warp & 1;

    int aRow = tid >> 1;          // 0..127
    int aKc  = (tid & 1) * 8;     // 0 or 8
    int bKr  = tid >> 4;          // 0..15
    int bNc  = (tid & 15) * 8;    // 0..120

    uint32_t sb = smem_u32(smem);

    auto issue = [&](int i) {
        int k0 = i * BK;
        uint32_t stg = sb + (i & 3) * G_STG;
        cp16(stg +         (aRow * 24 + aKc) * 2, &Ah[(long)(row0 + aRow) * lda + k0 + aKc]);
        cp16(stg + 6144  + (aRow * 24 + aKc) * 2, &Al[(long)(row0 + aRow) * lda + k0 + aKc]);
        cp16(stg + 12288 + (bKr * 136 + bNc) * 2, &Bh[(long)(k0 + bKr) * ldb + col0 + bNc]);
        cp16(stg + 16640 + (bKr * 136 + bNc) * 2, &Bl[(long)(k0 + bKr) * ldb + col0 + bNc]);
    };

    float acc[2][8][4];
#pragma unroll
    for (int i = 0; i < 2; i++)
#pragma unroll
        for (int j = 0; j < 8; j++)
#pragma unroll
            for (int q = 0; q < 4; q++) acc[i][j][q] = 0.f;

    int ntiles = K / BK;

    issue(0); cp_commit();
    if (ntiles > 1) issue(1);
    cp_commit();

    for (int i = 0; i < ntiles; i++) {
        if (i + 2 < ntiles) issue(i + 2);
        cp_commit();
        cp_wait<2>();
        __syncthreads();

        uint32_t stg = sb + (i & 3) * G_STG;
        uint32_t a_h[2][4], a_l[2][4];
#pragma unroll
        for (int mt = 0; mt < 2; mt++) {
            int r = wm * 32 + mt * 16 + (lane & 15);
            int c = (lane >> 4) * 8;
            ldsm_x4(stg +        (r * 24 + c) * 2, a_h[mt]);
            ldsm_x4(stg + 6144 + (r * 24 + c) * 2, a_l[mt]);
        }
        int rB    = lane & 15;
        int halfB = lane >> 4;
#pragma unroll
        for (int p = 0; p < 4; p++) {
            uint32_t bh[4], bl[4];
            int c = wn * 64 + p * 16 + halfB * 8;
            ldsm_x4_t(stg + 12288 + (rB * 136 + c) * 2, bh);
            ldsm_x4_t(stg + 16640 + (rB * 136 + c) * 2, bl);
#pragma unroll
            for (int mt = 0; mt < 2; mt++)
#pragma unroll
                for (int j = 0; j < 2; j++) {
                    float* c4 = acc[mt][2 * p + j];
                    mma_bf16(c4, a_h[mt], bh[2 * j], bh[2 * j + 1]);
                    mma_bf16(c4, a_h[mt], bl[2 * j], bl[2 * j + 1]);
                    mma_bf16(c4, a_l[mt], bh[2 * j], bh[2 * j + 1]);
                }
        }
        __syncthreads();
    }

    int gid = lane >> 2, tig = lane & 3;
#pragma unroll
    for (int mt = 0; mt < 2; mt++) {
        int r = row0 + wm * 32 + mt * 16 + gid;
#pragma unroll
        for (int nt = 0; nt < 8; nt++) {
            int c = col0 + wn * 64 + nt * 8 + tig * 2;
            if (c < N) {
                *reinterpret_cast<float2*>(&C[(long)r * ldc + c]) =
                    make_float2(alpha * acc[mt][nt][0], alpha * acc[mt][nt][1]);
                *reinterpret_cast<float2*>(&C[(long)(r + 8) * ldc + c]) =
                    make_float2(alpha * acc[mt][nt][2], alpha * acc[mt][nt][3]);
            }
        }
    }
}

// ---------------- Fused flash attention (G5 + softmax + G6) ----------------
// Q/K: [h][t][192] hi/lo (Q pre-scaled). V: [h][t][128] hi/lo.
// Out: at [t][h*128+dv] hi/lo bf16.
// CTA: 256 threads, 8 warps x 16 rows. Each CTA does row-blocks y and 15-y.
#define FA_QSZ   (2 * 128 * 200 * 2)   // 102400: Qh + Ql, stride 200
#define FA_STG   12288                 // chunk stage: plane at +6144
#define FA_SMEM  (FA_QSZ + 4 * FA_STG) // 151552

__global__ __launch_bounds__(256)
void flash_kernel(const bf16* __restrict__ qfh, const bf16* __restrict__ qfl,
                  const bf16* __restrict__ kfh, const bf16* __restrict__ kfl,
                  const bf16* __restrict__ vh,  const bf16* __restrict__ vl,
                  bf16* __restrict__ ath, bf16* __restrict__ atl)
{
    extern __shared__ char smem[];
    int h   = blockIdx.x;
    int tid = threadIdx.x;
    int lane = tid & 31;
    int wid  = tid >> 5;
    int wrow = wid * 16;

    uint32_t sQh = smem_u32(smem);
    uint32_t sQl = sQh + 128 * 200 * 2;
    uint32_t stg = sQh + FA_QSZ;

    const long hT = (long)h * T_SEQ;

    auto loadQ = [&](int i0) {
#pragma unroll
        for (int it = 0; it < 12; it++) {
            int u = it * 256 + tid;
            int row = u / 24, off = (u % 24) * 8;
            cp16(sQh + (row * 200 + off) * 2, qfh + (hT + i0 + row) * QK_HD + off);
            cp16(sQl + (row * 200 + off) * 2, qfl + (hT + i0 + row) * QK_HD + off);
        }
    };
    // chunk c within a row-block: j = c/20; r = c%20; r<12: K chunk d=r, else V chunk q=r-12
    auto load_chunk = [&](int c) {
        uint32_t st = stg + (c & 3) * FA_STG;
        int j = c / 20, r = c % 20;
        if (r < 12) {
            int d0 = r * 16;
            int row = tid >> 1, off = (tid & 1) * 8;
            const bf16* bh = kfh + (hT + j * 128 + row) * QK_HD + d0 + off;
            const bf16* bl = kfl + (hT + j * 128 + row) * QK_HD + d0 + off;
            cp16(st +        (row * 24 + off) * 2, bh);
            cp16(st + 6144 + (row * 24 + off) * 2, bl);
        } else {
            int q0 = (r - 12) * 16;
            int row = tid >> 4, off = (tid & 15) * 8;
            const bf16* bh = vh + (hT + j * 128 + q0 + row) * D_V + off;
            const bf16* bl = vl + (hT + j * 128 + q0 + row) * D_V + off;
            cp16(st +        (row * 136 + off) * 2, bh);
            cp16(st + 6144 + (row * 136 + off) * 2, bl);
        }
    };

    for (int rep = 0; rep < 2; rep++) {
        int iblk = rep == 0 ? blockIdx.y : (T_SEQ / 128 - 1) - blockIdx.y;
        int i0   = iblk * 128;
        int nch  = (iblk + 1) * 20;

        float s[16][4], o[16][4];
        float m0 = -1e30f, m1 = -1e30f, l0 = 0.f, l1 = 0.f;
#pragma unroll
        for (int nt = 0; nt < 16; nt++)
#pragma unroll
            for (int q = 0; q < 4; q++) o[nt][q] = 0.f;

        __syncthreads();               // guard smem reuse across reps
        loadQ(i0);
        load_chunk(0); cp_commit();
        load_chunk(1); cp_commit();

        int lr0 = wrow + (lane >> 2);
        int lr1 = lr0 + 8;

        for (int c = 0; c < nch; c++) {
            if (c + 2 < nch) load_chunk(c + 2);
            cp_commit();
            cp_wait<2>();
            __syncthreads();

            uint32_t st = stg + (c & 3) * FA_STG;
            int j = c / 20, r = c % 20;

            if (r < 12) {
                if (r == 0) {
#pragma unroll
                    for (int nt = 0; nt < 16; nt++)
#pragma unroll
                        for (int q = 0; q < 4; q++) s[nt][q] = 0.f;
                }
                // S += Qd @ Kd^T
                uint32_t a_h[4], a_l[4];
                int ar = wrow + (lane & 15);
                int ac = r * 16 + (lane >> 4) * 8;
                ldsm_x4(sQh + (ar * 200 + ac) * 2, a_h);
                ldsm_x4(sQl + (ar * 200 + ac) * 2, a_l);
                int g = lane >> 3, rr = lane & 7;
                int nbase = ((g >> 1) << 3) + rr;
                int cc = (g & 1) * 8;
#pragma unroll
                for (int p = 0; p < 8; p++) {
                    uint32_t bh[4], bl[4];
                    ldsm_x4(st +        ((p * 16 + nbase) * 24 + cc) * 2, bh);
                    ldsm_x4(st + 6144 + ((p * 16 + nbase) * 24 + cc) * 2, bl);
#pragma unroll
                    for (int jj = 0; jj < 2; jj++) {
                        float* c4 = s[2 * p + jj];
                        mma_bf16(c4, a_h, bh[2 * jj], bh[2 * jj + 1]);
                        mma_bf16(c4, a_h, bl[2 * jj], bl[2 * jj + 1]);
                        mma_bf16(c4, a_l, bh[2 * jj], bh[2 * jj + 1]);
                    }
                }
                if (r == 11) {
                    // ---- online softmax on S block j ----
                    if (j == iblk) {
#pragma unroll
                        for (int nt = 0; nt < 16; nt++) {
                            int c0 = nt * 8 + ((lane & 3) << 1);
                            if (c0     > lr0) s[nt][0] = -1e30f;
                            if (c0 + 1 > lr0) s[nt][1] = -1e30f;
                            if (c0     > lr1) s[nt][2] = -1e30f;
                            if (c0 + 1 > lr1) s[nt][3] = -1e30f;
                        }
                    }
                    float mr0 = -1e30f, mr1 = -1e30f;
#pragma unroll
                    for (int nt = 0; nt < 16; nt++) {
                        mr0 = fmaxf(mr0, fmaxf(s[nt][0], s[nt][1]));
                        mr1 = fmaxf(mr1, fmaxf(s[nt][2], s[nt][3]));
                    }
                    mr0 = fmaxf(mr0, __shfl_xor_sync(~0u, mr0, 1));
                    mr0 = fmaxf(mr0, __shfl_xor_sync(~0u, mr0, 2));
                    mr1 = fmaxf(mr1, __shfl_xor_sync(~0u, mr1, 1));
                    mr1 = fmaxf(mr1, __shfl_xor_sync(~0u, mr1, 2));
                    float mn0 = fmaxf(m0, mr0), mn1 = fmaxf(m1, mr1);
                    float sc0 = __expf(m0 - mn0), sc1 = __expf(m1 - mn1);
                    float rs0 = 0.f, rs1 = 0.f;
#pragma unroll
                    for (int nt = 0; nt < 16; nt++) {
                        s[nt][0] = __expf(s[nt][0] - mn0); rs0 += s[nt][0];
                        s[nt][1] = __expf(s[nt][1] - mn0); rs0 += s[nt][1];
                        s[nt][2] = __expf(s[nt][2] - mn1); rs1 += s[nt][2];
                        s[nt][3] = __expf(s[nt][3] - mn1); rs1 += s[nt][3];
                    }
                    rs0 += __shfl_xor_sync(~0u, rs0, 1); rs0 += __shfl_xor_sync(~0u, rs0, 2);
                    rs1 += __shfl_xor_sync(~0u, rs1, 1); rs1 += __shfl_xor_sync(~0u, rs1, 2);
                    l0 = l0 * sc0 + rs0;  l1 = l1 * sc1 + rs1;
                    m0 = mn0; m1 = mn1;
#pragma unroll
                    for (int nt = 0; nt < 16; nt++) {
                        o[nt][0] *= sc0; o[nt][1] *= sc0;
                        o[nt][2] *= sc1; o[nt][3] *= sc1;
                    }
                }
            } else {
                // O += P @ V, k-step q = r-12 (keys 16q..16q+15)
                int q = r - 12;
                uint32_t ah[4], al[4];
                {
                    const float* t0 = s[2 * q];
                    const float* t1 = s[2 * q + 1];
                    bf16 hA, lA, hB, lB;
                    split1(t0[0], hA, lA); split1(t0[1], hB, lB);
                    ah[0] = pack2(hA, hB); al[0] = pack2(lA, lB);
                    split1(t0[2], hA, lA); split1(t0[3], hB, lB);
                    ah[1] = pack2(hA, hB); al[1] = pack2(lA, lB);
                    split1(t1[0], hA, lA); split1(t1[1], hB, lB);
                    ah[2] = pack2(hA, hB); al[2] = pack2(lA, lB);
                    split1(t1[2], hA, lA); split1(t1[3], hB, lB);
                    ah[3] = pack2(hA, hB); al[3] = pack2(lA, lB);
                }
                int rv = lane & 15, half = lane >> 4;
#pragma unroll
                for (int pp = 0; pp < 8; pp++) {
                    uint32_t bh[4], bl[4];
                    int cV = pp * 16 + half * 8;
                    ldsm_x4_t(st +        (rv * 136 + cV) * 2, bh);
                    ldsm_x4_t(st + 6144 + (rv * 136 + cV) * 2, bl);
#pragma unroll
                    for (int jj = 0; jj < 2; jj++) {
                        float* c4 = o[2 * pp + jj];
                        mma_bf16(c4, ah, bh[2 * jj], bh[2 * jj + 1]);
                        mma_bf16(c4, ah, bl[2 * jj], bl[2 * jj + 1]);
                        mma_bf16(c4, al, bh[2 * jj], bh[2 * jj + 1]);
                    }
                }
            }
            __syncthreads();
        }

        // ---- write O / l ----
        float inv0 = 1.f / l0, inv1 = 1.f / l1;
        int gr0 = i0 + lr0;
#pragma unroll
        for (int nt = 0; nt < 16; nt++) {
            int col = h * D_V + nt * 8 + ((lane & 3) << 1);
            bf16 hA, lA, hB, lB;
            split1(o[nt][0] * inv0, hA, lA); split1(o[nt][1] * inv0, hB, lB);
            *reinterpret_cast<uint32_t*>(&ath[(long)gr0 * O_K + col]) = pack2(hA, hB);
            *reinterpret_cast<uint32_t*>(&atl[(long)gr0 * O_K + col]) = pack2(lA, lB);
            split1(o[nt][2] * inv1, hA, lA); split1(o[nt][3] * inv1, hB, lB);
            *reinterpret_cast<uint32_t*>(&ath[(long)(gr0 + 8) * O_K + col]) = pack2(hA, hB);
            *reinterpret_cast<uint32_t*>(&atl[(long)(gr0 + 8) * O_K + col]) = pack2(lA, lB);
        }
    }
}

// ---------------- fp32 -> bf16 hi/lo converters ----------------
__global__ void cvt_flat_kernel(const float* __restrict__ src,
                                bf16* __restrict__ h, bf16* __restrict__ l, long n)
{
    long i = ((long)blockIdx.x * blockDim.x + threadIdx.x) * 4;
    if (i >= n) return;
    float4 v = *reinterpret_cast<const float4*>(&src[i]);
    bf16 hh[4], ll[4];
    split1(v.x, hh[0], ll[0]); split1(v.y, hh[1], ll[1]);
    split1(v.z, hh[2], ll[2]); split1(v.w, hh[3], ll[3]);
    *reinterpret_cast<uint2*>(&h[i]) = make_uint2(pack2(hh[0], hh[1]), pack2(hh[2], hh[3]));
    *reinterpret_cast<uint2*>(&l[i]) = make_uint2(pack2(ll[0], ll[1]), pack2(ll[2], ll[3]));
}
__global__ void cvt_pad_kernel(const float* __restrict__ src,
                               bf16* __restrict__ h, bf16* __restrict__ l,
                               int rows, int srcN, int dstN)
{
    long i = (long)blockIdx.x * blockDim.x + threadIdx.x;
    long total = (long)rows * dstN;
    if (i >= total) return;
    int r = (int)(i / dstN), c = (int)(i % dstN);
    float v = (c < srcN) ? src[(long)r * srcN + c] : 0.f;
    bf16 hh, ll; split1(v, hh, ll);
    h[i] = hh; l[i] = ll;
}

// ---------------- RMSNorm (emits hi/lo bf16) ----------------
__global__ void rmsnorm_hl_kernel(const float* __restrict__ in,
                                  const float* __restrict__ w,
                                  bf16* __restrict__ outh, bf16* __restrict__ outl,
                                  int L, int inStride, int outStride)
{
    int t = blockIdx.x;
    const float* x = in + (long)t * inStride;

    float ss = 0.f;
    for (int i = threadIdx.x; i < L; i += blockDim.x) {
        float v = x[i]; ss += v * v;
    }
    __shared__ float sh[33];
#pragma unroll
    for (int o = 16; o; o >>= 1) ss += __shfl_xor_sync(~0u, ss, o);
    int lane = threadIdx.x & 31, wrp = threadIdx.x >> 5;
    if (lane == 0) sh[wrp] = ss;
    __syncthreads();
    if (wrp == 0) {
        float v = (lane < (blockDim.x >> 5)) ? sh[lane] : 0.f;
#pragma unroll
        for (int o = 16; o; o >>= 1) v += __shfl_xor_sync(~0u, v, o);
        if (lane == 0) sh[32] = v;
    }
    __syncthreads();
    float r = rsqrtf(sh[32] / (float)L + EPS_RMS);
    for (int i = threadIdx.x; i < L; i += blockDim.x) {
        bf16 hh, ll; split1(x[i] * r * w[i], hh, ll);
        outh[(long)t * outStride + i] = hh;
        outl[(long)t * outStride + i] = ll;
    }
}

// ---------------- RoPE + repack (Q pre-scaled; V in [h][t][dv]) ----------------
__global__ void pack_rope_kernel(const int* __restrict__ positions,
                                 const float* __restrict__ q,
                                 const float* __restrict__ kvbuf,
                                 const float* __restrict__ kvup,
                                 bf16* __restrict__ qfh, bf16* __restrict__ qfl,
                                 bf16* __restrict__ kfh, bf16* __restrict__ kfl,
                                 bf16* __restrict__ vh,  bf16* __restrict__ vl)
{
    int t   = blockIdx.x;
    int tid = threadIdx.x;
    float pos = (float)positions[t];

    __shared__ float kp[D_ROPE];
    if (tid < 32) {
        int i = tid;
        float inv = expf(-logf(10000.0f) * (2.0f * i) / (float)D_ROPE);
        float ang = pos * inv;
        float c = cosf(ang), s = sinf(ang);
        float x1 = kvbuf[(long)t * KVA_N + KV_LORA + 2 * i];
        float x2 = kvbuf[(long)t * KVA_N + KV_LORA + 2 * i + 1];
        kp[2 * i]     = x1 * c - x2 * s;
        kp[2 * i + 1] = x2 * c + x1 * s;
    }
    __syncthreads();

    for (int idx = tid; idx < NH * QK_HD; idx += blockDim.x) {
        int h = idx / QK_HD, d = idx % QK_HD;
        long dst = ((long)h * T_SEQ + t) * QK_HD + d;
        bf16 hh, ll;
        if (d < D_NOPE) {
            split1(q[(long)t * QB_N + h * QK_HD + d] * SCALE, hh, ll);
            qfh[dst] = hh; qfl[dst] = ll;
            split1(kvup[(long)t * KVB_N + h * (D_NOPE + D_V) + d], hh, ll);
            kfh[dst] = hh; kfl[dst] = ll;
        } else {
            split1(kp[d - D_NOPE], hh, ll);
            kfh[dst] = hh; kfl[dst] = ll;
        }
    }
    for (int idx = tid; idx < NH * (D_ROPE / 2); idx += blockDim.x) {
        int h = idx / (D_ROPE / 2), i = idx % (D_ROPE / 2);
        float inv = expf(-logf(10000.0f) * (2.0f * i) / (float)D_ROPE);
        float ang = pos * inv;
        float c = cosf(ang), s = sinf(ang);
        long src = (long)t * QB_N + h * QK_HD + D_NOPE;
        float x1 = q[src + 2 * i];
        float x2 = q[src + 2 * i + 1];
        long dst = ((long)h * T_SEQ + t) * QK_HD + D_NOPE;
        bf16 hh, ll;
        split1((x1 * c - x2 * s) * SCALE, hh, ll);
        qfh[dst + 2 * i] = hh;     qfl[dst + 2 * i] = ll;
        split1((x2 * c + x1 * s) * SCALE, hh, ll);
        qfh[dst + 2 * i + 1] = hh; qfl[dst + 2 * i + 1] = ll;
    }
    for (int idx = tid; idx < NH * D_V; idx += blockDim.x) {
        int h = idx / D_V, d = idx % D_V;
        bf16 hh, ll;
        split1(kvup[(long)t * KVB_N + h * (D_NOPE + D_V) + D_NOPE + d], hh, ll);
        vh[((long)h * T_SEQ + t) * D_V + d] = hh;
        vl[((long)h * T_SEQ + t) * D_V + d] = ll;
    }
}

// ---------------- Launch ----------------
extern "C" void kernel_launch(void* const* d_in, const int* in_sizes, int n_in,
                              void* d_out, int out_size)
{
    const int*   positions = (const int*)  d_in[0];
    const float* hs        = (const float*)d_in[1];
    const float* w_qa      = (const float*)d_in[2];
    const float* qa_ln_w   = (const float*)d_in[3];
    const float* w_qb      = (const float*)d_in[4];
    const float* w_kva     = (const float*)d_in[5];
    const float* kva_ln_w  = (const float*)d_in[6];
    const float* w_kvb     = (const float*)d_in[7];
    const float* w_o       = (const float*)d_in[8];
    float* out = (float*)d_out;

    float *p_qa, *p_q, *p_kv, *p_kvup;
    bf16 *hs_h, *hs_l, *wqa_h, *wqa_l, *wqb_h, *wqb_l, *wkva_h, *wkva_l;
    bf16 *wkvb_h, *wkvb_l, *wo_h, *wo_l, *qc_h, *qc_l, *kvc_h, *kvc_l;
    bf16 *qf_h, *qf_l, *kf_h, *kf_l, *v_h, *v_l, *at_h, *at_l;

    cudaGetSymbolAddress((void**)&p_qa,   g_qa);
    cudaGetSymbolAddress((void**)&p_q,    g_q);
    cudaGetSymbolAddress((void**)&p_kv,   g_kv);
    cudaGetSymbolAddress((void**)&p_kvup, g_kvup);
    cudaGetSymbolAddress((void**)&hs_h,   g_hs_h);   cudaGetSymbolAddress((void**)&hs_l,   g_hs_l);
    cudaGetSymbolAddress((void**)&wqa_h,  g_wqa_h);  cudaGetSymbolAddress((void**)&wqa_l,  g_wqa_l);
    cudaGetSymbolAddress((void**)&wqb_h,  g_wqb_h);  cudaGetSymbolAddress((void**)&wqb_l,  g_wqb_l);
    cudaGetSymbolAddress((void**)&wkva_h, g_wkva_h); cudaGetSymbolAddress((void**)&wkva_l, g_wkva_l);
    cudaGetSymbolAddress((void**)&wkvb_h, g_wkvb_h); cudaGetSymbolAddress((void**)&wkvb_l, g_wkvb_l);
    cudaGetSymbolAddress((void**)&wo_h,   g_wo_h);   cudaGetSymbolAddress((void**)&wo_l,   g_wo_l);
    cudaGetSymbolAddress((void**)&qc_h,   g_qc_h);   cudaGetSymbolAddress((void**)&qc_l,   g_qc_l);
    cudaGetSymbolAddress((void**)&kvc_h,  g_kvc_h);  cudaGetSymbolAddress((void**)&kvc_l,  g_kvc_l);
    cudaGetSymbolAddress((void**)&qf_h,   g_qf_h);   cudaGetSymbolAddress((void**)&qf_l,   g_qf_l);
    cudaGetSymbolAddress((void**)&kf_h,   g_kf_h);   cudaGetSymbolAddress((void**)&kf_l,   g_kf_l);
    cudaGetSymbolAddress((void**)&v_h,    g_v_h);    cudaGetSymbolAddress((void**)&v_l,    g_v_l);
    cudaGetSymbolAddress((void**)&at_h,   g_at_h);   cudaGetSymbolAddress((void**)&at_l,   g_at_l);

    cudaFuncSetAttribute(tgemm_nn,     cudaFuncAttributeMaxDynamicSharedMemorySize, G_SMEM);
    cudaFuncSetAttribute(flash_kernel, cudaFuncAttributeMaxDynamicSharedMemorySize, FA_SMEM);

    dim3 blk(256);
    auto cdiv = [](long a, long b) { return (int)((a + b - 1) / b); };

    // -------- converters --------
    auto cvt = [&](const float* s, bf16* h, bf16* l, long n) {
        cvt_flat_kernel<<<cdiv(n / 4, 256), 256>>>(s, h, l, n);
    };
    cvt(hs,    hs_h,   hs_l,   (long)T_SEQ * HID);
    cvt(w_qa,  wqa_h,  wqa_l,  (long)HID * Q_LORA);
    cvt(w_qb,  wqb_h,  wqb_l,  (long)Q_LORA * QB_N);
    cvt(w_kvb, wkvb_h, wkvb_l, (long)KV_LORA * KVB_N);
    cvt(w_o,   wo_h,   wo_l,   (long)O_K * HID);
    cvt_pad_kernel<<<cdiv((long)HID * KVA_NP, 256), 256>>>(w_kva, wkva_h, wkva_l, HID, KVA_N, KVA_NP);

    // G1: qa = hs @ w_qa (2048x1536, K=5120)
    tgemm_nn<<<dim3(Q_LORA/BN, T_SEQ/BM), blk, G_SMEM>>>(
        hs_h, hs_l, wqa_h, wqa_l, p_qa, Q_LORA, HID, HID, Q_LORA, Q_LORA, 1.f);

    // G2: kv = hs @ w_kva (2048x576, B padded 640, K=5120)
    tgemm_nn<<<dim3(KVA_NP/BN, T_SEQ/BM), blk, G_SMEM>>>(
        hs_h, hs_l, wkva_h, wkva_l, p_kv, KVA_N, HID, HID, KVA_NP, KVA_N, 1.f);

    rmsnorm_hl_kernel<<<T_SEQ, 256>>>(p_qa, qa_ln_w, qc_h, qc_l, Q_LORA, Q_LORA, Q_LORA);
    rmsnorm_hl_kernel<<<T_SEQ, 256>>>(p_kv, kva_ln_w, kvc_h, kvc_l, KV_LORA, KVA_N, KV_LORA);

    // G3: q = qc @ w_qb (2048x3072, K=1536)
    tgemm_nn<<<dim3(QB_N/BN, T_SEQ/BM), blk, G_SMEM>>>(
        qc_h, qc_l, wqb_h, wqb_l, p_q, QB_N, Q_LORA, Q_LORA, QB_N, QB_N, 1.f);

    // G4: kvup = kvc @ w_kvb (2048x4096, K=512)
    tgemm_nn<<<dim3(KVB_N/BN, T_SEQ/BM), blk, G_SMEM>>>(
        kvc_h, kvc_l, wkvb_h, wkvb_l, p_kvup, KVB_N, KV_LORA, KV_LORA, KVB_N, KVB_N, 1.f);

    pack_rope_kernel<<<T_SEQ, 256>>>(positions, p_q, p_kv, p_kvup,
                                     qf_h, qf_l, kf_h, kf_l, v_h, v_l);

    // Fused attention (replaces G5 + softmax + G6); row-blocks paired (y, 15-y)
    flash_kernel<<<dim3(NH, T_SEQ / 256), blk, FA_SMEM>>>(
        qf_h, qf_l, kf_h, kf_l, v_h, v_l, at_h, at_l);

    // G7: out = attn @ w_o (2048x5120, K=2048)
    tgemm_nn<<<dim3(HID/BN, T_SEQ/BM), blk, G_SMEM>>>(
        at_h, at_l, wo_h, wo_l, out, HID, O_K, O_K, HID, HID, 1.f);
}

// round 8
// speedup vs baseline: 1.3169x; 1.2998x over previous
#include <cuda_runtime.h>
#include <cuda_fp16.h>
#include <math.h>
#include <stdint.h>

// ---------------- Problem constants ----------------
#define T_SEQ   2048
#define HID     5120
#define NH      16
#define D_NOPE  128
#define D_ROPE  64
#define D_V     128
#define Q_LORA  1536
#define KV_LORA 512
#define QK_HD   (D_NOPE + D_ROPE)   // 192
#define KVA_N   (KV_LORA + D_ROPE)  // 576
#define KVA_NP  640
#define QB_N    (NH * QK_HD)        // 3072
#define KVB_N   (NH * (D_NOPE + D_V)) // 4096
#define O_K     (NH * D_V)          // 2048

static const float SCALE = 0.07216878364870322f; // 192^-0.5
#define EPS_RMS 1e-6f

typedef __half f16;

// ---------------- Scratch ----------------
__device__ float g_qa   [T_SEQ * Q_LORA];
__device__ float g_q    [T_SEQ * QB_N];
__device__ float g_kv   [T_SEQ * KVA_N];
__device__ float g_kvup [T_SEQ * KVB_N];

// A operands: hi/lo fp16 planes. B operands: single fp16 plane.
__device__ f16 g_hs_h [T_SEQ * HID],      g_hs_l [T_SEQ * HID];
__device__ f16 g_wqa  [HID * Q_LORA];
__device__ f16 g_wqb  [Q_LORA * QB_N];
__device__ f16 g_wkva [HID * KVA_NP];
__device__ f16 g_wkvb [KV_LORA * KVB_N];
__device__ f16 g_wo   [O_K * HID];
__device__ f16 g_qc_h [T_SEQ * Q_LORA],   g_qc_l [T_SEQ * Q_LORA];
__device__ f16 g_kvc_h[T_SEQ * KV_LORA],  g_kvc_l[T_SEQ * KV_LORA];
__device__ f16 g_qf_h [(long)NH*T_SEQ*QK_HD], g_qf_l[(long)NH*T_SEQ*QK_HD];
__device__ f16 g_kf   [(long)NH*T_SEQ*QK_HD];
__device__ f16 g_v    [(long)NH*T_SEQ*D_V];   // [h][t][dv]
__device__ f16 g_at_h [T_SEQ * O_K],      g_at_l [T_SEQ * O_K];

// ---------------- helpers ----------------
__device__ __forceinline__ uint32_t smem_u32(const void* p) {
    return (uint32_t)__cvta_generic_to_shared(p);
}
__device__ __forceinline__ void cp16(uint32_t dst, const void* src) {
    asm volatile("cp.async.cg.shared.global [%0], [%1], 16;\n" :: "r"(dst), "l"(src));
}
__device__ __forceinline__ void cp_commit() {
    asm volatile("cp.async.commit_group;\n");
}
template<int NMAX>
__device__ __forceinline__ void cp_wait() {
    asm volatile("cp.async.wait_group %0;\n" :: "n"(NMAX));
}
__device__ __forceinline__ void ldsm_x4(uint32_t addr, uint32_t r[4]) {
    asm volatile("ldmatrix.sync.aligned.m8n8.x4.shared.b16 {%0,%1,%2,%3}, [%4];"
                 : "=r"(r[0]), "=r"(r[1]), "=r"(r[2]), "=r"(r[3]) : "r"(addr));
}
__device__ __forceinline__ void ldsm_x4_t(uint32_t addr, uint32_t r[4]) {
    asm volatile("ldmatrix.sync.aligned.m8n8.x4.trans.shared.b16 {%0,%1,%2,%3}, [%4];"
                 : "=r"(r[0]), "=r"(r[1]), "=r"(r[2]), "=r"(r[3]) : "r"(addr));
}
__device__ __forceinline__ void mma_f16(float c[4], const uint32_t a[4],
                                        uint32_t b0, uint32_t b1) {
    asm volatile(
        "mma.sync.aligned.m16n8k16.row.col.f32.f16.f16.f32 "
        "{%0,%1,%2,%3}, {%4,%5,%6,%7}, {%8,%9}, {%0,%1,%2,%3};"
        : "+f"(c[0]), "+f"(c[1]), "+f"(c[2]), "+f"(c[3])
        : "r"(a[0]), "r"(a[1]), "r"(a[2]), "r"(a[3]), "r"(b0), "r"(b1));
}
__device__ __forceinline__ uint32_t pack2(f16 a, f16 b) {
    __half2 t = __halves2half2(a, b);
    return *reinterpret_cast<uint32_t*>(&t);
}
__device__ __forceinline__ void split1(float f, f16& h, f16& l) {
    h = __float2half_rn(f);
    l = __float2half_rn(f - __half2float(h));
}

// ---------------- NN tensor GEMM: C = A @ B (fp32 out) ----------------
// A hi/lo fp16 [M][K], B single fp16 [K][N]. 2 MMAs per step.
// 4-stage cp.async ring. M%128==0, K%16==0, B width >= col0+128.
#define BM 128
#define BN 128
#define BK 16
// stage: Ah 6144 | Al 6144 | B 4352 = 16640
#define G_STG   16640
#define G_SMEM  (4 * G_STG)

__global__ __launch_bounds__(256)
void tgemm_nn(const f16* __restrict__ Ah, const f16* __restrict__ Al,
              const f16* __restrict__ B,
              float* __restrict__ C,
              int N, int K, int lda, int ldb, int ldc, float alpha)
{
    extern __shared__ char smem[];
    int row0 = blockIdx.y * BM;
    int col0 = blockIdx.x * BN;

    int tid  = threadIdx.x;
    int lane = tid & 31;
    int warp = tid >> 5;
    int wm   = warp >> 1;
    int wn   = warp & 1;

    int aRow = tid >> 1;          // 0..127
    int aKc  = (tid & 1) * 8;     // 0 or 8
    int bKr  = tid >> 4;          // 0..15
    int bNc  = (tid & 15) * 8;    // 0..120

    uint32_t sb = smem_u32(smem);

    auto issue = [&](int i) {
        int k0 = i * BK;
        uint32_t stg = sb + (i & 3) * G_STG;
        cp16(stg +         (aRow * 24 + aKc) * 2, &Ah[(long)(row0 + aRow) * lda + k0 + aKc]);
        cp16(stg + 6144  + (aRow * 24 + aKc) * 2, &Al[(long)(row0 + aRow) * lda + k0 + aKc]);
        cp16(stg + 12288 + (bKr * 136 + bNc) * 2, &B[(long)(k0 + bKr) * ldb + col0 + bNc]);
    };

    float acc[2][8][4];
#pragma unroll
    for (int i = 0; i < 2; i++)
#pragma unroll
        for (int j = 0; j < 8; j++)
#pragma unroll
            for (int q = 0; q < 4; q++) acc[i][j][q] = 0.f;

    int ntiles = K / BK;

    issue(0); cp_commit();
    if (ntiles > 1) issue(1);
    cp_commit();

    for (int i = 0; i < ntiles; i++) {
        if (i + 2 < ntiles) issue(i + 2);
        cp_commit();
        cp_wait<2>();
        __syncthreads();

        uint32_t stg = sb + (i & 3) * G_STG;
        uint32_t a_h[2][4], a_l[2][4];
#pragma unroll
        for (int mt = 0; mt < 2; mt++) {
            int r = wm * 32 + mt * 16 + (lane & 15);
            int c = (lane >> 4) * 8;
            ldsm_x4(stg +        (r * 24 + c) * 2, a_h[mt]);
            ldsm_x4(stg + 6144 + (r * 24 + c) * 2, a_l[mt]);
        }
        int rB    = lane & 15;
        int halfB = lane >> 4;
#pragma unroll
        for (int p = 0; p < 4; p++) {
            uint32_t bh[4];
            int c = wn * 64 + p * 16 + halfB * 8;
            ldsm_x4_t(stg + 12288 + (rB * 136 + c) * 2, bh);
#pragma unroll
            for (int mt = 0; mt < 2; mt++)
#pragma unroll
                for (int j = 0; j < 2; j++) {
                    float* c4 = acc[mt][2 * p + j];
                    mma_f16(c4, a_h[mt], bh[2 * j], bh[2 * j + 1]);
                    mma_f16(c4, a_l[mt], bh[2 * j], bh[2 * j + 1]);
                }
        }
        __syncthreads();
    }

    int gid = lane >> 2, tig = lane & 3;
#pragma unroll
    for (int mt = 0; mt < 2; mt++) {
        int r = row0 + wm * 32 + mt * 16 + gid;
#pragma unroll
        for (int nt = 0; nt < 8; nt++) {
            int c = col0 + wn * 64 + nt * 8 + tig * 2;
            if (c < N) {
                *reinterpret_cast<float2*>(&C[(long)r * ldc + c]) =
                    make_float2(alpha * acc[mt][nt][0], alpha * acc[mt][nt][1]);
                *reinterpret_cast<float2*>(&C[(long)(r + 8) * ldc + c]) =
                    make_float2(alpha * acc[mt][nt][2], alpha * acc[mt][nt][3]);
            }
        }
    }
}

// ---------------- Fused flash attention ----------------
// Q: [h][t][192] hi/lo fp16 (unscaled; SCALE applied at softmax).
// K: [h][t][192] single fp16. V: [h][t][128] single fp16.
// Out: at [t][h*128+dv] hi/lo fp16.
#define FA_QSZ   (2 * 128 * 200 * 2)   // 102400
#define FA_STG   6144                  // single-plane chunk stage
#define FA_SMEM  (FA_QSZ + 4 * FA_STG) // 126976

__global__ __launch_bounds__(256)
void flash_kernel(const f16* __restrict__ qfh, const f16* __restrict__ qfl,
                  const f16* __restrict__ kf,  const f16* __restrict__ v,
                  f16* __restrict__ ath, f16* __restrict__ atl)
{
    extern __shared__ char smem[];
    int h   = blockIdx.x;
    int tid = threadIdx.x;
    int lane = tid & 31;
    int wid  = tid >> 5;
    int wrow = wid * 16;

    uint32_t sQh = smem_u32(smem);
    uint32_t sQl = sQh + 128 * 200 * 2;
    uint32_t stg = sQh + FA_QSZ;

    const long hT = (long)h * T_SEQ;

    auto loadQ = [&](int i0) {
#pragma unroll
        for (int it = 0; it < 12; it++) {
            int u = it * 256 + tid;
            int row = u / 24, off = (u % 24) * 8;
            cp16(sQh + (row * 200 + off) * 2, qfh + (hT + i0 + row) * QK_HD + off);
            cp16(sQl + (row * 200 + off) * 2, qfl + (hT + i0 + row) * QK_HD + off);
        }
    };
    auto load_chunk = [&](int c) {
        uint32_t st = stg + (c & 3) * FA_STG;
        int j = c / 20, r = c % 20;
        if (r < 12) {
            int d0 = r * 16;
            int row = tid >> 1, off = (tid & 1) * 8;
            cp16(st + (row * 24 + off) * 2, kf + (hT + j * 128 + row) * QK_HD + d0 + off);
        } else {
            int q0 = (r - 12) * 16;
            int row = tid >> 4, off = (tid & 15) * 8;
            cp16(st + (row * 136 + off) * 2, v + (hT + j * 128 + q0 + row) * D_V + off);
        }
    };

    for (int rep = 0; rep < 2; rep++) {
        int iblk = rep == 0 ? blockIdx.y : (T_SEQ / 128 - 1) - blockIdx.y;
        int i0   = iblk * 128;
        int nch  = (iblk + 1) * 20;

        float s[16][4], o[16][4];
        float m0 = -1e30f, m1 = -1e30f, l0 = 0.f, l1 = 0.f;
#pragma unroll
        for (int nt = 0; nt < 16; nt++)
#pragma unroll
            for (int q = 0; q < 4; q++) o[nt][q] = 0.f;

        __syncthreads();
        loadQ(i0);
        load_chunk(0); cp_commit();
        load_chunk(1); cp_commit();

        int lr0 = wrow + (lane >> 2);
        int lr1 = lr0 + 8;

        for (int c = 0; c < nch; c++) {
            if (c + 2 < nch) load_chunk(c + 2);
            cp_commit();
            cp_wait<2>();
            __syncthreads();

            uint32_t st = stg + (c & 3) * FA_STG;
            int j = c / 20, r = c % 20;

            if (r < 12) {
                if (r == 0) {
#pragma unroll
                    for (int nt = 0; nt < 16; nt++)
#pragma unroll
                        for (int q = 0; q < 4; q++) s[nt][q] = 0.f;
                }
                uint32_t a_h[4], a_l[4];
                int ar = wrow + (lane & 15);
                int ac = r * 16 + (lane >> 4) * 8;
                ldsm_x4(sQh + (ar * 200 + ac) * 2, a_h);
                ldsm_x4(sQl + (ar * 200 + ac) * 2, a_l);
                int g = lane >> 3, rr = lane & 7;
                int nbase = ((g >> 1) << 3) + rr;
                int cc = (g & 1) * 8;
#pragma unroll
                for (int p = 0; p < 8; p++) {
                    uint32_t bh[4];
                    ldsm_x4(st + ((p * 16 + nbase) * 24 + cc) * 2, bh);
#pragma unroll
                    for (int jj = 0; jj < 2; jj++) {
                        float* c4 = s[2 * p + jj];
                        mma_f16(c4, a_h, bh[2 * jj], bh[2 * jj + 1]);
                        mma_f16(c4, a_l, bh[2 * jj], bh[2 * jj + 1]);
                    }
                }
                if (r == 11) {
                    // apply SCALE, then mask, then online softmax
#pragma unroll
                    for (int nt = 0; nt < 16; nt++)
#pragma unroll
                        for (int q = 0; q < 4; q++) s[nt][q] *= SCALE;
                    if (j == iblk) {
#pragma unroll
                        for (int nt = 0; nt < 16; nt++) {
                            int c0 = nt * 8 + ((lane & 3) << 1);
                            if (c0     > lr0) s[nt][0] = -1e30f;
                            if (c0 + 1 > lr0) s[nt][1] = -1e30f;
                            if (c0     > lr1) s[nt][2] = -1e30f;
                            if (c0 + 1 > lr1) s[nt][3] = -1e30f;
                        }
                    }
                    float mr0 = -1e30f, mr1 = -1e30f;
#pragma unroll
                    for (int nt = 0; nt < 16; nt++) {
                        mr0 = fmaxf(mr0, fmaxf(s[nt][0], s[nt][1]));
                        mr1 = fmaxf(mr1, fmaxf(s[nt][2], s[nt][3]));
                    }
                    mr0 = fmaxf(mr0, __shfl_xor_sync(~0u, mr0, 1));
                    mr0 = fmaxf(mr0, __shfl_xor_sync(~0u, mr0, 2));
                    mr1 = fmaxf(mr1, __shfl_xor_sync(~0u, mr1, 1));
                    mr1 = fmaxf(mr1, __shfl_xor_sync(~0u, mr1, 2));
                    float mn0 = fmaxf(m0, mr0), mn1 = fmaxf(m1, mr1);
                    float sc0 = __expf(m0 - mn0), sc1 = __expf(m1 - mn1);
                    float rs0 = 0.f, rs1 = 0.f;
#pragma unroll
                    for (int nt = 0; nt < 16; nt++) {
                        s[nt][0] = __expf(s[nt][0] - mn0); rs0 += s[nt][0];
                        s[nt][1] = __expf(s[nt][1] - mn0); rs0 += s[nt][1];
                        s[nt][2] = __expf(s[nt][2] - mn1); rs1 += s[nt][2];
                        s[nt][3] = __expf(s[nt][3] - mn1); rs1 += s[nt][3];
                    }
                    rs0 += __shfl_xor_sync(~0u, rs0, 1); rs0 += __shfl_xor_sync(~0u, rs0, 2);
                    rs1 += __shfl_xor_sync(~0u, rs1, 1); rs1 += __shfl_xor_sync(~0u, rs1, 2);
                    l0 = l0 * sc0 + rs0;  l1 = l1 * sc1 + rs1;
                    m0 = mn0; m1 = mn1;
#pragma unroll
                    for (int nt = 0; nt < 16; nt++) {
                        o[nt][0] *= sc0; o[nt][1] *= sc0;
                        o[nt][2] *= sc1; o[nt][3] *= sc1;
                    }
                }
            } else {
                // O += P @ V (P split in registers, V single plane)
                int q = r - 12;
                uint32_t ah[4], al[4];
                {
                    const float* t0 = s[2 * q];
                    const float* t1 = s[2 * q + 1];
                    f16 hA, lA, hB, lB;
                    split1(t0[0], hA, lA); split1(t0[1], hB, lB);
                    ah[0] = pack2(hA, hB); al[0] = pack2(lA, lB);
                    split1(t0[2], hA, lA); split1(t0[3], hB, lB);
                    ah[1] = pack2(hA, hB); al[1] = pack2(lA, lB);
                    split1(t1[0], hA, lA); split1(t1[1], hB, lB);
                    ah[2] = pack2(hA, hB); al[2] = pack2(lA, lB);
                    split1(t1[2], hA, lA); split1(t1[3], hB, lB);
                    ah[3] = pack2(hA, hB); al[3] = pack2(lA, lB);
                }
                int rv = lane & 15, half = lane >> 4;
#pragma unroll
                for (int pp = 0; pp < 8; pp++) {
                    uint32_t bh[4];
                    int cV = pp * 16 + half * 8;
                    ldsm_x4_t(st + (rv * 136 + cV) * 2, bh);
#pragma unroll
                    for (int jj = 0; jj < 2; jj++) {
                        float* c4 = o[2 * pp + jj];
                        mma_f16(c4, ah, bh[2 * jj], bh[2 * jj + 1]);
                        mma_f16(c4, al, bh[2 * jj], bh[2 * jj + 1]);
                    }
                }
            }
            __syncthreads();
        }

        float inv0 = 1.f / l0, inv1 = 1.f / l1;
        int gr0 = i0 + lr0;
#pragma unroll
        for (int nt = 0; nt < 16; nt++) {
            int col = h * D_V + nt * 8 + ((lane & 3) << 1);
            f16 hA, lA, hB, lB;
            split1(o[nt][0] * inv0, hA, lA); split1(o[nt][1] * inv0, hB, lB);
            *reinterpret_cast<uint32_t*>(&ath[(long)gr0 * O_K + col]) = pack2(hA, hB);
            *reinterpret_cast<uint32_t*>(&atl[(long)gr0 * O_K + col]) = pack2(lA, lB);
            split1(o[nt][2] * inv1, hA, lA); split1(o[nt][3] * inv1, hB, lB);
            *reinterpret_cast<uint32_t*>(&ath[(long)(gr0 + 8) * O_K + col]) = pack2(hA, hB);
            *reinterpret_cast<uint32_t*>(&atl[(long)(gr0 + 8) * O_K + col]) = pack2(lA, lB);
        }
    }
}

// ---------------- converters ----------------
__global__ void cvt_split_kernel(const float* __restrict__ src,
                                 f16* __restrict__ h, f16* __restrict__ l, long n)
{
    long i = ((long)blockIdx.x * blockDim.x + threadIdx.x) * 4;
    if (i >= n) return;
    float4 vv = *reinterpret_cast<const float4*>(&src[i]);
    f16 hh[4], ll[4];
    split1(vv.x, hh[0], ll[0]); split1(vv.y, hh[1], ll[1]);
    split1(vv.z, hh[2], ll[2]); split1(vv.w, hh[3], ll[3]);
    *reinterpret_cast<uint2*>(&h[i]) = make_uint2(pack2(hh[0], hh[1]), pack2(hh[2], hh[3]));
    *reinterpret_cast<uint2*>(&l[i]) = make_uint2(pack2(ll[0], ll[1]), pack2(ll[2], ll[3]));
}
__global__ void cvt_single_kernel(const float* __restrict__ src,
                                  f16* __restrict__ h, long n)
{
    long i = ((long)blockIdx.x * blockDim.x + threadIdx.x) * 4;
    if (i >= n) return;
    float4 vv = *reinterpret_cast<const float4*>(&src[i]);
    *reinterpret_cast<uint2*>(&h[i]) =
        make_uint2(pack2(__float2half_rn(vv.x), __float2half_rn(vv.y)),
                   pack2(__float2half_rn(vv.z), __float2half_rn(vv.w)));
}
__global__ void cvt_pad_single_kernel(const float* __restrict__ src,
                                      f16* __restrict__ h,
                                      int rows, int srcN, int dstN)
{
    long i = (long)blockIdx.x * blockDim.x + threadIdx.x;
    long total = (long)rows * dstN;
    if (i >= total) return;
    int r = (int)(i / dstN), c = (int)(i % dstN);
    float vv = (c < srcN) ? src[(long)r * srcN + c] : 0.f;
    h[i] = __float2half_rn(vv);
}

// ---------------- RMSNorm (emits hi/lo fp16) ----------------
__global__ void rmsnorm_hl_kernel(const float* __restrict__ in,
                                  const float* __restrict__ w,
                                  f16* __restrict__ outh, f16* __restrict__ outl,
                                  int L, int inStride, int outStride)
{
    int t = blockIdx.x;
    const float* x = in + (long)t * inStride;

    float ss = 0.f;
    for (int i = threadIdx.x; i < L; i += blockDim.x) {
        float v = x[i]; ss += v * v;
    }
    __shared__ float sh[33];
#pragma unroll
    for (int o = 16; o; o >>= 1) ss += __shfl_xor_sync(~0u, ss, o);
    int lane = threadIdx.x & 31, wrp = threadIdx.x >> 5;
    if (lane == 0) sh[wrp] = ss;
    __syncthreads();
    if (wrp == 0) {
        float v = (lane < (blockDim.x >> 5)) ? sh[lane] : 0.f;
#pragma unroll
        for (int o = 16; o; o >>= 1) v += __shfl_xor_sync(~0u, v, o);
        if (lane == 0) sh[32] = v;
    }
    __syncthreads();
    float r = rsqrtf(sh[32] / (float)L + EPS_RMS);
    for (int i = threadIdx.x; i < L; i += blockDim.x) {
        f16 hh, ll; split1(x[i] * r * w[i], hh, ll);
        outh[(long)t * outStride + i] = hh;
        outl[(long)t * outStride + i] = ll;
    }
}

// ---------------- RoPE + repack (Q hi/lo; K,V single plane) ----------------
__global__ void pack_rope_kernel(const int* __restrict__ positions,
                                 const float* __restrict__ q,
                                 const float* __restrict__ kvbuf,
                                 const float* __restrict__ kvup,
                                 f16* __restrict__ qfh, f16* __restrict__ qfl,
                                 f16* __restrict__ kf,  f16* __restrict__ v)
{
    int t   = blockIdx.x;
    int tid = threadIdx.x;
    float pos = (float)positions[t];

    __shared__ float kp[D_ROPE];
    if (tid < 32) {
        int i = tid;
        float inv = expf(-logf(10000.0f) * (2.0f * i) / (float)D_ROPE);
        float ang = pos * inv;
        float c = cosf(ang), s = sinf(ang);
        float x1 = kvbuf[(long)t * KVA_N + KV_LORA + 2 * i];
        float x2 = kvbuf[(long)t * KVA_N + KV_LORA + 2 * i + 1];
        kp[2 * i]     = x1 * c - x2 * s;
        kp[2 * i + 1] = x2 * c + x1 * s;
    }
    __syncthreads();

    for (int idx = tid; idx < NH * QK_HD; idx += blockDim.x) {
        int h = idx / QK_HD, d = idx % QK_HD;
        long dst = ((long)h * T_SEQ + t) * QK_HD + d;
        if (d < D_NOPE) {
            f16 hh, ll;
            split1(q[(long)t * QB_N + h * QK_HD + d], hh, ll);
            qfh[dst] = hh; qfl[dst] = ll;
            kf[dst] = __float2half_rn(kvup[(long)t * KVB_N + h * (D_NOPE + D_V) + d]);
        } else {
            kf[dst] = __float2half_rn(kp[d - D_NOPE]);
        }
    }
    for (int idx = tid; idx < NH * (D_ROPE / 2); idx += blockDim.x) {
        int h = idx / (D_ROPE / 2), i = idx % (D_ROPE / 2);
        float inv = expf(-logf(10000.0f) * (2.0f * i) / (float)D_ROPE);
        float ang = pos * inv;
        float c = cosf(ang), s = sinf(ang);
        long src = (long)t * QB_N + h * QK_HD + D_NOPE;
        float x1 = q[src + 2 * i];
        float x2 = q[src + 2 * i + 1];
        long dst = ((long)h * T_SEQ + t) * QK_HD + D_NOPE;
        f16 hh, ll;
        split1(x1 * c - x2 * s, hh, ll);
        qfh[dst + 2 * i] = hh;     qfl[dst + 2 * i] = ll;
        split1(x2 * c + x1 * s, hh, ll);
        qfh[dst + 2 * i + 1] = hh; qfl[dst + 2 * i + 1] = ll;
    }
    for (int idx = tid; idx < NH * D_V; idx += blockDim.x) {
        int h = idx / D_V, d = idx % D_V;
        v[((long)h * T_SEQ + t) * D_V + d] =
            __float2half_rn(kvup[(long)t * KVB_N + h * (D_NOPE + D_V) + D_NOPE + d]);
    }
}

// ---------------- Launch ----------------
extern "C" void kernel_launch(void* const* d_in, const int* in_sizes, int n_in,
                              void* d_out, int out_size)
{
    const int*   positions = (const int*)  d_in[0];
    const float* hs        = (const float*)d_in[1];
    const float* w_qa      = (const float*)d_in[2];
    const float* qa_ln_w   = (const float*)d_in[3];
    const float* w_qb      = (const float*)d_in[4];
    const float* w_kva     = (const float*)d_in[5];
    const float* kva_ln_w  = (const float*)d_in[6];
    const float* w_kvb     = (const float*)d_in[7];
    const float* w_o       = (const float*)d_in[8];
    float* out = (float*)d_out;

    float *p_qa, *p_q, *p_kv, *p_kvup;
    f16 *hs_h, *hs_l, *wqa, *wqb, *wkva, *wkvb, *wo;
    f16 *qc_h, *qc_l, *kvc_h, *kvc_l, *qf_h, *qf_l, *kf, *v, *at_h, *at_l;

    cudaGetSymbolAddress((void**)&p_qa,   g_qa);
    cudaGetSymbolAddress((void**)&p_q,    g_q);
    cudaGetSymbolAddress((void**)&p_kv,   g_kv);
    cudaGetSymbolAddress((void**)&p_kvup, g_kvup);
    cudaGetSymbolAddress((void**)&hs_h,   g_hs_h);  cudaGetSymbolAddress((void**)&hs_l, g_hs_l);
    cudaGetSymbolAddress((void**)&wqa,    g_wqa);
    cudaGetSymbolAddress((void**)&wqb,    g_wqb);
    cudaGetSymbolAddress((void**)&wkva,   g_wkva);
    cudaGetSymbolAddress((void**)&wkvb,   g_wkvb);
    cudaGetSymbolAddress((void**)&wo,     g_wo);
    cudaGetSymbolAddress((void**)&qc_h,   g_qc_h);  cudaGetSymbolAddress((void**)&qc_l,  g_qc_l);
    cudaGetSymbolAddress((void**)&kvc_h,  g_kvc_h); cudaGetSymbolAddress((void**)&kvc_l, g_kvc_l);
    cudaGetSymbolAddress((void**)&qf_h,   g_qf_h);  cudaGetSymbolAddress((void**)&qf_l,  g_qf_l);
    cudaGetSymbolAddress((void**)&kf,     g_kf);
    cudaGetSymbolAddress((void**)&v,      g_v);
    cudaGetSymbolAddress((void**)&at_h,   g_at_h);  cudaGetSymbolAddress((void**)&at_l,  g_at_l);

    cudaFuncSetAttribute(tgemm_nn,     cudaFuncAttributeMaxDynamicSharedMemorySize, G_SMEM);
    cudaFuncSetAttribute(flash_kernel, cudaFuncAttributeMaxDynamicSharedMemorySize, FA_SMEM);

    dim3 blk(256);
    auto cdiv = [](long a, long b) { return (int)((a + b - 1) / b); };

    // converters
    cvt_split_kernel<<<cdiv((long)T_SEQ * HID / 4, 256), 256>>>(hs, hs_h, hs_l, (long)T_SEQ * HID);
    cvt_single_kernel<<<cdiv((long)HID * Q_LORA / 4, 256), 256>>>(w_qa, wqa, (long)HID * Q_LORA);
    cvt_single_kernel<<<cdiv((long)Q_LORA * QB_N / 4, 256), 256>>>(w_qb, wqb, (long)Q_LORA * QB_N);
    cvt_single_kernel<<<cdiv((long)KV_LORA * KVB_N / 4, 256), 256>>>(w_kvb, wkvb, (long)KV_LORA * KVB_N);
    cvt_single_kernel<<<cdiv((long)O_K * HID / 4, 256), 256>>>(w_o, wo, (long)O_K * HID);
    cvt_pad_single_kernel<<<cdiv((long)HID * KVA_NP, 256), 256>>>(w_kva, wkva, HID, KVA_N, KVA_NP);

    // G1: qa = hs @ w_qa (2048x1536, K=5120)
    tgemm_nn<<<dim3(Q_LORA/BN, T_SEQ/BM), blk, G_SMEM>>>(
        hs_h, hs_l, wqa, p_qa, Q_LORA, HID, HID, Q_LORA, Q_LORA, 1.f);

    // G2: kv = hs @ w_kva (2048x576, padded 640, K=5120)
    tgemm_nn<<<dim3(KVA_NP/BN, T_SEQ/BM), blk, G_SMEM>>>(
        hs_h, hs_l, wkva, p_kv, KVA_N, HID, HID, KVA_NP, KVA_N, 1.f);

    rmsnorm_hl_kernel<<<T_SEQ, 256>>>(p_qa, qa_ln_w, qc_h, qc_l, Q_LORA, Q_LORA, Q_LORA);
    rmsnorm_hl_kernel<<<T_SEQ, 256>>>(p_kv, kva_ln_w, kvc_h, kvc_l, KV_LORA, KVA_N, KV_LORA);

    // G3: q = qc @ w_qb (2048x3072, K=1536)
    tgemm_nn<<<dim3(QB_N/BN, T_SEQ/BM), blk, G_SMEM>>>(
        qc_h, qc_l, wqb, p_q, QB_N, Q_LORA, Q_LORA, QB_N, QB_N, 1.f);

    // G4: kvup = kvc @ w_kvb (2048x4096, K=512)
    tgemm_nn<<<dim3(KVB_N/BN, T_SEQ/BM), blk, G_SMEM>>>(
        kvc_h, kvc_l, wkvb, p_kvup, KVB_N, KV_LORA, KV_LORA, KVB_N, KVB_N, 1.f);

    pack_rope_kernel<<<T_SEQ, 256>>>(positions, p_q, p_kv, p_kvup,
                                     qf_h, qf_l, kf, v);

    // Fused attention
    flash_kernel<<<dim3(NH, T_SEQ / 256), blk, FA_SMEM>>>(
        qf_h, qf_l, kf, v, at_h, at_l);

    // G7: out = attn @ w_o (2048x5120, K=2048)
    tgemm_nn<<<dim3(HID/BN, T_SEQ/BM), blk, G_SMEM>>>(
        at_h, at_l, wo, out, HID, O_K, O_K, HID, HID, 1.f);
}

// round 10
// speedup vs baseline: 1.7847x; 1.3552x over previous
#include <cuda_runtime.h>
#include <cuda_fp16.h>
#include <math.h>
#include <stdint.h>

// ---------------- Problem constants ----------------
#define T_SEQ   2048
#define HID     5120
#define NH      16
#define D_NOPE  128
#define D_ROPE  64
#define D_V     128
#define Q_LORA  1536
#define KV_LORA 512
#define QK_HD   (D_NOPE + D_ROPE)   // 192
#define KVA_N   (KV_LORA + D_ROPE)  // 576
#define KVA_NP  640
#define QB_N    (NH * QK_HD)        // 3072
#define KVB_N   (NH * (D_NOPE + D_V)) // 4096
#define O_K     (NH * D_V)          // 2048

static const float SCALE = 0.07216878364870322f; // 192^-0.5
#define EPS_RMS 1e-6f

typedef __half f16;

// ---------------- Scratch ----------------
__device__ float g_qa   [T_SEQ * Q_LORA];
__device__ float g_q    [T_SEQ * QB_N];
__device__ float g_kv   [T_SEQ * KVA_N];
__device__ float g_kvup [T_SEQ * KVB_N];

__device__ f16 g_hs   [T_SEQ * HID];                 // single plane
__device__ f16 g_wqa  [HID * Q_LORA];
__device__ f16 g_wqb  [Q_LORA * QB_N];
__device__ f16 g_wkva [HID * KVA_NP];
__device__ f16 g_wkvb [KV_LORA * KVB_N];
__device__ f16 g_wo   [O_K * HID];
__device__ f16 g_qc_h [T_SEQ * Q_LORA],   g_qc_l [T_SEQ * Q_LORA];  // split (feeds logits)
__device__ f16 g_kvc  [T_SEQ * KV_LORA];             // single plane
__device__ f16 g_qf_h [(long)NH*T_SEQ*QK_HD], g_qf_l[(long)NH*T_SEQ*QK_HD];
__device__ f16 g_kf   [(long)NH*T_SEQ*QK_HD];
__device__ f16 g_v    [(long)NH*T_SEQ*D_V];
__device__ f16 g_at   [T_SEQ * O_K];                 // single plane

// ---------------- helpers ----------------
__device__ __forceinline__ uint32_t smem_u32(const void* p) {
    return (uint32_t)__cvta_generic_to_shared(p);
}
__device__ __forceinline__ void cp16(uint32_t dst, const void* src) {
    asm volatile("cp.async.cg.shared.global [%0], [%1], 16;\n" :: "r"(dst), "l"(src));
}
__device__ __forceinline__ void cp_commit() {
    asm volatile("cp.async.commit_group;\n");
}
template<int NMAX>
__device__ __forceinline__ void cp_wait() {
    asm volatile("cp.async.wait_group %0;\n" :: "n"(NMAX));
}
__device__ __forceinline__ void ldsm_x4(uint32_t addr, uint32_t r[4]) {
    asm volatile("ldmatrix.sync.aligned.m8n8.x4.shared.b16 {%0,%1,%2,%3}, [%4];"
                 : "=r"(r[0]), "=r"(r[1]), "=r"(r[2]), "=r"(r[3]) : "r"(addr));
}
__device__ __forceinline__ void ldsm_x4_t(uint32_t addr, uint32_t r[4]) {
    asm volatile("ldmatrix.sync.aligned.m8n8.x4.trans.shared.b16 {%0,%1,%2,%3}, [%4];"
                 : "=r"(r[0]), "=r"(r[1]), "=r"(r[2]), "=r"(r[3]) : "r"(addr));
}
__device__ __forceinline__ void mma_f16(float c[4], const uint32_t a[4],
                                        uint32_t b0, uint32_t b1) {
    asm volatile(
        "mma.sync.aligned.m16n8k16.row.col.f32.f16.f16.f32 "
        "{%0,%1,%2,%3}, {%4,%5,%6,%7}, {%8,%9}, {%0,%1,%2,%3};"
        : "+f"(c[0]), "+f"(c[1]), "+f"(c[2]), "+f"(c[3])
        : "r"(a[0]), "r"(a[1]), "r"(a[2]), "r"(a[3]), "r"(b0), "r"(b1));
}
__device__ __forceinline__ uint32_t pack2(f16 a, f16 b) {
    __half2 t = __halves2half2(a, b);
    return *reinterpret_cast<uint32_t*>(&t);
}
__device__ __forceinline__ void split1(float f, f16& h, f16& l) {
    h = __float2half_rn(f);
    l = __float2half_rn(f - __half2float(h));
}

// ---------------- NN tensor GEMM: C = A @ B (fp32 out) ----------------
// ASPLIT=1: A is hi/lo fp16 (2 MMAs per step). ASPLIT=0: single plane (1 MMA).
// 4-stage cp.async ring. M%128==0, K%16==0, B width >= col0+128.
#define BM 128
#define BN 128
#define BK 16

template<int ASPLIT>
__global__ __launch_bounds__(256)
void tgemm_nn(const f16* __restrict__ Ah, const f16* __restrict__ Al,
              const f16* __restrict__ B,
              float* __restrict__ C,
              int N, int K, int lda, int ldb, int ldc, float alpha)
{
    constexpr int B_OFF = ASPLIT ? 12288 : 6144;
    constexpr int STG   = B_OFF + 4352;

    extern __shared__ char smem[];
    int row0 = blockIdx.y * BM;
    int col0 = blockIdx.x * BN;

    int tid  = threadIdx.x;
    int lane = tid & 31;
    int warp = tid >> 5;
    int wm   = warp >> 1;
    int wn   = warp & 1;

    int aRow = tid >> 1;          // 0..127
    int aKc  = (tid & 1) * 8;     // 0 or 8
    int bKr  = tid >> 4;          // 0..15
    int bNc  = (tid & 15) * 8;    // 0..120

    uint32_t sb = smem_u32(smem);

    auto issue = [&](int i) {
        int k0 = i * BK;
        uint32_t stg = sb + (i & 3) * STG;
        cp16(stg + (aRow * 24 + aKc) * 2, &Ah[(long)(row0 + aRow) * lda + k0 + aKc]);
        if (ASPLIT)
            cp16(stg + 6144 + (aRow * 24 + aKc) * 2, &Al[(long)(row0 + aRow) * lda + k0 + aKc]);
        cp16(stg + B_OFF + (bKr * 136 + bNc) * 2, &B[(long)(k0 + bKr) * ldb + col0 + bNc]);
    };

    float acc[2][8][4];
#pragma unroll
    for (int i = 0; i < 2; i++)
#pragma unroll
        for (int j = 0; j < 8; j++)
#pragma unroll
            for (int q = 0; q < 4; q++) acc[i][j][q] = 0.f;

    int ntiles = K / BK;

    issue(0); cp_commit();
    if (ntiles > 1) issue(1);
    cp_commit();

    for (int i = 0; i < ntiles; i++) {
        if (i + 2 < ntiles) issue(i + 2);
        cp_commit();
        cp_wait<2>();
        __syncthreads();

        uint32_t stg = sb + (i & 3) * STG;
        uint32_t a_h[2][4], a_l[2][4];
#pragma unroll
        for (int mt = 0; mt < 2; mt++) {
            int r = wm * 32 + mt * 16 + (lane & 15);
            int c = (lane >> 4) * 8;
            ldsm_x4(stg + (r * 24 + c) * 2, a_h[mt]);
            if (ASPLIT) ldsm_x4(stg + 6144 + (r * 24 + c) * 2, a_l[mt]);
        }
        int rB    = lane & 15;
        int halfB = lane >> 4;
#pragma unroll
        for (int p = 0; p < 4; p++) {
            uint32_t bh[4];
            int c = wn * 64 + p * 16 + halfB * 8;
            ldsm_x4_t(stg + B_OFF + (rB * 136 + c) * 2, bh);
#pragma unroll
            for (int mt = 0; mt < 2; mt++)
#pragma unroll
                for (int j = 0; j < 2; j++) {
                    float* c4 = acc[mt][2 * p + j];
                    mma_f16(c4, a_h[mt], bh[2 * j], bh[2 * j + 1]);
                    if (ASPLIT) mma_f16(c4, a_l[mt], bh[2 * j], bh[2 * j + 1]);
                }
        }
        __syncthreads();
    }

    int gid = lane >> 2, tig = lane & 3;
#pragma unroll
    for (int mt = 0; mt < 2; mt++) {
        int r = row0 + wm * 32 + mt * 16 + gid;
#pragma unroll
        for (int nt = 0; nt < 8; nt++) {
            int c = col0 + wn * 64 + nt * 8 + tig * 2;
            if (c < N) {
                *reinterpret_cast<float2*>(&C[(long)r * ldc + c]) =
                    make_float2(alpha * acc[mt][nt][0], alpha * acc[mt][nt][1]);
                *reinterpret_cast<float2*>(&C[(long)(r + 8) * ldc + c]) =
                    make_float2(alpha * acc[mt][nt][2], alpha * acc[mt][nt][3]);
            }
        }
    }
}
#define G_SMEM_SPLIT  (4 * 16640)
#define G_SMEM_SINGLE (4 * 10496)

// ---------------- Fused flash attention ----------------
// Q: hi/lo fp16 (unscaled). K, V: single fp16. Out: at single fp16.
#define FA_QSZ   (2 * 128 * 200 * 2)
#define FA_STG   6144
#define FA_SMEM  (FA_QSZ + 4 * FA_STG)

__global__ __launch_bounds__(256)
void flash_kernel(const f16* __restrict__ qfh, const f16* __restrict__ qfl,
                  const f16* __restrict__ kf,  const f16* __restrict__ v,
                  f16* __restrict__ at)
{
    extern __shared__ char smem[];
    int h   = blockIdx.x;
    int tid = threadIdx.x;
    int lane = tid & 31;
    int wid  = tid >> 5;
    int wrow = wid * 16;

    uint32_t sQh = smem_u32(smem);
    uint32_t sQl = sQh + 128 * 200 * 2;
    uint32_t stg = sQh + FA_QSZ;

    const long hT = (long)h * T_SEQ;

    auto loadQ = [&](int i0) {
#pragma unroll
        for (int it = 0; it < 12; it++) {
            int u = it * 256 + tid;
            int row = u / 24, off = (u % 24) * 8;
            cp16(sQh + (row * 200 + off) * 2, qfh + (hT + i0 + row) * QK_HD + off);
            cp16(sQl + (row * 200 + off) * 2, qfl + (hT + i0 + row) * QK_HD + off);
        }
    };
    auto load_chunk = [&](int c) {
        uint32_t st = stg + (c & 3) * FA_STG;
        int j = c / 20, r = c % 20;
        if (r < 12) {
            int d0 = r * 16;
            int row = tid >> 1, off = (tid & 1) * 8;
            cp16(st + (row * 24 + off) * 2, kf + (hT + j * 128 + row) * QK_HD + d0 + off);
        } else {
            int q0 = (r - 12) * 16;
            int row = tid >> 4, off = (tid & 15) * 8;
            cp16(st + (row * 136 + off) * 2, v + (hT + j * 128 + q0 + row) * D_V + off);
        }
    };

    for (int rep = 0; rep < 2; rep++) {
        int iblk = rep == 0 ? blockIdx.y : (T_SEQ / 128 - 1) - blockIdx.y;
        int i0   = iblk * 128;
        int nch  = (iblk + 1) * 20;

        float s[16][4], o[16][4];
        float m0 = -1e30f, m1 = -1e30f, l0 = 0.f, l1 = 0.f;
#pragma unroll
        for (int nt = 0; nt < 16; nt++)
#pragma unroll
            for (int q = 0; q < 4; q++) o[nt][q] = 0.f;

        __syncthreads();
        loadQ(i0);
        load_chunk(0); cp_commit();
        load_chunk(1); cp_commit();

        int lr0 = wrow + (lane >> 2);
        int lr1 = lr0 + 8;

        for (int c = 0; c < nch; c++) {
            if (c + 2 < nch) load_chunk(c + 2);
            cp_commit();
            cp_wait<2>();
            __syncthreads();

            uint32_t st = stg + (c & 3) * FA_STG;
            int j = c / 20, r = c % 20;

            if (r < 12) {
                if (r == 0) {
#pragma unroll
                    for (int nt = 0; nt < 16; nt++)
#pragma unroll
                        for (int q = 0; q < 4; q++) s[nt][q] = 0.f;
                }
                uint32_t a_h[4], a_l[4];
                int ar = wrow + (lane & 15);
                int ac = r * 16 + (lane >> 4) * 8;
                ldsm_x4(sQh + (ar * 200 + ac) * 2, a_h);
                ldsm_x4(sQl + (ar * 200 + ac) * 2, a_l);
                int g = lane >> 3, rr = lane & 7;
                int nbase = ((g >> 1) << 3) + rr;
                int cc = (g & 1) * 8;
#pragma unroll
                for (int p = 0; p < 8; p++) {
                    uint32_t bh[4];
                    ldsm_x4(st + ((p * 16 + nbase) * 24 + cc) * 2, bh);
#pragma unroll
                    for (int jj = 0; jj < 2; jj++) {
                        float* c4 = s[2 * p + jj];
                        mma_f16(c4, a_h, bh[2 * jj], bh[2 * jj + 1]);
                        mma_f16(c4, a_l, bh[2 * jj], bh[2 * jj + 1]);
                    }
                }
                if (r == 11) {
#pragma unroll
                    for (int nt = 0; nt < 16; nt++)
#pragma unroll
                        for (int q = 0; q < 4; q++) s[nt][q] *= SCALE;
                    if (j == iblk) {
#pragma unroll
                        for (int nt = 0; nt < 16; nt++) {
                            int c0 = nt * 8 + ((lane & 3) << 1);
                            if (c0     > lr0) s[nt][0] = -1e30f;
                            if (c0 + 1 > lr0) s[nt][1] = -1e30f;
                            if (c0     > lr1) s[nt][2] = -1e30f;
                            if (c0 + 1 > lr1) s[nt][3] = -1e30f;
                        }
                    }
                    float mr0 = -1e30f, mr1 = -1e30f;
#pragma unroll
                    for (int nt = 0; nt < 16; nt++) {
                        mr0 = fmaxf(mr0, fmaxf(s[nt][0], s[nt][1]));
                        mr1 = fmaxf(mr1, fmaxf(s[nt][2], s[nt][3]));
                    }
                    mr0 = fmaxf(mr0, __shfl_xor_sync(~0u, mr0, 1));
                    mr0 = fmaxf(mr0, __shfl_xor_sync(~0u, mr0, 2));
                    mr1 = fmaxf(mr1, __shfl_xor_sync(~0u, mr1, 1));
                    mr1 = fmaxf(mr1, __shfl_xor_sync(~0u, mr1, 2));
                    float mn0 = fmaxf(m0, mr0), mn1 = fmaxf(m1, mr1);
                    float sc0 = __expf(m0 - mn0), sc1 = __expf(m1 - mn1);
                    float rs0 = 0.f, rs1 = 0.f;
#pragma unroll
                    for (int nt = 0; nt < 16; nt++) {
                        s[nt][0] = __expf(s[nt][0] - mn0); rs0 += s[nt][0];
                        s[nt][1] = __expf(s[nt][1] - mn0); rs0 += s[nt][1];
                        s[nt][2] = __expf(s[nt][2] - mn1); rs1 += s[nt][2];
                        s[nt][3] = __expf(s[nt][3] - mn1); rs1 += s[nt][3];
                    }
                    rs0 += __shfl_xor_sync(~0u, rs0, 1); rs0 += __shfl_xor_sync(~0u, rs0, 2);
                    rs1 += __shfl_xor_sync(~0u, rs1, 1); rs1 += __shfl_xor_sync(~0u, rs1, 2);
                    l0 = l0 * sc0 + rs0;  l1 = l1 * sc1 + rs1;
                    m0 = mn0; m1 = mn1;
#pragma unroll
                    for (int nt = 0; nt < 16; nt++) {
                        o[nt][0] *= sc0; o[nt][1] *= sc0;
                        o[nt][2] *= sc1; o[nt][3] *= sc1;
                    }
                }
            } else {
                int q = r - 12;
                uint32_t ah[4], al[4];
                {
                    const float* t0 = s[2 * q];
                    const float* t1 = s[2 * q + 1];
                    f16 hA, lA, hB, lB;
                    split1(t0[0], hA, lA); split1(t0[1], hB, lB);
                    ah[0] = pack2(hA, hB); al[0] = pack2(lA, lB);
                    split1(t0[2], hA, lA); split1(t0[3], hB, lB);
                    ah[1] = pack2(hA, hB); al[1] = pack2(lA, lB);
                    split1(t1[0], hA, lA); split1(t1[1], hB, lB);
                    ah[2] = pack2(hA, hB); al[2] = pack2(lA, lB);
                    split1(t1[2], hA, lA); split1(t1[3], hB, lB);
                    ah[3] = pack2(hA, hB); al[3] = pack2(lA, lB);
                }
                int rv = lane & 15, half = lane >> 4;
#pragma unroll
                for (int pp = 0; pp < 8; pp++) {
                    uint32_t bh[4];
                    int cV = pp * 16 + half * 8;
                    ldsm_x4_t(st + (rv * 136 + cV) * 2, bh);
#pragma unroll
                    for (int jj = 0; jj < 2; jj++) {
                        float* c4 = o[2 * pp + jj];
                        mma_f16(c4, ah, bh[2 * jj], bh[2 * jj + 1]);
                        mma_f16(c4, al, bh[2 * jj], bh[2 * jj + 1]);
                    }
                }
            }
            __syncthreads();
        }

        float inv0 = 1.f / l0, inv1 = 1.f / l1;
        int gr0 = i0 + lr0;
#pragma unroll
        for (int nt = 0; nt < 16; nt++) {
            int col = h * D_V + nt * 8 + ((lane & 3) << 1);
            *reinterpret_cast<uint32_t*>(&at[(long)gr0 * O_K + col]) =
                pack2(__float2half_rn(o[nt][0] * inv0), __float2half_rn(o[nt][1] * inv0));
            *reinterpret_cast<uint32_t*>(&at[(long)(gr0 + 8) * O_K + col]) =
                pack2(__float2half_rn(o[nt][2] * inv1), __float2half_rn(o[nt][3] * inv1));
        }
    }
}

// ---------------- converters (8 elts/thread) ----------------
__global__ void cvt_single_kernel(const float* __restrict__ src,
                                  f16* __restrict__ h, long n)
{
    long i = ((long)blockIdx.x * blockDim.x + threadIdx.x) * 8;
    if (i >= n) return;
    float4 v0 = *reinterpret_cast<const float4*>(&src[i]);
    float4 v1 = *reinterpret_cast<const float4*>(&src[i + 4]);
    uint4 o;
    o.x = pack2(__float2half_rn(v0.x), __float2half_rn(v0.y));
    o.y = pack2(__float2half_rn(v0.z), __float2half_rn(v0.w));
    o.z = pack2(__float2half_rn(v1.x), __float2half_rn(v1.y));
    o.w = pack2(__float2half_rn(v1.z), __float2half_rn(v1.w));
    *reinterpret_cast<uint4*>(&h[i]) = o;
}
__global__ void cvt_pad_single_kernel(const float* __restrict__ src,
                                      f16* __restrict__ h,
                                      int rows, int srcN, int dstN)
{
    long i = (long)blockIdx.x * blockDim.x + threadIdx.x;
    long total = (long)rows * dstN;
    if (i >= total) return;
    int r = (int)(i / dstN), c = (int)(i % dstN);
    float vv = (c < srcN) ? src[(long)r * srcN + c] : 0.f;
    h[i] = __float2half_rn(vv);
}

// ---------------- RMSNorm (hi/lo if outl != null, else single) ----------------
__global__ void rmsnorm_hl_kernel(const float* __restrict__ in,
                                  const float* __restrict__ w,
                                  f16* __restrict__ outh, f16* __restrict__ outl,
                                  int L, int inStride, int outStride)
{
    int t = blockIdx.x;
    const float* x = in + (long)t * inStride;

    float ss = 0.f;
    for (int i = threadIdx.x; i < L; i += blockDim.x) {
        float v = x[i]; ss += v * v;
    }
    __shared__ float sh[33];
#pragma unroll
    for (int o = 16; o; o >>= 1) ss += __shfl_xor_sync(~0u, ss, o);
    int lane = threadIdx.x & 31, wrp = threadIdx.x >> 5;
    if (lane == 0) sh[wrp] = ss;
    __syncthreads();
    if (wrp == 0) {
        float v = (lane < (blockDim.x >> 5)) ? sh[lane] : 0.f;
#pragma unroll
        for (int o = 16; o; o >>= 1) v += __shfl_xor_sync(~0u, v, o);
        if (lane == 0) sh[32] = v;
    }
    __syncthreads();
    float r = rsqrtf(sh[32] / (float)L + EPS_RMS);
    if (outl) {
        for (int i = threadIdx.x; i < L; i += blockDim.x) {
            f16 hh, ll; split1(x[i] * r * w[i], hh, ll);
            outh[(long)t * outStride + i] = hh;
            outl[(long)t * outStride + i] = ll;
        }
    } else {
        for (int i = threadIdx.x; i < L; i += blockDim.x)
            outh[(long)t * outStride + i] = __float2half_rn(x[i] * r * w[i]);
    }
}

// ---------------- RoPE + repack ----------------
__global__ void pack_rope_kernel(const int* __restrict__ positions,
                                 const float* __restrict__ q,
                                 const float* __restrict__ kvbuf,
                                 const float* __restrict__ kvup,
                                 f16* __restrict__ qfh, f16* __restrict__ qfl,
                                 f16* __restrict__ kf,  f16* __restrict__ v)
{
    int t   = blockIdx.x;
    int tid = threadIdx.x;
    float pos = (float)positions[t];

    __shared__ float kp[D_ROPE];
    if (tid < 32) {
        int i = tid;
        float inv = expf(-logf(10000.0f) * (2.0f * i) / (float)D_ROPE);
        float ang = pos * inv;
        float c = cosf(ang), s = sinf(ang);
        float x1 = kvbuf[(long)t * KVA_N + KV_LORA + 2 * i];
        float x2 = kvbuf[(long)t * KVA_N + KV_LORA + 2 * i + 1];
        kp[2 * i]     = x1 * c - x2 * s;
        kp[2 * i + 1] = x2 * c + x1 * s;
    }
    __syncthreads();

    for (int idx = tid; idx < NH * QK_HD; idx += blockDim.x) {
        int h = idx / QK_HD, d = idx % QK_HD;
        long dst = ((long)h * T_SEQ + t) * QK_HD + d;
        if (d < D_NOPE) {
            f16 hh, ll;
            split1(q[(long)t * QB_N + h * QK_HD + d], hh, ll);
            qfh[dst] = hh; qfl[dst] = ll;
            kf[dst] = __float2half_rn(kvup[(long)t * KVB_N + h * (D_NOPE + D_V) + d]);
        } else {
            kf[dst] = __float2half_rn(kp[d - D_NOPE]);
        }
    }
    for (int idx = tid; idx < NH * (D_ROPE / 2); idx += blockDim.x) {
        int h = idx / (D_ROPE / 2), i = idx % (D_ROPE / 2);
        float inv = expf(-logf(10000.0f) * (2.0f * i) / (float)D_ROPE);
        float ang = pos * inv;
        float c = cosf(ang), s = sinf(ang);
        long src = (long)t * QB_N + h * QK_HD + D_NOPE;
        float x1 = q[src + 2 * i];
        float x2 = q[src + 2 * i + 1];
        long dst = ((long)h * T_SEQ + t) * QK_HD + D_NOPE;
        f16 hh, ll;
        split1(x1 * c - x2 * s, hh, ll);
        qfh[dst + 2 * i] = hh;     qfl[dst + 2 * i] = ll;
        split1(x2 * c + x1 * s, hh, ll);
        qfh[dst + 2 * i + 1] = hh; qfl[dst + 2 * i + 1] = ll;
    }
    for (int idx = tid; idx < NH * D_V; idx += blockDim.x) {
        int h = idx / D_V, d = idx % D_V;
        v[((long)h * T_SEQ + t) * D_V + d] =
            __float2half_rn(kvup[(long)t * KVB_N + h * (D_NOPE + D_V) + D_NOPE + d]);
    }
}

// ---------------- Launch ----------------
extern "C" void kernel_launch(void* const* d_in, const int* in_sizes, int n_in,
                              void* d_out, int out_size)
{
    const int*   positions = (const int*)  d_in[0];
    const float* hs        = (const float*)d_in[1];
    const float* w_qa      = (const float*)d_in[2];
    const float* qa_ln_w   = (const float*)d_in[3];
    const float* w_qb      = (const float*)d_in[4];
    const float* w_kva     = (const float*)d_in[5];
    const float* kva_ln_w  = (const float*)d_in[6];
    const float* w_kvb     = (const float*)d_in[7];
    const float* w_o       = (const float*)d_in[8];
    float* out = (float*)d_out;

    float *p_qa, *p_q, *p_kv, *p_kvup;
    f16 *phs, *wqa, *wqb, *wkva, *wkvb, *wo;
    f16 *qc_h, *qc_l, *kvc, *qf_h, *qf_l, *kf, *v, *at;

    cudaGetSymbolAddress((void**)&p_qa,   g_qa);
    cudaGetSymbolAddress((void**)&p_q,    g_q);
    cudaGetSymbolAddress((void**)&p_kv,   g_kv);
    cudaGetSymbolAddress((void**)&p_kvup, g_kvup);
    cudaGetSymbolAddress((void**)&phs,    g_hs);
    cudaGetSymbolAddress((void**)&wqa,    g_wqa);
    cudaGetSymbolAddress((void**)&wqb,    g_wqb);
    cudaGetSymbolAddress((void**)&wkva,   g_wkva);
    cudaGetSymbolAddress((void**)&wkvb,   g_wkvb);
    cudaGetSymbolAddress((void**)&wo,     g_wo);
    cudaGetSymbolAddress((void**)&qc_h,   g_qc_h);  cudaGetSymbolAddress((void**)&qc_l, g_qc_l);
    cudaGetSymbolAddress((void**)&kvc,    g_kvc);
    cudaGetSymbolAddress((void**)&qf_h,   g_qf_h);  cudaGetSymbolAddress((void**)&qf_l, g_qf_l);
    cudaGetSymbolAddress((void**)&kf,     g_kf);
    cudaGetSymbolAddress((void**)&v,      g_v);
    cudaGetSymbolAddress((void**)&at,     g_at);

    cudaFuncSetAttribute(tgemm_nn<1>,  cudaFuncAttributeMaxDynamicSharedMemorySize, G_SMEM_SPLIT);
    cudaFuncSetAttribute(tgemm_nn<0>,  cudaFuncAttributeMaxDynamicSharedMemorySize, G_SMEM_SINGLE);
    cudaFuncSetAttribute(flash_kernel, cudaFuncAttributeMaxDynamicSharedMemorySize, FA_SMEM);

    dim3 blk(256);
    auto cdiv = [](long a, long b) { return (int)((a + b - 1) / b); };

    // converters
    cvt_single_kernel<<<cdiv((long)T_SEQ * HID / 8, 256), 256>>>(hs, phs, (long)T_SEQ * HID);
    cvt_single_kernel<<<cdiv((long)HID * Q_LORA / 8, 256), 256>>>(w_qa, wqa, (long)HID * Q_LORA);
    cvt_single_kernel<<<cdiv((long)Q_LORA * QB_N / 8, 256), 256>>>(w_qb, wqb, (long)Q_LORA * QB_N);
    cvt_single_kernel<<<cdiv((long)KV_LORA * KVB_N / 8, 256), 256>>>(w_kvb, wkvb, (long)KV_LORA * KVB_N);
    cvt_single_kernel<<<cdiv((long)O_K * HID / 8, 256), 256>>>(w_o, wo, (long)O_K * HID);
    cvt_pad_single_kernel<<<cdiv((long)HID * KVA_NP, 256), 256>>>(w_kva, wkva, HID, KVA_N, KVA_NP);

    // G1: qa = hs @ w_qa (single-plane A)
    tgemm_nn<0><<<dim3(Q_LORA/BN, T_SEQ/BM), blk, G_SMEM_SINGLE>>>(
        phs, nullptr, wqa, p_qa, Q_LORA, HID, HID, Q_LORA, Q_LORA, 1.f);

    // G2: kv = hs @ w_kva (single-plane A)
    tgemm_nn<0><<<dim3(KVA_NP/BN, T_SEQ/BM), blk, G_SMEM_SINGLE>>>(
        phs, nullptr, wkva, p_kv, KVA_N, HID, HID, KVA_NP, KVA_N, 1.f);

    rmsnorm_hl_kernel<<<T_SEQ, 256>>>(p_qa, qa_ln_w, qc_h, qc_l, Q_LORA, Q_LORA, Q_LORA);
    rmsnorm_hl_kernel<<<T_SEQ, 256>>>(p_kv, kva_ln_w, kvc, nullptr, KV_LORA, KVA_N, KV_LORA);

    // G3: q = qc @ w_qb (SPLIT A — feeds logits)
    tgemm_nn<1><<<dim3(QB_N/BN, T_SEQ/BM), blk, G_SMEM_SPLIT>>>(
        qc_h, qc_l, wqb, p_q, QB_N, Q_LORA, Q_LORA, QB_N, QB_N, 1.f);

    // G4: kvup = kvc @ w_kvb (single-plane A)
    tgemm_nn<0><<<dim3(KVB_N/BN, T_SEQ/BM), blk, G_SMEM_SINGLE>>>(
        kvc, nullptr, wkvb, p_kvup, KVB_N, KV_LORA, KV_LORA, KVB_N, KVB_N, 1.f);

    pack_rope_kernel<<<T_SEQ, 256>>>(positions, p_q, p_kv, p_kvup,
                                     qf_h, qf_l, kf, v);

    // Fused attention (Q split, P split)
    flash_kernel<<<dim3(NH, T_SEQ / 256), blk, FA_SMEM>>>(
        qf_h, qf_l, kf, v, at);

    // G7: out = attn @ w_o (single-plane A) — w_o is [O_K][HID], ldb = HID
    tgemm_nn<0><<<dim3(HID/BN, T_SEQ/BM), blk, G_SMEM_SINGLE>>>(
        at, nullptr, wo, out, HID, O_K, O_K, HID, HID, 1.f);
}

// round 11
// speedup vs baseline: 1.9767x; 1.1075x over previous
#include <cuda_runtime.h>
#include <cuda_fp16.h>
#include <math.h>
#include <stdint.h>

// ---------------- Problem constants ----------------
#define T_SEQ   2048
#define HID     5120
#define NH      16
#define D_NOPE  128
#define D_ROPE  64
#define D_V     128
#define Q_LORA  1536
#define KV_LORA 512
#define QK_HD   (D_NOPE + D_ROPE)   // 192
#define KVA_N   (KV_LORA + D_ROPE)  // 576
#define KVA_NP  640
#define QB_N    (NH * QK_HD)        // 3072
#define KVB_N   (NH * (D_NOPE + D_V)) // 4096
#define O_K     (NH * D_V)          // 2048

static const float SCALE = 0.07216878364870322f; // 192^-0.5
#define EPS_RMS 1e-6f

typedef __half f16;

// ---------------- Scratch ----------------
__device__ float g_qa   [T_SEQ * Q_LORA];
__device__ float g_q    [T_SEQ * QB_N];
__device__ float g_kv   [T_SEQ * KVA_N];
__device__ float g_kvup [T_SEQ * KVB_N];

__device__ f16 g_hs   [T_SEQ * HID];
__device__ f16 g_wqa  [HID * Q_LORA];
__device__ f16 g_wqb  [Q_LORA * QB_N];
__device__ f16 g_wkva [HID * KVA_NP];
__device__ f16 g_wkvb [KV_LORA * KVB_N];
__device__ f16 g_wo   [O_K * HID];
__device__ f16 g_qc   [T_SEQ * Q_LORA];              // single plane now
__device__ f16 g_kvc  [T_SEQ * KV_LORA];
__device__ f16 g_qf   [(long)NH*T_SEQ*QK_HD];        // single plane now
__device__ f16 g_kf   [(long)NH*T_SEQ*QK_HD];
__device__ f16 g_v    [(long)NH*T_SEQ*D_V];
__device__ f16 g_at   [T_SEQ * O_K];

// ---------------- helpers ----------------
__device__ __forceinline__ uint32_t smem_u32(const void* p) {
    return (uint32_t)__cvta_generic_to_shared(p);
}
__device__ __forceinline__ void cp16(uint32_t dst, const void* src) {
    asm volatile("cp.async.cg.shared.global [%0], [%1], 16;\n" :: "r"(dst), "l"(src));
}
__device__ __forceinline__ void cp_commit() {
    asm volatile("cp.async.commit_group;\n");
}
template<int NMAX>
__device__ __forceinline__ void cp_wait() {
    asm volatile("cp.async.wait_group %0;\n" :: "n"(NMAX));
}
__device__ __forceinline__ void ldsm_x4(uint32_t addr, uint32_t r[4]) {
    asm volatile("ldmatrix.sync.aligned.m8n8.x4.shared.b16 {%0,%1,%2,%3}, [%4];"
                 : "=r"(r[0]), "=r"(r[1]), "=r"(r[2]), "=r"(r[3]) : "r"(addr));
}
__device__ __forceinline__ void ldsm_x4_t(uint32_t addr, uint32_t r[4]) {
    asm volatile("ldmatrix.sync.aligned.m8n8.x4.trans.shared.b16 {%0,%1,%2,%3}, [%4];"
                 : "=r"(r[0]), "=r"(r[1]), "=r"(r[2]), "=r"(r[3]) : "r"(addr));
}
__device__ __forceinline__ void mma_f16(float c[4], const uint32_t a[4],
                                        uint32_t b0, uint32_t b1) {
    asm volatile(
        "mma.sync.aligned.m16n8k16.row.col.f32.f16.f16.f32 "
        "{%0,%1,%2,%3}, {%4,%5,%6,%7}, {%8,%9}, {%0,%1,%2,%3};"
        : "+f"(c[0]), "+f"(c[1]), "+f"(c[2]), "+f"(c[3])
        : "r"(a[0]), "r"(a[1]), "r"(a[2]), "r"(a[3]), "r"(b0), "r"(b1));
}
__device__ __forceinline__ uint32_t pack2(f16 a, f16 b) {
    __half2 t = __halves2half2(a, b);
    return *reinterpret_cast<uint32_t*>(&t);
}
__device__ __forceinline__ void split1(float f, f16& h, f16& l) {
    h = __float2half_rn(f);
    l = __float2half_rn(f - __half2float(h));
}

// ---------------- NN tensor GEMM: C = A @ B (fp32 out) ----------------
// ASPLIT=1: A is hi/lo fp16 (2 MMAs per step). ASPLIT=0: single plane (1 MMA).
// 4-stage cp.async ring, prefetch depth 2, ONE sync per tile
// (issue(i+2) writes stage (i-2)%4; laggards read (i-1)%4 or i%4 — disjoint).
#define BM 128
#define BN 128
#define BK 16

template<int ASPLIT>
__global__ __launch_bounds__(256)
void tgemm_nn(const f16* __restrict__ Ah, const f16* __restrict__ Al,
              const f16* __restrict__ B,
              float* __restrict__ C,
              int N, int K, int lda, int ldb, int ldc, float alpha)
{
    constexpr int B_OFF = ASPLIT ? 12288 : 6144;
    constexpr int STG   = B_OFF + 4352;

    extern __shared__ char smem[];
    int row0 = blockIdx.y * BM;
    int col0 = blockIdx.x * BN;

    int tid  = threadIdx.x;
    int lane = tid & 31;
    int warp = tid >> 5;
    int wm   = warp >> 1;
    int wn   = warp & 1;

    int aRow = tid >> 1;          // 0..127
    int aKc  = (tid & 1) * 8;     // 0 or 8
    int bKr  = tid >> 4;          // 0..15
    int bNc  = (tid & 15) * 8;    // 0..120

    uint32_t sb = smem_u32(smem);

    auto issue = [&](int i) {
        int k0 = i * BK;
        uint32_t stg = sb + (i & 3) * STG;
        cp16(stg + (aRow * 24 + aKc) * 2, &Ah[(long)(row0 + aRow) * lda + k0 + aKc]);
        if (ASPLIT)
            cp16(stg + 6144 + (aRow * 24 + aKc) * 2, &Al[(long)(row0 + aRow) * lda + k0 + aKc]);
        cp16(stg + B_OFF + (bKr * 136 + bNc) * 2, &B[(long)(k0 + bKr) * ldb + col0 + bNc]);
    };

    float acc[2][8][4];
#pragma unroll
    for (int i = 0; i < 2; i++)
#pragma unroll
        for (int j = 0; j < 8; j++)
#pragma unroll
            for (int q = 0; q < 4; q++) acc[i][j][q] = 0.f;

    int ntiles = K / BK;

    issue(0); cp_commit();
    if (ntiles > 1) issue(1);
    cp_commit();

    for (int i = 0; i < ntiles; i++) {
        if (i + 2 < ntiles) issue(i + 2);
        cp_commit();
        cp_wait<2>();
        __syncthreads();

        uint32_t stg = sb + (i & 3) * STG;
        uint32_t a_h[2][4], a_l[2][4];
#pragma unroll
        for (int mt = 0; mt < 2; mt++) {
            int r = wm * 32 + mt * 16 + (lane & 15);
            int c = (lane >> 4) * 8;
            ldsm_x4(stg + (r * 24 + c) * 2, a_h[mt]);
            if (ASPLIT) ldsm_x4(stg + 6144 + (r * 24 + c) * 2, a_l[mt]);
        }
        int rB    = lane & 15;
        int halfB = lane >> 4;
#pragma unroll
        for (int p = 0; p < 4; p++) {
            uint32_t bh[4];
            int c = wn * 64 + p * 16 + halfB * 8;
            ldsm_x4_t(stg + B_OFF + (rB * 136 + c) * 2, bh);
#pragma unroll
            for (int mt = 0; mt < 2; mt++)
#pragma unroll
                for (int j = 0; j < 2; j++) {
                    float* c4 = acc[mt][2 * p + j];
                    mma_f16(c4, a_h[mt], bh[2 * j], bh[2 * j + 1]);
                    if (ASPLIT) mma_f16(c4, a_l[mt], bh[2 * j], bh[2 * j + 1]);
                }
        }
        // no trailing sync — 4-stage ring keeps writes 2 stages ahead of reads
    }

    int gid = lane >> 2, tig = lane & 3;
#pragma unroll
    for (int mt = 0; mt < 2; mt++) {
        int r = row0 + wm * 32 + mt * 16 + gid;
#pragma unroll
        for (int nt = 0; nt < 8; nt++) {
            int c = col0 + wn * 64 + nt * 8 + tig * 2;
            if (c < N) {
                *reinterpret_cast<float2*>(&C[(long)r * ldc + c]) =
                    make_float2(alpha * acc[mt][nt][0], alpha * acc[mt][nt][1]);
                *reinterpret_cast<float2*>(&C[(long)(r + 8) * ldc + c]) =
                    make_float2(alpha * acc[mt][nt][2], alpha * acc[mt][nt][3]);
            }
        }
    }
}
#define G_SMEM_SINGLE (4 * 10496)

// ---------------- Fused flash attention ----------------
// Q, K, V: single fp16 planes. P kept split for P@V accumulation accuracy.
#define FA_QSZ   (128 * 200 * 2)       // 51200 (Q hi only)
#define FA_STG   6144
#define FA_SMEM  (FA_QSZ + 4 * FA_STG) // 75776

__global__ __launch_bounds__(256)
void flash_kernel(const f16* __restrict__ qf,
                  const f16* __restrict__ kf,  const f16* __restrict__ v,
                  f16* __restrict__ at)
{
    extern __shared__ char smem[];
    int h   = blockIdx.x;
    int tid = threadIdx.x;
    int lane = tid & 31;
    int wid  = tid >> 5;
    int wrow = wid * 16;

    uint32_t sQ  = smem_u32(smem);
    uint32_t stg = sQ + FA_QSZ;

    const long hT = (long)h * T_SEQ;

    auto loadQ = [&](int i0) {
#pragma unroll
        for (int it = 0; it < 12; it++) {
            int u = it * 256 + tid;
            int row = u / 24, off = (u % 24) * 8;
            cp16(sQ + (row * 200 + off) * 2, qf + (hT + i0 + row) * QK_HD + off);
        }
    };
    auto load_chunk = [&](int c) {
        uint32_t st = stg + (c & 3) * FA_STG;
        int j = c / 20, r = c % 20;
        if (r < 12) {
            int d0 = r * 16;
            int row = tid >> 1, off = (tid & 1) * 8;
            cp16(st + (row * 24 + off) * 2, kf + (hT + j * 128 + row) * QK_HD + d0 + off);
        } else {
            int q0 = (r - 12) * 16;
            int row = tid >> 4, off = (tid & 15) * 8;
            cp16(st + (row * 136 + off) * 2, v + (hT + j * 128 + q0 + row) * D_V + off);
        }
    };

    for (int rep = 0; rep < 2; rep++) {
        int iblk = rep == 0 ? blockIdx.y : (T_SEQ / 128 - 1) - blockIdx.y;
        int i0   = iblk * 128;
        int nch  = (iblk + 1) * 20;

        float s[16][4], o[16][4];
        float m0 = -1e30f, m1 = -1e30f, l0 = 0.f, l1 = 0.f;
#pragma unroll
        for (int nt = 0; nt < 16; nt++)
#pragma unroll
            for (int q = 0; q < 4; q++) o[nt][q] = 0.f;

        __syncthreads();               // guard smem reuse across reps
        loadQ(i0);
        load_chunk(0); cp_commit();
        load_chunk(1); cp_commit();

        int lr0 = wrow + (lane >> 2);
        int lr1 = lr0 + 8;

        for (int c = 0; c < nch; c++) {
            if (c + 2 < nch) load_chunk(c + 2);
            cp_commit();
            cp_wait<2>();
            __syncthreads();

            uint32_t st = stg + (c & 3) * FA_STG;
            int j = c / 20, r = c % 20;

            if (r < 12) {
                if (r == 0) {
#pragma unroll
                    for (int nt = 0; nt < 16; nt++)
#pragma unroll
                        for (int q = 0; q < 4; q++) s[nt][q] = 0.f;
                }
                uint32_t a_h[4];
                int ar = wrow + (lane & 15);
                int ac = r * 16 + (lane >> 4) * 8;
                ldsm_x4(sQ + (ar * 200 + ac) * 2, a_h);
                int g = lane >> 3, rr = lane & 7;
                int nbase = ((g >> 1) << 3) + rr;
                int cc = (g & 1) * 8;
#pragma unroll
                for (int p = 0; p < 8; p++) {
                    uint32_t bh[4];
                    ldsm_x4(st + ((p * 16 + nbase) * 24 + cc) * 2, bh);
#pragma unroll
                    for (int jj = 0; jj < 2; jj++)
                        mma_f16(s[2 * p + jj], a_h, bh[2 * jj], bh[2 * jj + 1]);
                }
                if (r == 11) {
#pragma unroll
                    for (int nt = 0; nt < 16; nt++)
#pragma unroll
                        for (int q = 0; q < 4; q++) s[nt][q] *= SCALE;
                    if (j == iblk) {
#pragma unroll
                        for (int nt = 0; nt < 16; nt++) {
                            int c0 = nt * 8 + ((lane & 3) << 1);
                            if (c0     > lr0) s[nt][0] = -1e30f;
                            if (c0 + 1 > lr0) s[nt][1] = -1e30f;
                            if (c0     > lr1) s[nt][2] = -1e30f;
                            if (c0 + 1 > lr1) s[nt][3] = -1e30f;
                        }
                    }
                    float mr0 = -1e30f, mr1 = -1e30f;
#pragma unroll
                    for (int nt = 0; nt < 16; nt++) {
                        mr0 = fmaxf(mr0, fmaxf(s[nt][0], s[nt][1]));
                        mr1 = fmaxf(mr1, fmaxf(s[nt][2], s[nt][3]));
                    }
                    mr0 = fmaxf(mr0, __shfl_xor_sync(~0u, mr0, 1));
                    mr0 = fmaxf(mr0, __shfl_xor_sync(~0u, mr0, 2));
                    mr1 = fmaxf(mr1, __shfl_xor_sync(~0u, mr1, 1));
                    mr1 = fmaxf(mr1, __shfl_xor_sync(~0u, mr1, 2));
                    float mn0 = fmaxf(m0, mr0), mn1 = fmaxf(m1, mr1);
                    float sc0 = __expf(m0 - mn0), sc1 = __expf(m1 - mn1);
                    float rs0 = 0.f, rs1 = 0.f;
#pragma unroll
                    for (int nt = 0; nt < 16; nt++) {
                        s[nt][0] = __expf(s[nt][0] - mn0); rs0 += s[nt][0];
                        s[nt][1] = __expf(s[nt][1] - mn0); rs0 += s[nt][1];
                        s[nt][2] = __expf(s[nt][2] - mn1); rs1 += s[nt][2];
                        s[nt][3] = __expf(s[nt][3] - mn1); rs1 += s[nt][3];
                    }
                    rs0 += __shfl_xor_sync(~0u, rs0, 1); rs0 += __shfl_xor_sync(~0u, rs0, 2);
                    rs1 += __shfl_xor_sync(~0u, rs1, 1); rs1 += __shfl_xor_sync(~0u, rs1, 2);
                    l0 = l0 * sc0 + rs0;  l1 = l1 * sc1 + rs1;
                    m0 = mn0; m1 = mn1;
#pragma unroll
                    for (int nt = 0; nt < 16; nt++) {
                        o[nt][0] *= sc0; o[nt][1] *= sc0;
                        o[nt][2] *= sc1; o[nt][3] *= sc1;
                    }
                }
            } else {
                // O += P @ V (P split for accumulation accuracy)
                int q = r - 12;
                uint32_t ah[4], al[4];
                {
                    const float* t0 = s[2 * q];
                    const float* t1 = s[2 * q + 1];
                    f16 hA, lA, hB, lB;
                    split1(t0[0], hA, lA); split1(t0[1], hB, lB);
                    ah[0] = pack2(hA, hB); al[0] = pack2(lA, lB);
                    split1(t0[2], hA, lA); split1(t0[3], hB, lB);
                    ah[1] = pack2(hA, hB); al[1] = pack2(lA, lB);
                    split1(t1[0], hA, lA); split1(t1[1], hB, lB);
                    ah[2] = pack2(hA, hB); al[2] = pack2(lA, lB);
                    split1(t1[2], hA, lA); split1(t1[3], hB, lB);
                    ah[3] = pack2(hA, hB); al[3] = pack2(lA, lB);
                }
                int rv = lane & 15, half = lane >> 4;
#pragma unroll
                for (int pp = 0; pp < 8; pp++) {
                    uint32_t bh[4];
                    int cV = pp * 16 + half * 8;
                    ldsm_x4_t(st + (rv * 136 + cV) * 2, bh);
#pragma unroll
                    for (int jj = 0; jj < 2; jj++) {
                        float* c4 = o[2 * pp + jj];
                        mma_f16(c4, ah, bh[2 * jj], bh[2 * jj + 1]);
                        mma_f16(c4, al, bh[2 * jj], bh[2 * jj + 1]);
                    }
                }
            }
            // no trailing sync — 4-stage ring
        }

        float inv0 = 1.f / l0, inv1 = 1.f / l1;
        int gr0 = i0 + lr0;
#pragma unroll
        for (int nt = 0; nt < 16; nt++) {
            int col = h * D_V + nt * 8 + ((lane & 3) << 1);
            *reinterpret_cast<uint32_t*>(&at[(long)gr0 * O_K + col]) =
                pack2(__float2half_rn(o[nt][0] * inv0), __float2half_rn(o[nt][1] * inv0));
            *reinterpret_cast<uint32_t*>(&at[(long)(gr0 + 8) * O_K + col]) =
                pack2(__float2half_rn(o[nt][2] * inv1), __float2half_rn(o[nt][3] * inv1));
        }
    }
}

// ---------------- converters ----------------
__global__ void cvt_single_kernel(const float* __restrict__ src,
                                  f16* __restrict__ h, long n)
{
    long i = ((long)blockIdx.x * blockDim.x + threadIdx.x) * 8;
    if (i >= n) return;
    float4 v0 = *reinterpret_cast<const float4*>(&src[i]);
    float4 v1 = *reinterpret_cast<const float4*>(&src[i + 4]);
    uint4 o;
    o.x = pack2(__float2half_rn(v0.x), __float2half_rn(v0.y));
    o.y = pack2(__float2half_rn(v0.z), __float2half_rn(v0.w));
    o.z = pack2(__float2half_rn(v1.x), __float2half_rn(v1.y));
    o.w = pack2(__float2half_rn(v1.z), __float2half_rn(v1.w));
    *reinterpret_cast<uint4*>(&h[i]) = o;
}
__global__ void cvt_pad_single_kernel(const float* __restrict__ src,
                                      f16* __restrict__ h,
                                      int rows, int srcN, int dstN)
{
    long i = (long)blockIdx.x * blockDim.x + threadIdx.x;
    long total = (long)rows * dstN;
    if (i >= total) return;
    int r = (int)(i / dstN), c = (int)(i % dstN);
    float vv = (c < srcN) ? src[(long)r * srcN + c] : 0.f;
    h[i] = __float2half_rn(vv);
}

// ---------------- RMSNorm (single fp16 out) ----------------
__global__ void rmsnorm_kernel(const float* __restrict__ in,
                               const float* __restrict__ w,
                               f16* __restrict__ outh,
                               int L, int inStride, int outStride)
{
    int t = blockIdx.x;
    const float* x = in + (long)t * inStride;

    float ss = 0.f;
    for (int i = threadIdx.x; i < L; i += blockDim.x) {
        float v = x[i]; ss += v * v;
    }
    __shared__ float sh[33];
#pragma unroll
    for (int o = 16; o; o >>= 1) ss += __shfl_xor_sync(~0u, ss, o);
    int lane = threadIdx.x & 31, wrp = threadIdx.x >> 5;
    if (lane == 0) sh[wrp] = ss;
    __syncthreads();
    if (wrp == 0) {
        float v = (lane < (blockDim.x >> 5)) ? sh[lane] : 0.f;
#pragma unroll
        for (int o = 16; o; o >>= 1) v += __shfl_xor_sync(~0u, v, o);
        if (lane == 0) sh[32] = v;
    }
    __syncthreads();
    float r = rsqrtf(sh[32] / (float)L + EPS_RMS);
    for (int i = threadIdx.x; i < L; i += blockDim.x)
        outh[(long)t * outStride + i] = __float2half_rn(x[i] * r * w[i]);
}

// ---------------- RoPE + repack (all single plane) ----------------
__global__ void pack_rope_kernel(const int* __restrict__ positions,
                                 const float* __restrict__ q,
                                 const float* __restrict__ kvbuf,
                                 const float* __restrict__ kvup,
                                 f16* __restrict__ qf,
                                 f16* __restrict__ kf,  f16* __restrict__ v)
{
    int t   = blockIdx.x;
    int tid = threadIdx.x;
    float pos = (float)positions[t];

    __shared__ float kp[D_ROPE];
    if (tid < 32) {
        int i = tid;
        float inv = expf(-logf(10000.0f) * (2.0f * i) / (float)D_ROPE);
        float ang = pos * inv;
        float c = cosf(ang), s = sinf(ang);
        float x1 = kvbuf[(long)t * KVA_N + KV_LORA + 2 * i];
        float x2 = kvbuf[(long)t * KVA_N + KV_LORA + 2 * i + 1];
        kp[2 * i]     = x1 * c - x2 * s;
        kp[2 * i + 1] = x2 * c + x1 * s;
    }
    __syncthreads();

    for (int idx = tid; idx < NH * QK_HD; idx += blockDim.x) {
        int h = idx / QK_HD, d = idx % QK_HD;
        long dst = ((long)h * T_SEQ + t) * QK_HD + d;
        if (d < D_NOPE) {
            qf[dst] = __float2half_rn(q[(long)t * QB_N + h * QK_HD + d]);
            kf[dst] = __float2half_rn(kvup[(long)t * KVB_N + h * (D_NOPE + D_V) + d]);
        } else {
            kf[dst] = __float2half_rn(kp[d - D_NOPE]);
        }
    }
    for (int idx = tid; idx < NH * (D_ROPE / 2); idx += blockDim.x) {
        int h = idx / (D_ROPE / 2), i = idx % (D_ROPE / 2);
        float inv = expf(-logf(10000.0f) * (2.0f * i) / (float)D_ROPE);
        float ang = pos * inv;
        float c = cosf(ang), s = sinf(ang);
        long src = (long)t * QB_N + h * QK_HD + D_NOPE;
        float x1 = q[src + 2 * i];
        float x2 = q[src + 2 * i + 1];
        long dst = ((long)h * T_SEQ + t) * QK_HD + D_NOPE;
        qf[dst + 2 * i]     = __float2half_rn(x1 * c - x2 * s);
        qf[dst + 2 * i + 1] = __float2half_rn(x2 * c + x1 * s);
    }
    for (int idx = tid; idx < NH * D_V; idx += blockDim.x) {
        int h = idx / D_V, d = idx % D_V;
        v[((long)h * T_SEQ + t) * D_V + d] =
            __float2half_rn(kvup[(long)t * KVB_N + h * (D_NOPE + D_V) + D_NOPE + d]);
    }
}

// ---------------- Launch ----------------
extern "C" void kernel_launch(void* const* d_in, const int* in_sizes, int n_in,
                              void* d_out, int out_size)
{
    const int*   positions = (const int*)  d_in[0];
    const float* hs        = (const float*)d_in[1];
    const float* w_qa      = (const float*)d_in[2];
    const float* qa_ln_w   = (const float*)d_in[3];
    const float* w_qb      = (const float*)d_in[4];
    const float* w_kva     = (const float*)d_in[5];
    const float* kva_ln_w  = (const float*)d_in[6];
    const float* w_kvb     = (const float*)d_in[7];
    const float* w_o       = (const float*)d_in[8];
    float* out = (float*)d_out;

    float *p_qa, *p_q, *p_kv, *p_kvup;
    f16 *phs, *wqa, *wqb, *wkva, *wkvb, *wo;
    f16 *qc, *kvc, *qf, *kf, *v, *at;

    cudaGetSymbolAddress((void**)&p_qa,   g_qa);
    cudaGetSymbolAddress((void**)&p_q,    g_q);
    cudaGetSymbolAddress((void**)&p_kv,   g_kv);
    cudaGetSymbolAddress((void**)&p_kvup, g_kvup);
    cudaGetSymbolAddress((void**)&phs,    g_hs);
    cudaGetSymbolAddress((void**)&wqa,    g_wqa);
    cudaGetSymbolAddress((void**)&wqb,    g_wqb);
    cudaGetSymbolAddress((void**)&wkva,   g_wkva);
    cudaGetSymbolAddress((void**)&wkvb,   g_wkvb);
    cudaGetSymbolAddress((void**)&wo,     g_wo);
    cudaGetSymbolAddress((void**)&qc,     g_qc);
    cudaGetSymbolAddress((void**)&kvc,    g_kvc);
    cudaGetSymbolAddress((void**)&qf,     g_qf);
    cudaGetSymbolAddress((void**)&kf,     g_kf);
    cudaGetSymbolAddress((void**)&v,      g_v);
    cudaGetSymbolAddress((void**)&at,     g_at);

    cudaFuncSetAttribute(tgemm_nn<0>,  cudaFuncAttributeMaxDynamicSharedMemorySize, G_SMEM_SINGLE);
    cudaFuncSetAttribute(flash_kernel, cudaFuncAttributeMaxDynamicSharedMemorySize, FA_SMEM);

    dim3 blk(256);
    auto cdiv = [](long a, long b) { return (int)((a + b - 1) / b); };

    // converters
    cvt_single_kernel<<<cdiv((long)T_SEQ * HID / 8, 256), 256>>>(hs, phs, (long)T_SEQ * HID);
    cvt_single_kernel<<<cdiv((long)HID * Q_LORA / 8, 256), 256>>>(w_qa, wqa, (long)HID * Q_LORA);
    cvt_single_kernel<<<cdiv((long)Q_LORA * QB_N / 8, 256), 256>>>(w_qb, wqb, (long)Q_LORA * QB_N);
    cvt_single_kernel<<<cdiv((long)KV_LORA * KVB_N / 8, 256), 256>>>(w_kvb, wkvb, (long)KV_LORA * KVB_N);
    cvt_single_kernel<<<cdiv((long)O_K * HID / 8, 256), 256>>>(w_o, wo, (long)O_K * HID);
    cvt_pad_single_kernel<<<cdiv((long)HID * KVA_NP, 256), 256>>>(w_kva, wkva, HID, KVA_N, KVA_NP);

    // G1: qa = hs @ w_qa
    tgemm_nn<0><<<dim3(Q_LORA/BN, T_SEQ/BM), blk, G_SMEM_SINGLE>>>(
        phs, nullptr, wqa, p_qa, Q_LORA, HID, HID, Q_LORA, Q_LORA, 1.f);

    // G2: kv = hs @ w_kva
    tgemm_nn<0><<<dim3(KVA_NP/BN, T_SEQ/BM), blk, G_SMEM_SINGLE>>>(
        phs, nullptr, wkva, p_kv, KVA_N, HID, HID, KVA_NP, KVA_N, 1.f);

    rmsnorm_kernel<<<T_SEQ, 256>>>(p_qa, qa_ln_w, qc, Q_LORA, Q_LORA, Q_LORA);
    rmsnorm_kernel<<<T_SEQ, 256>>>(p_kv, kva_ln_w, kvc, KV_LORA, KVA_N, KV_LORA);

    // G3: q = qc @ w_qb (single plane now)
    tgemm_nn<0><<<dim3(QB_N/BN, T_SEQ/BM), blk, G_SMEM_SINGLE>>>(
        qc, nullptr, wqb, p_q, QB_N, Q_LORA, Q_LORA, QB_N, QB_N, 1.f);

    // G4: kvup = kvc @ w_kvb
    tgemm_nn<0><<<dim3(KVB_N/BN, T_SEQ/BM), blk, G_SMEM_SINGLE>>>(
        kvc, nullptr, wkvb, p_kvup, KVB_N, KV_LORA, KV_LORA, KVB_N, KVB_N, 1.f);

    pack_rope_kernel<<<T_SEQ, 256>>>(positions, p_q, p_kv, p_kvup, qf, kf, v);

    // Fused attention (Q single plane; P split in registers)
    flash_kernel<<<dim3(NH, T_SEQ / 256), blk, FA_SMEM>>>(qf, kf, v, at);

    // G7: out = attn @ w_o — w_o is [O_K][HID], ldb = HID
    tgemm_nn<0><<<dim3(HID/BN, T_SEQ/BM), blk, G_SMEM_SINGLE>>>(
        at, nullptr, wo, out, HID, O_K, O_K, HID, HID, 1.f);
}

// round 12
// speedup vs baseline: 1.9880x; 1.0057x over previous
#include <cuda_runtime.h>
#include <cuda_fp16.h>
#include <math.h>
#include <stdint.h>

// ---------------- Problem constants ----------------
#define T_SEQ   2048
#define HID     5120
#define NH      16
#define D_NOPE  128
#define D_ROPE  64
#define D_V     128
#define Q_LORA  1536
#define KV_LORA 512
#define QK_HD   (D_NOPE + D_ROPE)   // 192
#define KVA_N   (KV_LORA + D_ROPE)  // 576
#define KVA_NP  640
#define QB_N    (NH * QK_HD)        // 3072
#define KVB_N   (NH * (D_NOPE + D_V)) // 4096
#define O_K     (NH * D_V)          // 2048

static const float SCALE = 0.07216878364870322f; // 192^-0.5
#define EPS_RMS 1e-6f

typedef __half f16;

// ---------------- Scratch ----------------
__device__ float g_qa   [T_SEQ * Q_LORA];
__device__ float g_kv   [T_SEQ * KVA_N];

__device__ f16 g_hs   [T_SEQ * HID];
__device__ f16 g_wqa  [HID * Q_LORA];
__device__ f16 g_wqb  [Q_LORA * QB_N];
__device__ f16 g_wkva [HID * KVA_NP];
__device__ f16 g_wkvb [KV_LORA * KVB_N];
__device__ f16 g_wo   [O_K * HID];
__device__ f16 g_qc   [T_SEQ * Q_LORA];
__device__ f16 g_kvc  [T_SEQ * KV_LORA];
__device__ f16 g_qf   [(long)NH*T_SEQ*QK_HD];   // roped Q, written by G3 epilogue
__device__ f16 g_kf   [(long)NH*T_SEQ*QK_HD];   // K (nope from G4 epi, pe from kpe kernel)
__device__ f16 g_v    [(long)NH*T_SEQ*D_V];     // V, written by G4 epilogue
__device__ f16 g_at   [T_SEQ * O_K];

// ---------------- helpers ----------------
__device__ __forceinline__ uint32_t smem_u32(const void* p) {
    return (uint32_t)__cvta_generic_to_shared(p);
}
__device__ __forceinline__ void cp16(uint32_t dst, const void* src) {
    asm volatile("cp.async.cg.shared.global [%0], [%1], 16;\n" :: "r"(dst), "l"(src));
}
__device__ __forceinline__ void cp_commit() {
    asm volatile("cp.async.commit_group;\n");
}
template<int NMAX>
__device__ __forceinline__ void cp_wait() {
    asm volatile("cp.async.wait_group %0;\n" :: "n"(NMAX));
}
__device__ __forceinline__ void ldsm_x4(uint32_t addr, uint32_t r[4]) {
    asm volatile("ldmatrix.sync.aligned.m8n8.x4.shared.b16 {%0,%1,%2,%3}, [%4];"
                 : "=r"(r[0]), "=r"(r[1]), "=r"(r[2]), "=r"(r[3]) : "r"(addr));
}
__device__ __forceinline__ void ldsm_x4_t(uint32_t addr, uint32_t r[4]) {
    asm volatile("ldmatrix.sync.aligned.m8n8.x4.trans.shared.b16 {%0,%1,%2,%3}, [%4];"
                 : "=r"(r[0]), "=r"(r[1]), "=r"(r[2]), "=r"(r[3]) : "r"(addr));
}
__device__ __forceinline__ void mma_f16(float c[4], const uint32_t a[4],
                                        uint32_t b0, uint32_t b1) {
    asm volatile(
        "mma.sync.aligned.m16n8k16.row.col.f32.f16.f16.f32 "
        "{%0,%1,%2,%3}, {%4,%5,%6,%7}, {%8,%9}, {%0,%1,%2,%3};"
        : "+f"(c[0]), "+f"(c[1]), "+f"(c[2]), "+f"(c[3])
        : "r"(a[0]), "r"(a[1]), "r"(a[2]), "r"(a[3]), "r"(b0), "r"(b1));
}
__device__ __forceinline__ uint32_t pack2(f16 a, f16 b) {
    __half2 t = __halves2half2(a, b);
    return *reinterpret_cast<uint32_t*>(&t);
}
__device__ __forceinline__ void split1(float f, f16& h, f16& l) {
    h = __float2half_rn(f);
    l = __float2half_rn(f - __half2float(h));
}

// ---------------- NN tensor GEMM with fused epilogues ----------------
// EPI=0: C fp32.  EPI=1: write roped Q -> qf[h][t][192] f16 (needs positions).
// EPI=2: scatter kvup -> kf[h][t][0..127], v[h][t][0..127] f16.
// 4-stage cp.async ring, prefetch depth 2, one sync per tile.
#define BM 128
#define BN 128
#define BK 16
#define G_STG  10496
#define G_SMEM (4 * G_STG)

template<int EPI>
__global__ __launch_bounds__(256)
void tgemm_nn(const f16* __restrict__ A, const f16* __restrict__ B,
              float* __restrict__ C, f16* __restrict__ O1, f16* __restrict__ O2,
              const int* __restrict__ positions,
              int N, int K, int lda, int ldb, int ldc, float alpha)
{
    extern __shared__ char smem[];
    int row0 = blockIdx.y * BM;
    int col0 = blockIdx.x * BN;

    int tid  = threadIdx.x;
    int lane = tid & 31;
    int warp = tid >> 5;
    int wm   = warp >> 1;
    int wn   = warp & 1;

    int aRow = tid >> 1;          // 0..127
    int aKc  = (tid & 1) * 8;     // 0 or 8
    int bKr  = tid >> 4;          // 0..15
    int bNc  = (tid & 15) * 8;    // 0..120

    uint32_t sb = smem_u32(smem);

    auto issue = [&](int i) {
        int k0 = i * BK;
        uint32_t stg = sb + (i & 3) * G_STG;
        cp16(stg +        (aRow * 24 + aKc) * 2, &A[(long)(row0 + aRow) * lda + k0 + aKc]);
        cp16(stg + 6144 + (bKr * 136 + bNc) * 2, &B[(long)(k0 + bKr) * ldb + col0 + bNc]);
    };

    float acc[2][8][4];
#pragma unroll
    for (int i = 0; i < 2; i++)
#pragma unroll
        for (int j = 0; j < 8; j++)
#pragma unroll
            for (int q = 0; q < 4; q++) acc[i][j][q] = 0.f;

    int ntiles = K / BK;

    issue(0); cp_commit();
    if (ntiles > 1) issue(1);
    cp_commit();

    for (int i = 0; i < ntiles; i++) {
        if (i + 2 < ntiles) issue(i + 2);
        cp_commit();
        cp_wait<2>();
        __syncthreads();

        uint32_t stg = sb + (i & 3) * G_STG;
        uint32_t a_h[2][4];
#pragma unroll
        for (int mt = 0; mt < 2; mt++) {
            int r = wm * 32 + mt * 16 + (lane & 15);
            int c = (lane >> 4) * 8;
            ldsm_x4(stg + (r * 24 + c) * 2, a_h[mt]);
        }
        int rB    = lane & 15;
        int halfB = lane >> 4;
#pragma unroll
        for (int p = 0; p < 4; p++) {
            uint32_t bh[4];
            int c = wn * 64 + p * 16 + halfB * 8;
            ldsm_x4_t(stg + 6144 + (rB * 136 + c) * 2, bh);
#pragma unroll
            for (int mt = 0; mt < 2; mt++)
#pragma unroll
                for (int j = 0; j < 2; j++)
                    mma_f16(acc[mt][2 * p + j], a_h[mt], bh[2 * j], bh[2 * j + 1]);
        }
        // no trailing sync — 4-stage ring keeps writes 2 stages ahead of reads
    }

    int gid = lane >> 2, tig = lane & 3;
#pragma unroll
    for (int mt = 0; mt < 2; mt++) {
        int rb = row0 + wm * 32 + mt * 16 + gid;
#pragma unroll
        for (int nt = 0; nt < 8; nt++) {
            int c = col0 + wn * 64 + nt * 8 + tig * 2;
            if (c >= N) continue;
            float p00 = acc[mt][nt][0], p01 = acc[mt][nt][1];
            float p10 = acc[mt][nt][2], p11 = acc[mt][nt][3];
            if (EPI == 0) {
                *reinterpret_cast<float2*>(&C[(long)rb * ldc + c]) =
                    make_float2(alpha * p00, alpha * p01);
                *reinterpret_cast<float2*>(&C[(long)(rb + 8) * ldc + c]) =
                    make_float2(alpha * p10, alpha * p11);
            } else if (EPI == 1) {
                int h = c / QK_HD, d = c % QK_HD;
#pragma unroll
                for (int rr = 0; rr < 2; rr++) {
                    int r = rb + rr * 8;
                    float v0 = rr ? p10 : p00, v1 = rr ? p11 : p01;
                    long dst = ((long)h * T_SEQ + r) * QK_HD + d;
                    if (d < D_NOPE) {
                        *reinterpret_cast<uint32_t*>(&O1[dst]) =
                            pack2(__float2half_rn(v0), __float2half_rn(v1));
                    } else {
                        int i2 = (d - D_NOPE) >> 1;
                        float pos = (float)positions[r];
                        float inv = expf(-logf(10000.0f) * (2.0f * i2) / (float)D_ROPE);
                        float ang = pos * inv;
                        float cs = cosf(ang), sn = sinf(ang);
                        *reinterpret_cast<uint32_t*>(&O1[dst]) =
                            pack2(__float2half_rn(v0 * cs - v1 * sn),
                                  __float2half_rn(v1 * cs + v0 * sn));
                    }
                }
            } else {
                int h = c >> 8, d = c & 255;
#pragma unroll
                for (int rr = 0; rr < 2; rr++) {
                    int r = rb + rr * 8;
                    float v0 = rr ? p10 : p00, v1 = rr ? p11 : p01;
                    uint32_t pk = pack2(__float2half_rn(v0), __float2half_rn(v1));
                    if (d < D_NOPE)
                        *reinterpret_cast<uint32_t*>(&O1[((long)h * T_SEQ + r) * QK_HD + d]) = pk;
                    else
                        *reinterpret_cast<uint32_t*>(&O2[((long)h * T_SEQ + r) * D_V + d - D_NOPE]) = pk;
                }
            }
        }
    }
}

// ---------------- Fused flash attention ----------------
#define FA_QSZ   (128 * 200 * 2)
#define FA_STG   6144
#define FA_SMEM  (FA_QSZ + 4 * FA_STG)

__global__ __launch_bounds__(256)
void flash_kernel(const f16* __restrict__ qf,
                  const f16* __restrict__ kf,  const f16* __restrict__ v,
                  f16* __restrict__ at)
{
    extern __shared__ char smem[];
    int h   = blockIdx.x;
    int tid = threadIdx.x;
    int lane = tid & 31;
    int wid  = tid >> 5;
    int wrow = wid * 16;

    uint32_t sQ  = smem_u32(smem);
    uint32_t stg = sQ + FA_QSZ;

    const long hT = (long)h * T_SEQ;

    auto loadQ = [&](int i0) {
#pragma unroll
        for (int it = 0; it < 12; it++) {
            int u = it * 256 + tid;
            int row = u / 24, off = (u % 24) * 8;
            cp16(sQ + (row * 200 + off) * 2, qf + (hT + i0 + row) * QK_HD + off);
        }
    };
    auto load_chunk = [&](int c) {
        uint32_t st = stg + (c & 3) * FA_STG;
        int j = c / 20, r = c % 20;
        if (r < 12) {
            int d0 = r * 16;
            int row = tid >> 1, off = (tid & 1) * 8;
            cp16(st + (row * 24 + off) * 2, kf + (hT + j * 128 + row) * QK_HD + d0 + off);
        } else {
            int q0 = (r - 12) * 16;
            int row = tid >> 4, off = (tid & 15) * 8;
            cp16(st + (row * 136 + off) * 2, v + (hT + j * 128 + q0 + row) * D_V + off);
        }
    };

    for (int rep = 0; rep < 2; rep++) {
        int iblk = rep == 0 ? blockIdx.y : (T_SEQ / 128 - 1) - blockIdx.y;
        int i0   = iblk * 128;
        int nch  = (iblk + 1) * 20;

        float s[16][4], o[16][4];
        float m0 = -1e30f, m1 = -1e30f, l0 = 0.f, l1 = 0.f;
#pragma unroll
        for (int nt = 0; nt < 16; nt++)
#pragma unroll
            for (int q = 0; q < 4; q++) o[nt][q] = 0.f;

        __syncthreads();
        loadQ(i0);
        load_chunk(0); cp_commit();
        load_chunk(1); cp_commit();

        int lr0 = wrow + (lane >> 2);
        int lr1 = lr0 + 8;

        for (int c = 0; c < nch; c++) {
            if (c + 2 < nch) load_chunk(c + 2);
            cp_commit();
            cp_wait<2>();
            __syncthreads();

            uint32_t st = stg + (c & 3) * FA_STG;
            int j = c / 20, r = c % 20;

            if (r < 12) {
                if (r == 0) {
#pragma unroll
                    for (int nt = 0; nt < 16; nt++)
#pragma unroll
                        for (int q = 0; q < 4; q++) s[nt][q] = 0.f;
                }
                uint32_t a_h[4];
                int ar = wrow + (lane & 15);
                int ac = r * 16 + (lane >> 4) * 8;
                ldsm_x4(sQ + (ar * 200 + ac) * 2, a_h);
                int g = lane >> 3, rr = lane & 7;
                int nbase = ((g >> 1) << 3) + rr;
                int cc = (g & 1) * 8;
#pragma unroll
                for (int p = 0; p < 8; p++) {
                    uint32_t bh[4];
                    ldsm_x4(st + ((p * 16 + nbase) * 24 + cc) * 2, bh);
#pragma unroll
                    for (int jj = 0; jj < 2; jj++)
                        mma_f16(s[2 * p + jj], a_h, bh[2 * jj], bh[2 * jj + 1]);
                }
                if (r == 11) {
#pragma unroll
                    for (int nt = 0; nt < 16; nt++)
#pragma unroll
                        for (int q = 0; q < 4; q++) s[nt][q] *= SCALE;
                    if (j == iblk) {
#pragma unroll
                        for (int nt = 0; nt < 16; nt++) {
                            int c0 = nt * 8 + ((lane & 3) << 1);
                            if (c0     > lr0) s[nt][0] = -1e30f;
                            if (c0 + 1 > lr0) s[nt][1] = -1e30f;
                            if (c0     > lr1) s[nt][2] = -1e30f;
                            if (c0 + 1 > lr1) s[nt][3] = -1e30f;
                        }
                    }
                    float mr0 = -1e30f, mr1 = -1e30f;
#pragma unroll
                    for (int nt = 0; nt < 16; nt++) {
                        mr0 = fmaxf(mr0, fmaxf(s[nt][0], s[nt][1]));
                        mr1 = fmaxf(mr1, fmaxf(s[nt][2], s[nt][3]));
                    }
                    mr0 = fmaxf(mr0, __shfl_xor_sync(~0u, mr0, 1));
                    mr0 = fmaxf(mr0, __shfl_xor_sync(~0u, mr0, 2));
                    mr1 = fmaxf(mr1, __shfl_xor_sync(~0u, mr1, 1));
                    mr1 = fmaxf(mr1, __shfl_xor_sync(~0u, mr1, 2));
                    float mn0 = fmaxf(m0, mr0), mn1 = fmaxf(m1, mr1);
                    float sc0 = __expf(m0 - mn0), sc1 = __expf(m1 - mn1);
                    float rs0 = 0.f, rs1 = 0.f;
#pragma unroll
                    for (int nt = 0; nt < 16; nt++) {
                        s[nt][0] = __expf(s[nt][0] - mn0); rs0 += s[nt][0];
                        s[nt][1] = __expf(s[nt][1] - mn0); rs0 += s[nt][1];
                        s[nt][2] = __expf(s[nt][2] - mn1); rs1 += s[nt][2];
                        s[nt][3] = __expf(s[nt][3] - mn1); rs1 += s[nt][3];
                    }
                    rs0 += __shfl_xor_sync(~0u, rs0, 1); rs0 += __shfl_xor_sync(~0u, rs0, 2);
                    rs1 += __shfl_xor_sync(~0u, rs1, 1); rs1 += __shfl_xor_sync(~0u, rs1, 2);
                    l0 = l0 * sc0 + rs0;  l1 = l1 * sc1 + rs1;
                    m0 = mn0; m1 = mn1;
#pragma unroll
                    for (int nt = 0; nt < 16; nt++) {
                        o[nt][0] *= sc0; o[nt][1] *= sc0;
                        o[nt][2] *= sc1; o[nt][3] *= sc1;
                    }
                }
            } else {
                int q = r - 12;
                uint32_t ah[4], al[4];
                {
                    const float* t0 = s[2 * q];
                    const float* t1 = s[2 * q + 1];
                    f16 hA, lA, hB, lB;
                    split1(t0[0], hA, lA); split1(t0[1], hB, lB);
                    ah[0] = pack2(hA, hB); al[0] = pack2(lA, lB);
                    split1(t0[2], hA, lA); split1(t0[3], hB, lB);
                    ah[1] = pack2(hA, hB); al[1] = pack2(lA, lB);
                    split1(t1[0], hA, lA); split1(t1[1], hB, lB);
                    ah[2] = pack2(hA, hB); al[2] = pack2(lA, lB);
                    split1(t1[2], hA, lA); split1(t1[3], hB, lB);
                    ah[3] = pack2(hA, hB); al[3] = pack2(lA, lB);
                }
                int rv = lane & 15, half = lane >> 4;
#pragma unroll
                for (int pp = 0; pp < 8; pp++) {
                    uint32_t bh[4];
                    int cV = pp * 16 + half * 8;
                    ldsm_x4_t(st + (rv * 136 + cV) * 2, bh);
#pragma unroll
                    for (int jj = 0; jj < 2; jj++) {
                        float* c4 = o[2 * pp + jj];
                        mma_f16(c4, ah, bh[2 * jj], bh[2 * jj + 1]);
                        mma_f16(c4, al, bh[2 * jj], bh[2 * jj + 1]);
                    }
                }
            }
        }

        float inv0 = 1.f / l0, inv1 = 1.f / l1;
        int gr0 = i0 + lr0;
#pragma unroll
        for (int nt = 0; nt < 16; nt++) {
            int col = h * D_V + nt * 8 + ((lane & 3) << 1);
            *reinterpret_cast<uint32_t*>(&at[(long)gr0 * O_K + col]) =
                pack2(__float2half_rn(o[nt][0] * inv0), __float2half_rn(o[nt][1] * inv0));
            *reinterpret_cast<uint32_t*>(&at[(long)(gr0 + 8) * O_K + col]) =
                pack2(__float2half_rn(o[nt][2] * inv1), __float2half_rn(o[nt][3] * inv1));
        }
    }
}

// ---------------- converters ----------------
__global__ void cvt_single_kernel(const float* __restrict__ src,
                                  f16* __restrict__ h, long n)
{
    long i = ((long)blockIdx.x * blockDim.x + threadIdx.x) * 8;
    if (i >= n) return;
    float4 v0 = *reinterpret_cast<const float4*>(&src[i]);
    float4 v1 = *reinterpret_cast<const float4*>(&src[i + 4]);
    uint4 o;
    o.x = pack2(__float2half_rn(v0.x), __float2half_rn(v0.y));
    o.y = pack2(__float2half_rn(v0.z), __float2half_rn(v0.w));
    o.z = pack2(__float2half_rn(v1.x), __float2half_rn(v1.y));
    o.w = pack2(__float2half_rn(v1.z), __float2half_rn(v1.w));
    *reinterpret_cast<uint4*>(&h[i]) = o;
}
__global__ void cvt_pad_single_kernel(const float* __restrict__ src,
                                      f16* __restrict__ h,
                                      int rows, int srcN, int dstN)
{
    long i = (long)blockIdx.x * blockDim.x + threadIdx.x;
    long total = (long)rows * dstN;
    if (i >= total) return;
    int r = (int)(i / dstN), c = (int)(i % dstN);
    float vv = (c < srcN) ? src[(long)r * srcN + c] : 0.f;
    h[i] = __float2half_rn(vv);
}

// ---------------- RMSNorm (single fp16 out) ----------------
__global__ void rmsnorm_kernel(const float* __restrict__ in,
                               const float* __restrict__ w,
                               f16* __restrict__ outh,
                               int L, int inStride, int outStride)
{
    int t = blockIdx.x;
    const float* x = in + (long)t * inStride;

    float ss = 0.f;
    for (int i = threadIdx.x; i < L; i += blockDim.x) {
        float v = x[i]; ss += v * v;
    }
    __shared__ float sh[33];
#pragma unroll
    for (int o = 16; o; o >>= 1) ss += __shfl_xor_sync(~0u, ss, o);
    int lane = threadIdx.x & 31, wrp = threadIdx.x >> 5;
    if (lane == 0) sh[wrp] = ss;
    __syncthreads();
    if (wrp == 0) {
        float v = (lane < (blockDim.x >> 5)) ? sh[lane] : 0.f;
#pragma unroll
        for (int o = 16; o; o >>= 1) v += __shfl_xor_sync(~0u, v, o);
        if (lane == 0) sh[32] = v;
    }
    __syncthreads();
    float r = rsqrtf(sh[32] / (float)L + EPS_RMS);
    for (int i = threadIdx.x; i < L; i += blockDim.x)
        outh[(long)t * outStride + i] = __float2half_rn(x[i] * r * w[i]);
}

// ---------------- k_pe rope + broadcast to all heads ----------------
__global__ void kpe_kernel(const int* __restrict__ positions,
                           const float* __restrict__ kvbuf,
                           f16* __restrict__ kf)
{
    long i = (long)blockIdx.x * blockDim.x + threadIdx.x;
    if (i >= (long)T_SEQ * (D_ROPE / 2)) return;
    int t = (int)(i >> 5), k = (int)(i & 31);
    float pos = (float)positions[t];
    float inv = expf(-logf(10000.0f) * (2.0f * k) / (float)D_ROPE);
    float ang = pos * inv;
    float cs = cosf(ang), sn = sinf(ang);
    float x1 = kvbuf[(long)t * KVA_N + KV_LORA + 2 * k];
    float x2 = kvbuf[(long)t * KVA_N + KV_LORA + 2 * k + 1];
    uint32_t pk = pack2(__float2half_rn(x1 * cs - x2 * sn),
                        __float2half_rn(x2 * cs + x1 * sn));
#pragma unroll
    for (int h = 0; h < NH; h++)
        *reinterpret_cast<uint32_t*>(&kf[((long)h * T_SEQ + t) * QK_HD + D_NOPE + 2 * k]) = pk;
}

// ---------------- Launch ----------------
extern "C" void kernel_launch(void* const* d_in, const int* in_sizes, int n_in,
                              void* d_out, int out_size)
{
    const int*   positions = (const int*)  d_in[0];
    const float* hs        = (const float*)d_in[1];
    const float* w_qa      = (const float*)d_in[2];
    const float* qa_ln_w   = (const float*)d_in[3];
    const float* w_qb      = (const float*)d_in[4];
    const float* w_kva     = (const float*)d_in[5];
    const float* kva_ln_w  = (const float*)d_in[6];
    const float* w_kvb     = (const float*)d_in[7];
    const float* w_o       = (const float*)d_in[8];
    float* out = (float*)d_out;

    float *p_qa, *p_kv;
    f16 *phs, *wqa, *wqb, *wkva, *wkvb, *wo;
    f16 *qc, *kvc, *qf, *kf, *v, *at;

    cudaGetSymbolAddress((void**)&p_qa,   g_qa);
    cudaGetSymbolAddress((void**)&p_kv,   g_kv);
    cudaGetSymbolAddress((void**)&phs,    g_hs);
    cudaGetSymbolAddress((void**)&wqa,    g_wqa);
    cudaGetSymbolAddress((void**)&wqb,    g_wqb);
    cudaGetSymbolAddress((void**)&wkva,   g_wkva);
    cudaGetSymbolAddress((void**)&wkvb,   g_wkvb);
    cudaGetSymbolAddress((void**)&wo,     g_wo);
    cudaGetSymbolAddress((void**)&qc,     g_qc);
    cudaGetSymbolAddress((void**)&kvc,    g_kvc);
    cudaGetSymbolAddress((void**)&qf,     g_qf);
    cudaGetSymbolAddress((void**)&kf,     g_kf);
    cudaGetSymbolAddress((void**)&v,      g_v);
    cudaGetSymbolAddress((void**)&at,     g_at);

    cudaFuncSetAttribute(tgemm_nn<0>,  cudaFuncAttributeMaxDynamicSharedMemorySize, G_SMEM);
    cudaFuncSetAttribute(tgemm_nn<1>,  cudaFuncAttributeMaxDynamicSharedMemorySize, G_SMEM);
    cudaFuncSetAttribute(tgemm_nn<2>,  cudaFuncAttributeMaxDynamicSharedMemorySize, G_SMEM);
    cudaFuncSetAttribute(flash_kernel, cudaFuncAttributeMaxDynamicSharedMemorySize, FA_SMEM);

    dim3 blk(256);
    auto cdiv = [](long a, long b) { return (int)((a + b - 1) / b); };

    // converters
    cvt_single_kernel<<<cdiv((long)T_SEQ * HID / 8, 256), 256>>>(hs, phs, (long)T_SEQ * HID);
    cvt_single_kernel<<<cdiv((long)HID * Q_LORA / 8, 256), 256>>>(w_qa, wqa, (long)HID * Q_LORA);
    cvt_single_kernel<<<cdiv((long)Q_LORA * QB_N / 8, 256), 256>>>(w_qb, wqb, (long)Q_LORA * QB_N);
    cvt_single_kernel<<<cdiv((long)KV_LORA * KVB_N / 8, 256), 256>>>(w_kvb, wkvb, (long)KV_LORA * KVB_N);
    cvt_single_kernel<<<cdiv((long)O_K * HID / 8, 256), 256>>>(w_o, wo, (long)O_K * HID);
    cvt_pad_single_kernel<<<cdiv((long)HID * KVA_NP, 256), 256>>>(w_kva, wkva, HID, KVA_N, KVA_NP);

    // G1: qa = hs @ w_qa (fp32 out)
    tgemm_nn<0><<<dim3(Q_LORA/BN, T_SEQ/BM), blk, G_SMEM>>>(
        phs, wqa, p_qa, nullptr, nullptr, nullptr,
        Q_LORA, HID, HID, Q_LORA, Q_LORA, 1.f);

    // G2: kv = hs @ w_kva (fp32 out)
    tgemm_nn<0><<<dim3(KVA_NP/BN, T_SEQ/BM), blk, G_SMEM>>>(
        phs, wkva, p_kv, nullptr, nullptr, nullptr,
        KVA_N, HID, HID, KVA_NP, KVA_N, 1.f);

    rmsnorm_kernel<<<T_SEQ, 256>>>(p_qa, qa_ln_w, qc, Q_LORA, Q_LORA, Q_LORA);
    rmsnorm_kernel<<<T_SEQ, 256>>>(p_kv, kva_ln_w, kvc, KV_LORA, KVA_N, KV_LORA);

    // k_pe rope + broadcast (reads g_kv fp32)
    kpe_kernel<<<cdiv((long)T_SEQ * (D_ROPE/2), 256), 256>>>(positions, p_kv, kf);

    // G3: q = qc @ w_qb — fused RoPE epilogue writes qf directly
    tgemm_nn<1><<<dim3(QB_N/BN, T_SEQ/BM), blk, G_SMEM>>>(
        qc, wqb, nullptr, qf, nullptr, positions,
        QB_N, Q_LORA, Q_LORA, QB_N, 0, 1.f);

    // G4: kvup = kvc @ w_kvb — fused scatter epilogue writes kf (nope) + v
    tgemm_nn<2><<<dim3(KVB_N/BN, T_SEQ/BM), blk, G_SMEM>>>(
        kvc, wkvb, nullptr, kf, v, nullptr,
        KVB_N, KV_LORA, KV_LORA, KVB_N, 0, 1.f);

    // Fused attention
    flash_kernel<<<dim3(NH, T_SEQ / 256), blk, FA_SMEM>>>(qf, kf, v, at);

    // G7: out = attn @ w_o — w_o is [O_K][HID], ldb = HID
    tgemm_nn<0><<<dim3(HID/BN, T_SEQ/BM), blk, G_SMEM>>>(
        at, wo, out, nullptr, nullptr, nullptr,
        HID, O_K, O_K, HID, HID, 1.f);
}

// round 13
// speedup vs baseline: 2.1329x; 1.0729x over previous
#include <cuda_runtime.h>
#include <cuda_fp16.h>
#include <math.h>
#include <stdint.h>

// ---------------- Problem constants ----------------
#define T_SEQ   2048
#define HID     5120
#define NH      16
#define D_NOPE  128
#define D_ROPE  64
#define D_V     128
#define Q_LORA  1536
#define KV_LORA 512
#define QK_HD   (D_NOPE + D_ROPE)   // 192
#define KVA_N   (KV_LORA + D_ROPE)  // 576
#define KVA_NP  640
#define QKV_N   (Q_LORA + KVA_NP)   // 2176 = 17 * 128
#define QB_N    (NH * QK_HD)        // 3072
#define KVB_N   (NH * (D_NOPE + D_V)) // 4096
#define O_K     (NH * D_V)          // 2048

static const float SCALE = 0.07216878364870322f; // 192^-0.5
#define EPS_RMS 1e-6f

typedef __half f16;

// ---------------- Scratch ----------------
__device__ float g_qkv  [T_SEQ * QKV_N];        // [qa(1536) | kv(576) | pad]

__device__ f16 g_hs    [T_SEQ * HID];
__device__ f16 g_wcomb [HID * QKV_N];           // [w_qa | w_kva | 0]
__device__ f16 g_wqb   [Q_LORA * QB_N];
__device__ f16 g_wkvb  [KV_LORA * KVB_N];
__device__ f16 g_wo    [O_K * HID];
__device__ f16 g_qc    [T_SEQ * Q_LORA];
__device__ f16 g_kvc   [T_SEQ * KV_LORA];
__device__ f16 g_qf    [(long)NH*T_SEQ*QK_HD];  // roped Q (G3 epilogue)
__device__ f16 g_kf    [(long)NH*T_SEQ*QK_HD];  // K (G4 epi + kpe)
__device__ f16 g_v     [(long)NH*T_SEQ*D_V];    // V (G4 epilogue)
__device__ f16 g_at    [T_SEQ * O_K];

// ---------------- helpers ----------------
__device__ __forceinline__ uint32_t smem_u32(const void* p) {
    return (uint32_t)__cvta_generic_to_shared(p);
}
__device__ __forceinline__ void cp16(uint32_t dst, const void* src) {
    asm volatile("cp.async.cg.shared.global [%0], [%1], 16;\n" :: "r"(dst), "l"(src));
}
__device__ __forceinline__ void cp_commit() {
    asm volatile("cp.async.commit_group;\n");
}
template<int NMAX>
__device__ __forceinline__ void cp_wait() {
    asm volatile("cp.async.wait_group %0;\n" :: "n"(NMAX));
}
__device__ __forceinline__ void ldsm_x4(uint32_t addr, uint32_t r[4]) {
    asm volatile("ldmatrix.sync.aligned.m8n8.x4.shared.b16 {%0,%1,%2,%3}, [%4];"
                 : "=r"(r[0]), "=r"(r[1]), "=r"(r[2]), "=r"(r[3]) : "r"(addr));
}
__device__ __forceinline__ void ldsm_x4_t(uint32_t addr, uint32_t r[4]) {
    asm volatile("ldmatrix.sync.aligned.m8n8.x4.trans.shared.b16 {%0,%1,%2,%3}, [%4];"
                 : "=r"(r[0]), "=r"(r[1]), "=r"(r[2]), "=r"(r[3]) : "r"(addr));
}
__device__ __forceinline__ void mma_f16(float c[4], const uint32_t a[4],
                                        uint32_t b0, uint32_t b1) {
    asm volatile(
        "mma.sync.aligned.m16n8k16.row.col.f32.f16.f16.f32 "
        "{%0,%1,%2,%3}, {%4,%5,%6,%7}, {%8,%9}, {%0,%1,%2,%3};"
        : "+f"(c[0]), "+f"(c[1]), "+f"(c[2]), "+f"(c[3])
        : "r"(a[0]), "r"(a[1]), "r"(a[2]), "r"(a[3]), "r"(b0), "r"(b1));
}
__device__ __forceinline__ uint32_t pack2(f16 a, f16 b) {
    __half2 t = __halves2half2(a, b);
    return *reinterpret_cast<uint32_t*>(&t);
}

// ---------------- NN tensor GEMM with fused epilogues ----------------
// EPI=0: C fp32.  EPI=1: roped Q -> qf f16.  EPI=2: scatter -> kf/v f16.
#define BM 128
#define BN 128
#define BK 16
#define G_STG  10496
#define G_SMEM (4 * G_STG)

template<int EPI>
__global__ __launch_bounds__(256)
void tgemm_nn(const f16* __restrict__ A, const f16* __restrict__ B,
              float* __restrict__ C, f16* __restrict__ O1, f16* __restrict__ O2,
              const int* __restrict__ positions,
              int N, int K, int lda, int ldb, int ldc, float alpha)
{
    extern __shared__ char smem[];
    int row0 = blockIdx.y * BM;
    int col0 = blockIdx.x * BN;

    int tid  = threadIdx.x;
    int lane = tid & 31;
    int warp = tid >> 5;
    int wm   = warp >> 1;
    int wn   = warp & 1;

    int aRow = tid >> 1;
    int aKc  = (tid & 1) * 8;
    int bKr  = tid >> 4;
    int bNc  = (tid & 15) * 8;

    uint32_t sb = smem_u32(smem);

    auto issue = [&](int i) {
        int k0 = i * BK;
        uint32_t stg = sb + (i & 3) * G_STG;
        cp16(stg +        (aRow * 24 + aKc) * 2, &A[(long)(row0 + aRow) * lda + k0 + aKc]);
        cp16(stg + 6144 + (bKr * 136 + bNc) * 2, &B[(long)(k0 + bKr) * ldb + col0 + bNc]);
    };

    float acc[2][8][4];
#pragma unroll
    for (int i = 0; i < 2; i++)
#pragma unroll
        for (int j = 0; j < 8; j++)
#pragma unroll
            for (int q = 0; q < 4; q++) acc[i][j][q] = 0.f;

    int ntiles = K / BK;

    issue(0); cp_commit();
    if (ntiles > 1) issue(1);
    cp_commit();

    for (int i = 0; i < ntiles; i++) {
        if (i + 2 < ntiles) issue(i + 2);
        cp_commit();
        cp_wait<2>();
        __syncthreads();

        uint32_t stg = sb + (i & 3) * G_STG;
        uint32_t a_h[2][4];
#pragma unroll
        for (int mt = 0; mt < 2; mt++) {
            int r = wm * 32 + mt * 16 + (lane & 15);
            int c = (lane >> 4) * 8;
            ldsm_x4(stg + (r * 24 + c) * 2, a_h[mt]);
        }
        int rB    = lane & 15;
        int halfB = lane >> 4;
#pragma unroll
        for (int p = 0; p < 4; p++) {
            uint32_t bh[4];
            int c = wn * 64 + p * 16 + halfB * 8;
            ldsm_x4_t(stg + 6144 + (rB * 136 + c) * 2, bh);
#pragma unroll
            for (int mt = 0; mt < 2; mt++)
#pragma unroll
                for (int j = 0; j < 2; j++)
                    mma_f16(acc[mt][2 * p + j], a_h[mt], bh[2 * j], bh[2 * j + 1]);
        }
    }

    int gid = lane >> 2, tig = lane & 3;
#pragma unroll
    for (int mt = 0; mt < 2; mt++) {
        int rb = row0 + wm * 32 + mt * 16 + gid;
#pragma unroll
        for (int nt = 0; nt < 8; nt++) {
            int c = col0 + wn * 64 + nt * 8 + tig * 2;
            if (c >= N) continue;
            float p00 = acc[mt][nt][0], p01 = acc[mt][nt][1];
            float p10 = acc[mt][nt][2], p11 = acc[mt][nt][3];
            if (EPI == 0) {
                *reinterpret_cast<float2*>(&C[(long)rb * ldc + c]) =
                    make_float2(alpha * p00, alpha * p01);
                *reinterpret_cast<float2*>(&C[(long)(rb + 8) * ldc + c]) =
                    make_float2(alpha * p10, alpha * p11);
            } else if (EPI == 1) {
                int h = c / QK_HD, d = c % QK_HD;
#pragma unroll
                for (int rr = 0; rr < 2; rr++) {
                    int r = rb + rr * 8;
                    float v0 = rr ? p10 : p00, v1 = rr ? p11 : p01;
                    long dst = ((long)h * T_SEQ + r) * QK_HD + d;
                    if (d < D_NOPE) {
                        *reinterpret_cast<uint32_t*>(&O1[dst]) =
                            pack2(__float2half_rn(v0), __float2half_rn(v1));
                    } else {
                        int i2 = (d - D_NOPE) >> 1;
                        float pos = (float)positions[r];
                        float inv = expf(-logf(10000.0f) * (2.0f * i2) / (float)D_ROPE);
                        float ang = pos * inv;
                        float cs = cosf(ang), sn = sinf(ang);
                        *reinterpret_cast<uint32_t*>(&O1[dst]) =
                            pack2(__float2half_rn(v0 * cs - v1 * sn),
                                  __float2half_rn(v1 * cs + v0 * sn));
                    }
                }
            } else {
                int h = c >> 8, d = c & 255;
#pragma unroll
                for (int rr = 0; rr < 2; rr++) {
                    int r = rb + rr * 8;
                    float v0 = rr ? p10 : p00, v1 = rr ? p11 : p01;
                    uint32_t pk = pack2(__float2half_rn(v0), __float2half_rn(v1));
                    if (d < D_NOPE)
                        *reinterpret_cast<uint32_t*>(&O1[((long)h * T_SEQ + r) * QK_HD + d]) = pk;
                    else
                        *reinterpret_cast<uint32_t*>(&O2[((long)h * T_SEQ + r) * D_V + d - D_NOPE]) = pk;
                }
            }
        }
    }
}

// ---------------- Fused flash attention (all single-plane fp16) ----------------
#define FA_QSZ   (128 * 200 * 2)
#define FA_STG   6144
#define FA_SMEM  (FA_QSZ + 4 * FA_STG)

__global__ __launch_bounds__(256)
void flash_kernel(const f16* __restrict__ qf,
                  const f16* __restrict__ kf,  const f16* __restrict__ v,
                  f16* __restrict__ at)
{
    extern __shared__ char smem[];
    int h   = blockIdx.x;
    int tid = threadIdx.x;
    int lane = tid & 31;
    int wid  = tid >> 5;
    int wrow = wid * 16;

    uint32_t sQ  = smem_u32(smem);
    uint32_t stg = sQ + FA_QSZ;

    const long hT = (long)h * T_SEQ;

    auto loadQ = [&](int i0) {
#pragma unroll
        for (int it = 0; it < 12; it++) {
            int u = it * 256 + tid;
            int row = u / 24, off = (u % 24) * 8;
            cp16(sQ + (row * 200 + off) * 2, qf + (hT + i0 + row) * QK_HD + off);
        }
    };
    auto load_chunk = [&](int c) {
        uint32_t st = stg + (c & 3) * FA_STG;
        int j = c / 20, r = c % 20;
        if (r < 12) {
            int d0 = r * 16;
            int row = tid >> 1, off = (tid & 1) * 8;
            cp16(st + (row * 24 + off) * 2, kf + (hT + j * 128 + row) * QK_HD + d0 + off);
        } else {
            int q0 = (r - 12) * 16;
            int row = tid >> 4, off = (tid & 15) * 8;
            cp16(st + (row * 136 + off) * 2, v + (hT + j * 128 + q0 + row) * D_V + off);
        }
    };

    for (int rep = 0; rep < 2; rep++) {
        int iblk = rep == 0 ? blockIdx.y : (T_SEQ / 128 - 1) - blockIdx.y;
        int i0   = iblk * 128;
        int nch  = (iblk + 1) * 20;

        float s[16][4], o[16][4];
        float m0 = -1e30f, m1 = -1e30f, l0 = 0.f, l1 = 0.f;
#pragma unroll
        for (int nt = 0; nt < 16; nt++)
#pragma unroll
            for (int q = 0; q < 4; q++) o[nt][q] = 0.f;

        __syncthreads();
        loadQ(i0);
        load_chunk(0); cp_commit();
        load_chunk(1); cp_commit();

        int lr0 = wrow + (lane >> 2);
        int lr1 = lr0 + 8;

        for (int c = 0; c < nch; c++) {
            if (c + 2 < nch) load_chunk(c + 2);
            cp_commit();
            cp_wait<2>();
            __syncthreads();

            uint32_t st = stg + (c & 3) * FA_STG;
            int j = c / 20, r = c % 20;

            if (r < 12) {
                if (r == 0) {
#pragma unroll
                    for (int nt = 0; nt < 16; nt++)
#pragma unroll
                        for (int q = 0; q < 4; q++) s[nt][q] = 0.f;
                }
                uint32_t a_h[4];
                int ar = wrow + (lane & 15);
                int ac = r * 16 + (lane >> 4) * 8;
                ldsm_x4(sQ + (ar * 200 + ac) * 2, a_h);
                int g = lane >> 3, rr = lane & 7;
                int nbase = ((g >> 1) << 3) + rr;
                int cc = (g & 1) * 8;
#pragma unroll
                for (int p = 0; p < 8; p++) {
                    uint32_t bh[4];
                    ldsm_x4(st + ((p * 16 + nbase) * 24 + cc) * 2, bh);
#pragma unroll
                    for (int jj = 0; jj < 2; jj++)
                        mma_f16(s[2 * p + jj], a_h, bh[2 * jj], bh[2 * jj + 1]);
                }
                if (r == 11) {
#pragma unroll
                    for (int nt = 0; nt < 16; nt++)
#pragma unroll
                        for (int q = 0; q < 4; q++) s[nt][q] *= SCALE;
                    if (j == iblk) {
#pragma unroll
                        for (int nt = 0; nt < 16; nt++) {
                            int c0 = nt * 8 + ((lane & 3) << 1);
                            if (c0     > lr0) s[nt][0] = -1e30f;
                            if (c0 + 1 > lr0) s[nt][1] = -1e30f;
                            if (c0     > lr1) s[nt][2] = -1e30f;
                            if (c0 + 1 > lr1) s[nt][3] = -1e30f;
                        }
                    }
                    float mr0 = -1e30f, mr1 = -1e30f;
#pragma unroll
                    for (int nt = 0; nt < 16; nt++) {
                        mr0 = fmaxf(mr0, fmaxf(s[nt][0], s[nt][1]));
                        mr1 = fmaxf(mr1, fmaxf(s[nt][2], s[nt][3]));
                    }
                    mr0 = fmaxf(mr0, __shfl_xor_sync(~0u, mr0, 1));
                    mr0 = fmaxf(mr0, __shfl_xor_sync(~0u, mr0, 2));
                    mr1 = fmaxf(mr1, __shfl_xor_sync(~0u, mr1, 1));
                    mr1 = fmaxf(mr1, __shfl_xor_sync(~0u, mr1, 2));
                    float mn0 = fmaxf(m0, mr0), mn1 = fmaxf(m1, mr1);
                    float sc0 = __expf(m0 - mn0), sc1 = __expf(m1 - mn1);
                    float rs0 = 0.f, rs1 = 0.f;
#pragma unroll
                    for (int nt = 0; nt < 16; nt++) {
                        s[nt][0] = __expf(s[nt][0] - mn0); rs0 += s[nt][0];
                        s[nt][1] = __expf(s[nt][1] - mn0); rs0 += s[nt][1];
                        s[nt][2] = __expf(s[nt][2] - mn1); rs1 += s[nt][2];
                        s[nt][3] = __expf(s[nt][3] - mn1); rs1 += s[nt][3];
                    }
                    rs0 += __shfl_xor_sync(~0u, rs0, 1); rs0 += __shfl_xor_sync(~0u, rs0, 2);
                    rs1 += __shfl_xor_sync(~0u, rs1, 1); rs1 += __shfl_xor_sync(~0u, rs1, 2);
                    l0 = l0 * sc0 + rs0;  l1 = l1 * sc1 + rs1;
                    m0 = mn0; m1 = mn1;
#pragma unroll
                    for (int nt = 0; nt < 16; nt++) {
                        o[nt][0] *= sc0; o[nt][1] *= sc0;
                        o[nt][2] *= sc1; o[nt][3] *= sc1;
                    }
                }
            } else {
                // O += P @ V (P single-plane fp16 now)
                int q = r - 12;
                uint32_t ah[4];
                {
                    const float* t0 = s[2 * q];
                    const float* t1 = s[2 * q + 1];
                    ah[0] = pack2(__float2half_rn(t0[0]), __float2half_rn(t0[1]));
                    ah[1] = pack2(__float2half_rn(t0[2]), __float2half_rn(t0[3]));
                    ah[2] = pack2(__float2half_rn(t1[0]), __float2half_rn(t1[1]));
                    ah[3] = pack2(__float2half_rn(t1[2]), __float2half_rn(t1[3]));
                }
                int rv = lane & 15, half = lane >> 4;
#pragma unroll
                for (int pp = 0; pp < 8; pp++) {
                    uint32_t bh[4];
                    int cV = pp * 16 + half * 8;
                    ldsm_x4_t(st + (rv * 136 + cV) * 2, bh);
#pragma unroll
                    for (int jj = 0; jj < 2; jj++)
                        mma_f16(o[2 * pp + jj], ah, bh[2 * jj], bh[2 * jj + 1]);
                }
            }
        }

        float inv0 = 1.f / l0, inv1 = 1.f / l1;
        int gr0 = i0 + lr0;
#pragma unroll
        for (int nt = 0; nt < 16; nt++) {
            int col = h * D_V + nt * 8 + ((lane & 3) << 1);
            *reinterpret_cast<uint32_t*>(&at[(long)gr0 * O_K + col]) =
                pack2(__float2half_rn(o[nt][0] * inv0), __float2half_rn(o[nt][1] * inv0));
            *reinterpret_cast<uint32_t*>(&at[(long)(gr0 + 8) * O_K + col]) =
                pack2(__float2half_rn(o[nt][2] * inv1), __float2half_rn(o[nt][3] * inv1));
        }
    }
}

// ---------------- converters ----------------
__global__ void cvt_single_kernel(const float* __restrict__ src,
                                  f16* __restrict__ h, long n)
{
    long i = ((long)blockIdx.x * blockDim.x + threadIdx.x) * 8;
    if (i >= n) return;
    float4 v0 = *reinterpret_cast<const float4*>(&src[i]);
    float4 v1 = *reinterpret_cast<const float4*>(&src[i + 4]);
    uint4 o;
    o.x = pack2(__float2half_rn(v0.x), __float2half_rn(v0.y));
    o.y = pack2(__float2half_rn(v0.z), __float2half_rn(v0.w));
    o.z = pack2(__float2half_rn(v1.x), __float2half_rn(v1.y));
    o.w = pack2(__float2half_rn(v1.z), __float2half_rn(v1.w));
    *reinterpret_cast<uint4*>(&h[i]) = o;
}
// combined weight: dst[r][c] = c<1536 ? w_qa[r][c] : (c-1536<576 ? w_kva[r][c-1536] : 0)
__global__ void cvt_comb_kernel(const float* __restrict__ wqa,
                                const float* __restrict__ wkva,
                                f16* __restrict__ dst)
{
    long i = (long)blockIdx.x * blockDim.x + threadIdx.x;
    if (i >= (long)HID * QKV_N) return;
    int r = (int)(i / QKV_N), c = (int)(i % QKV_N);
    float vv;
    if (c < Q_LORA)               vv = wqa[(long)r * Q_LORA + c];
    else if (c - Q_LORA < KVA_N)  vv = wkva[(long)r * KVA_N + (c - Q_LORA)];
    else                          vv = 0.f;
    dst[i] = __float2half_rn(vv);
}

// ---------------- RMSNorm (single fp16 out) ----------------
__global__ void rmsnorm_kernel(const float* __restrict__ in,
                               const float* __restrict__ w,
                               f16* __restrict__ outh,
                               int L, int inStride, int outStride)
{
    int t = blockIdx.x;
    const float* x = in + (long)t * inStride;

    float ss = 0.f;
    for (int i = threadIdx.x; i < L; i += blockDim.x) {
        float v = x[i]; ss += v * v;
    }
    __shared__ float sh[33];
#pragma unroll
    for (int o = 16; o; o >>= 1) ss += __shfl_xor_sync(~0u, ss, o);
    int lane = threadIdx.x & 31, wrp = threadIdx.x >> 5;
    if (lane == 0) sh[wrp] = ss;
    __syncthreads();
    if (wrp == 0) {
        float v = (lane < (blockDim.x >> 5)) ? sh[lane] : 0.f;
#pragma unroll
        for (int o = 16; o; o >>= 1) v += __shfl_xor_sync(~0u, v, o);
        if (lane == 0) sh[32] = v;
    }
    __syncthreads();
    float r = rsqrtf(sh[32] / (float)L + EPS_RMS);
    for (int i = threadIdx.x; i < L; i += blockDim.x)
        outh[(long)t * outStride + i] = __float2half_rn(x[i] * r * w[i]);
}

// ---------------- k_pe rope + broadcast (reads combined qkv buffer) ----------------
__global__ void kpe_kernel(const int* __restrict__ positions,
                           const float* __restrict__ qkv,
                           f16* __restrict__ kf)
{
    long i = (long)blockIdx.x * blockDim.x + threadIdx.x;
    if (i >= (long)T_SEQ * (D_ROPE / 2)) return;
    int t = (int)(i >> 5), k = (int)(i & 31);
    float pos = (float)positions[t];
    float inv = expf(-logf(10000.0f) * (2.0f * k) / (float)D_ROPE);
    float ang = pos * inv;
    float cs = cosf(ang), sn = sinf(ang);
    float x1 = qkv[(long)t * QKV_N + Q_LORA + KV_LORA + 2 * k];
    float x2 = qkv[(long)t * QKV_N + Q_LORA + KV_LORA + 2 * k + 1];
    uint32_t pk = pack2(__float2half_rn(x1 * cs - x2 * sn),
                        __float2half_rn(x2 * cs + x1 * sn));
#pragma unroll
    for (int h = 0; h < NH; h++)
        *reinterpret_cast<uint32_t*>(&kf[((long)h * T_SEQ + t) * QK_HD + D_NOPE + 2 * k]) = pk;
}

// ---------------- Launch ----------------
extern "C" void kernel_launch(void* const* d_in, const int* in_sizes, int n_in,
                              void* d_out, int out_size)
{
    const int*   positions = (const int*)  d_in[0];
    const float* hs        = (const float*)d_in[1];
    const float* w_qa      = (const float*)d_in[2];
    const float* qa_ln_w   = (const float*)d_in[3];
    const float* w_qb      = (const float*)d_in[4];
    const float* w_kva     = (const float*)d_in[5];
    const float* kva_ln_w  = (const float*)d_in[6];
    const float* w_kvb     = (const float*)d_in[7];
    const float* w_o       = (const float*)d_in[8];
    float* out = (float*)d_out;

    float *p_qkv;
    f16 *phs, *wcomb, *wqb, *wkvb, *wo;
    f16 *qc, *kvc, *qf, *kf, *v, *at;

    cudaGetSymbolAddress((void**)&p_qkv,  g_qkv);
    cudaGetSymbolAddress((void**)&phs,    g_hs);
    cudaGetSymbolAddress((void**)&wcomb,  g_wcomb);
    cudaGetSymbolAddress((void**)&wqb,    g_wqb);
    cudaGetSymbolAddress((void**)&wkvb,   g_wkvb);
    cudaGetSymbolAddress((void**)&wo,     g_wo);
    cudaGetSymbolAddress((void**)&qc,     g_qc);
    cudaGetSymbolAddress((void**)&kvc,    g_kvc);
    cudaGetSymbolAddress((void**)&qf,     g_qf);
    cudaGetSymbolAddress((void**)&kf,     g_kf);
    cudaGetSymbolAddress((void**)&v,      g_v);
    cudaGetSymbolAddress((void**)&at,     g_at);

    cudaFuncSetAttribute(tgemm_nn<0>,  cudaFuncAttributeMaxDynamicSharedMemorySize, G_SMEM);
    cudaFuncSetAttribute(tgemm_nn<1>,  cudaFuncAttributeMaxDynamicSharedMemorySize, G_SMEM);
    cudaFuncSetAttribute(tgemm_nn<2>,  cudaFuncAttributeMaxDynamicSharedMemorySize, G_SMEM);
    cudaFuncSetAttribute(flash_kernel, cudaFuncAttributeMaxDynamicSharedMemorySize, FA_SMEM);

    dim3 blk(256);
    auto cdiv = [](long a, long b) { return (int)((a + b - 1) / b); };

    // converters
    cvt_single_kernel<<<cdiv((long)T_SEQ * HID / 8, 256), 256>>>(hs, phs, (long)T_SEQ * HID);
    cvt_comb_kernel<<<cdiv((long)HID * QKV_N, 256), 256>>>(w_qa, w_kva, wcomb);
    cvt_single_kernel<<<cdiv((long)Q_LORA * QB_N / 8, 256), 256>>>(w_qb, wqb, (long)Q_LORA * QB_N);
    cvt_single_kernel<<<cdiv((long)KV_LORA * KVB_N / 8, 256), 256>>>(w_kvb, wkvb, (long)KV_LORA * KVB_N);
    cvt_single_kernel<<<cdiv((long)O_K * HID / 8, 256), 256>>>(w_o, wo, (long)O_K * HID);

    // G1+G2 merged: qkv = hs @ [w_qa | w_kva] (N=2176, K=5120)
    tgemm_nn<0><<<dim3(QKV_N/BN, T_SEQ/BM), blk, G_SMEM>>>(
        phs, wcomb, p_qkv, nullptr, nullptr, nullptr,
        QKV_N, HID, HID, QKV_N, QKV_N, 1.f);

    rmsnorm_kernel<<<T_SEQ, 256>>>(p_qkv,          qa_ln_w,  qc,  Q_LORA,  QKV_N, Q_LORA);
    rmsnorm_kernel<<<T_SEQ, 256>>>(p_qkv + Q_LORA, kva_ln_w, kvc, KV_LORA, QKV_N, KV_LORA);

    // k_pe rope + broadcast
    kpe_kernel<<<cdiv((long)T_SEQ * (D_ROPE/2), 256), 256>>>(positions, p_qkv, kf);

    // G3: q = qc @ w_qb — fused RoPE epilogue
    tgemm_nn<1><<<dim3(QB_N/BN, T_SEQ/BM), blk, G_SMEM>>>(
        qc, wqb, nullptr, qf, nullptr, positions,
        QB_N, Q_LORA, Q_LORA, QB_N, 0, 1.f);

    // G4: kvup = kvc @ w_kvb — fused scatter epilogue
    tgemm_nn<2><<<dim3(KVB_N/BN, T_SEQ/BM), blk, G_SMEM>>>(
        kvc, wkvb, nullptr, kf, v, nullptr,
        KVB_N, KV_LORA, KV_LORA, KVB_N, 0, 1.f);

    // Fused attention
    flash_kernel<<<dim3(NH, T_SEQ / 256), blk, FA_SMEM>>>(qf, kf, v, at);

    // G7: out = attn @ w_o
    tgemm_nn<0><<<dim3(HID/BN, T_SEQ/BM), blk, G_SMEM>>>(
        at, wo, out, nullptr, nullptr, nullptr,
        HID, O_K, O_K, HID, HID, 1.f);
}